// round 11
// baseline (speedup 1.0000x reference)
#include <cuda_runtime.h>
#include <cuda_bf16.h>
#include <math.h>

#define BATCH 8
#define SEQ   1024
#define NROWS (BATCH*SEQ)   // 8192
#define DENC  128
#define DMAIN 256
#define NHEADS 4

// ---------------- scratch (device globals: no allocation in kernel_launch) ----------------
__device__ float g_x[NROWS*DENC];
__device__ float g_lnbuf[NROWS*DMAIN];
__device__ float g_qkv[NROWS*3*DMAIN];
__device__ float g_att[NROWS*DMAIN];
__device__ float g_mlp[NROWS*2*DMAIN];
__device__ float g_z[NROWS*DMAIN];
__device__ float g_comp[NROWS*DENC];
__device__ float g_qr[NROWS*DENC];
__device__ float g_kr[NROWS*DENC];
__device__ float g_zdown[NROWS*DENC];
__device__ float g_zbar[NROWS*DENC];
__device__ float g_p[NROWS];
__device__ float g_bh[NROWS];
__device__ float g_pcomp[NROWS];
__device__ int   g_cum[NROWS];
__device__ int   g_counts[BATCH];
__device__ float g_loss[1];

// ---------------- helpers ----------------
__device__ __forceinline__ float gelu_exact(float v) {
    return 0.5f * v * (1.0f + erff(v * 0.70710678118654752440f));
}

// ---------------- embedding lookup ----------------
__global__ void embed_kernel(const int* __restrict__ ids, const float* __restrict__ emb,
                             float* __restrict__ x) {
    int row = blockIdx.x;
    int t = threadIdx.x;
    x[(size_t)row * DENC + t] = emb[(size_t)ids[row] * DENC + t];
}

// ---------------- LayerNorm (one block per row, blockDim = D) ----------------
// If cnts != nullptr, rows beyond cnts[batch] (padded main-stack rows) are skipped:
// every downstream consumer of those rows is itself skipped or masked.
__global__ void ln_kernel(const float* __restrict__ x, const float* __restrict__ w,
                          const float* __restrict__ b, float* __restrict__ y, int D,
                          const int* __restrict__ cnts) {
    int row = blockIdx.x;
    if (cnts && (row & (SEQ - 1)) >= cnts[row >> 10]) return;
    int t = threadIdx.x;
    __shared__ float sw[8];
    __shared__ float sbr;
    float v = x[(size_t)row * D + t];
    float s = v;
    #pragma unroll
    for (int o = 16; o; o >>= 1) s += __shfl_xor_sync(0xffffffffu, s, o);
    if ((t & 31) == 0) sw[t >> 5] = s;
    __syncthreads();
    if (t == 0) {
        float tot = 0.f; int nw = D >> 5;
        for (int i = 0; i < nw; i++) tot += sw[i];
        sbr = tot / (float)D;
    }
    __syncthreads();
    float mu = sbr;
    float dlt = v - mu;
    s = dlt * dlt;
    #pragma unroll
    for (int o = 16; o; o >>= 1) s += __shfl_xor_sync(0xffffffffu, s, o);
    __syncthreads();
    if ((t & 31) == 0) sw[t >> 5] = s;
    __syncthreads();
    if (t == 0) {
        float tot = 0.f; int nw = D >> 5;
        for (int i = 0; i < nw; i++) tot += sw[i];
        sbr = rsqrtf(tot / (float)D + 1e-5f);
    }
    __syncthreads();
    y[(size_t)row * D + t] = dlt * sbr * w[t] + b[t];
}

// ---------------- SGEMM: C[M,N] (+)= act(A[M,K] @ W[N,K]^T) ----------------
// M fixed at 8192 (grid.y = 64). BM=BN=128, BK=8, 256 threads, 8x8 per thread.
// FUSE: 0 = store, 1 = C += result, 2 = gelu(result)
// cnts: optional per-batch live-row counts; blocks fully in the padded tail skip.
template<int FUSE>
__global__ __launch_bounds__(256)
void gemm_kernel(const float* __restrict__ A, const float* __restrict__ W,
                 float* __restrict__ C, int N, int K, const int* __restrict__ cnts) {
    int row0 = blockIdx.y * 128, col0 = blockIdx.x * 128;
    if (cnts && (row0 & (SEQ - 1)) >= cnts[row0 >> 10]) return;
    __shared__ float As[8][128];
    __shared__ float Ws[8][128];
    int tid = threadIdx.x;
    int tr = (tid >> 4) << 3;
    int tc = (tid & 15) << 3;
    float acc[8][8];
    #pragma unroll
    for (int i = 0; i < 8; i++)
        #pragma unroll
        for (int j = 0; j < 8; j++) acc[i][j] = 0.f;
    int la = tid << 2;
    int lar = la >> 3, lac = la & 7;
    const float* Ag = A + (size_t)(row0 + lar) * K + lac;
    int wrow = col0 + lar;
    bool wok = wrow < N;
    const float* Wg = W + (size_t)(wok ? wrow : 0) * K + lac;
    for (int k0 = 0; k0 < K; k0 += 8) {
        float4 av = *(const float4*)(Ag + k0);
        float4 wv = wok ? *(const float4*)(Wg + k0) : make_float4(0.f, 0.f, 0.f, 0.f);
        As[lac + 0][lar] = av.x; As[lac + 1][lar] = av.y;
        As[lac + 2][lar] = av.z; As[lac + 3][lar] = av.w;
        Ws[lac + 0][lar] = wv.x; Ws[lac + 1][lar] = wv.y;
        Ws[lac + 2][lar] = wv.z; Ws[lac + 3][lar] = wv.w;
        __syncthreads();
        #pragma unroll
        for (int k = 0; k < 8; k++) {
            float af[8], wf[8];
            *(float4*)(af)     = *(const float4*)(&As[k][tr]);
            *(float4*)(af + 4) = *(const float4*)(&As[k][tr + 4]);
            *(float4*)(wf)     = *(const float4*)(&Ws[k][tc]);
            *(float4*)(wf + 4) = *(const float4*)(&Ws[k][tc + 4]);
            #pragma unroll
            for (int i = 0; i < 8; i++)
                #pragma unroll
                for (int j = 0; j < 8; j++)
                    acc[i][j] += af[i] * wf[j];
        }
        __syncthreads();
    }
    #pragma unroll
    for (int i = 0; i < 8; i++) {
        float* Cr = C + (size_t)(row0 + tr + i) * N;
        #pragma unroll
        for (int j = 0; j < 8; j++) {
            int cc = col0 + tc + j;
            if (cc < N) {
                float v = acc[i][j];
                if (FUSE == 1) v += Cr[cc];
                if (FUSE == 2) v = gelu_exact(v);
                Cr[cc] = v;
            }
        }
    }
}

// ---------------- flash-style causal attention ----------------
// grid: (BATCH*NHEADS, SEQ/128), block 128 threads, 1 query row per thread.
// qkv row layout: [q(0:D) | k(D:2D) | v(2D:3D)], head h owns cols h*DH..h*DH+DH-1.
// If counts != nullptr: keys >= counts[b] masked (redundant for valid q, since
// causal already restricts), queries >= counts[b] produce zeros (unused downstream).
template<int DH>
__global__ __launch_bounds__(128)
void attn_kernel(const float* __restrict__ qkv, float* __restrict__ out,
                 int D, const int* __restrict__ counts, float scale) {
    const int D3 = 3 * D;
    int b = blockIdx.x >> 2, h = blockIdx.x & 3;
    int tid = threadIdx.x;
    int q = blockIdx.y * 128 + tid;
    __shared__ float Ksh[32][DH];
    __shared__ float Vsh[32][DH];
    int cnt = counts ? counts[b] : SEQ;
    float* orow = out + ((size_t)(b * SEQ) + q) * D + h * DH;
    if (counts && (int)(blockIdx.y * 128) >= cnt) {
        #pragma unroll
        for (int d = 0; d < DH; d++) orow[d] = 0.f;
        return;
    }
    int qlim = (q < cnt) ? q : -1;               // inclusive max key for this thread
    int limit = min((int)(blockIdx.y * 128 + 127), cnt - 1);  // block-wide max key
    const float* qrow = qkv + ((size_t)(b * SEQ) + q) * D3 + h * DH;
    float qreg[DH], acc[DH];
    #pragma unroll
    for (int d = 0; d < DH; d++) { qreg[d] = qrow[d]; acc[d] = 0.f; }
    float mval = -1e30f, lsum = 0.f;
    int ntiles = limit / 32 + 1;
    for (int kt = 0; kt < ntiles; kt++) {
        int k0 = kt * 32;
        for (int idx = tid; idx < 32 * DH; idx += 128) {
            int j = idx / DH, d = idx - j * DH;
            size_t base = ((size_t)(b * SEQ) + (k0 + j)) * D3 + h * DH + d;
            Ksh[j][d] = qkv[base + D];
            Vsh[j][d] = qkv[base + 2 * D];
        }
        __syncthreads();
        int jmax = qlim - k0;                    // inclusive within tile
        if (jmax > 31) jmax = 31;
        for (int j = 0; j <= jmax; j++) {
            float s = 0.f;
            #pragma unroll
            for (int d = 0; d < DH; d++) s += qreg[d] * Ksh[j][d];
            s *= scale;
            if (s > mval) {
                float f = __expf(mval - s);
                lsum *= f;
                #pragma unroll
                for (int d = 0; d < DH; d++) acc[d] *= f;
                mval = s;
            }
            float w = __expf(s - mval);
            lsum += w;
            #pragma unroll
            for (int d = 0; d < DH; d++) acc[d] += w * Vsh[j][d];
        }
        __syncthreads();
    }
    if (qlim >= 0) {
        float inv = 1.f / lsum;
        #pragma unroll
        for (int d = 0; d < DH; d++) orow[d] = acc[d] * inv;
    } else {
        #pragma unroll
        for (int d = 0; d < DH; d++) orow[d] = 0.f;
    }
}

// ---------------- routing: cos similarity of normalized q[l], k[l-1] ----------------
__global__ void route_kernel(const float* __restrict__ q, const float* __restrict__ k,
                             float* __restrict__ p, float* __restrict__ bh) {
    int wid = (blockIdx.x * blockDim.x + threadIdx.x) >> 5;
    int lane = threadIdx.x & 31;
    if (wid >= NROWS) return;
    int l = wid & (SEQ - 1);
    const float* qr = q + (size_t)wid * DENC;
    const float* kr = (l > 0) ? (k + (size_t)(wid - 1) * DENC) : nullptr;
    float nq = 0.f, nk = 0.f, dt = 0.f;
    for (int i = lane; i < DENC; i += 32) {
        float qv = qr[i];
        float kv = kr ? kr[i] : 0.f;
        nq += qv * qv; nk += kv * kv; dt += qv * kv;
    }
    #pragma unroll
    for (int o = 16; o; o >>= 1) {
        nq += __shfl_xor_sync(0xffffffffu, nq, o);
        nk += __shfl_xor_sync(0xffffffffu, nk, o);
        dt += __shfl_xor_sync(0xffffffffu, dt, o);
    }
    if (lane == 0) {
        float denom = fmaxf(sqrtf(nq), 1e-12f) * fmaxf(sqrtf(nk), 1e-12f);
        float cosv = dt / denom;
        float pv = fminf(fmaxf(0.5f * (1.f - cosv), 0.f), 1.f);
        if (l == 0) pv = 1.f;
        p[wid] = pv;
        bh[wid] = (pv >= 0.5f) ? 1.f : 0.f;
    }
}

// ---------------- per-batch inclusive scan of b_hard ----------------
__global__ void scan_kernel(const float* __restrict__ bh, int* __restrict__ cum,
                            int* __restrict__ counts) {
    int b = blockIdx.x, t = threadIdx.x;   // 1024 threads
    __shared__ int s[SEQ];
    s[t] = (int)bh[b * SEQ + t];
    __syncthreads();
    for (int o = 1; o < SEQ; o <<= 1) {
        int add = (t >= o) ? s[t - o] : 0;
        __syncthreads();
        s[t] += add;
        __syncthreads();
    }
    cum[b * SEQ + t] = s[t];
    if (t == SEQ - 1) counts[b] = s[t];
}

// ---------------- ratio loss (single block, deterministic) ----------------
__global__ void stats_kernel(const float* __restrict__ bh, const float* __restrict__ p,
                             float* __restrict__ loss) {
    int t = threadIdx.x;   // 1024
    __shared__ float rb[1024], rp[1024];
    float sb = 0.f, sp = 0.f;
    for (int i = t; i < NROWS; i += 1024) { sb += bh[i]; sp += p[i]; }
    rb[t] = sb; rp[t] = sp;
    __syncthreads();
    for (int o = 512; o; o >>= 1) {
        if (t < o) { rb[t] += rb[t + o]; rp[t] += rp[t + o]; }
        __syncthreads();
    }
    if (t == 0) {
        float F = rb[0] / (float)NROWS, G = rp[0] / (float)NROWS;
        loss[0] = 1.2f * (5.f * F * G + (1.f - F) * (1.f - G));
    }
}

__global__ void zero_kernel(float* __restrict__ ptr, int n) {
    int i = blockIdx.x * blockDim.x + threadIdx.x;
    if (i < n) ptr[i] = 0.f;
}

// ---------------- scatter selected rows to front (downsample) ----------------
__global__ void scatter_kernel(const float* __restrict__ x, const float* __restrict__ p,
                               const float* __restrict__ bh, const int* __restrict__ cum,
                               float* __restrict__ comp, float* __restrict__ pcomp) {
    int row = blockIdx.x;
    if (bh[row] < 0.5f) return;
    int b = row >> 10;
    int dst = cum[row] - 1;
    int t = threadIdx.x;
    comp[((size_t)(b << 10) + dst) * DENC + t] = x[(size_t)row * DENC + t];
    if (t == 0) pcomp[(b << 10) + dst] = p[row];
}

// ---------------- EMA linear recurrence scan: zbar[t] = a[t]*zbar[t-1] + bv[t] ----
// Only t < counts[b] is ever consumed (gather clamps chunk index below counts).
__global__ void ema_kernel(const float* __restrict__ z, const float* __restrict__ pc,
                           float* __restrict__ zbar, const int* __restrict__ counts) {
    int b = blockIdx.x, d = threadIdx.x;   // 128 threads
    const float* zb = z + (size_t)b * SEQ * DENC;
    float* ob = zbar + (size_t)b * SEQ * DENC;
    const float* pb = pc + b * SEQ;
    int Tn = counts[b];
    float prev = 0.f;
    for (int t = 0; t < Tn; t++) {
        float pv = pb[t];
        float pcl = fminf(fmaxf(pv, 1e-4f), 0.9999f);
        float zv = zb[(size_t)t * DENC + d];
        float cur = (t == 0) ? zv : ((1.f - pcl) * prev + pcl * zv);
        ob[(size_t)t * DENC + d] = cur;
        prev = cur;
    }
}

// ---------------- gather + STE residual add (forward c_ste computed exactly) ----
__global__ void gather_kernel(const float* __restrict__ zbar, const int* __restrict__ cum,
                              const float* __restrict__ p, const float* __restrict__ bh,
                              float* __restrict__ x) {
    int row = blockIdx.x, t = threadIdx.x;
    int b = row >> 10;
    int ci = cum[row] - 1; if (ci < 0) ci = 0;
    float pv = p[row], bv = bh[row];
    float c = bv * pv + (1.f - bv) * (1.f - pv);
    float cste = c + (1.f - c);   // forward value of STE (== 1 up to rounding, match ref)
    x[(size_t)row * DENC + t] += cste * zbar[((size_t)(b << 10) + ci) * DENC + t];
}

__global__ void tail_kernel(float* __restrict__ dst, const float* __restrict__ loss) {
    dst[0] = loss[0];
}

// ---------------- host orchestration ----------------
static void* symaddr(const void* sym) {
    void* p = nullptr;
    cudaGetSymbolAddress(&p, sym);
    return p;
}

// Logical input order (reference signature order):
//  0 byte_ids 1 embed 2 wq 3 wk
//  4..11  enc: ln1_w ln1_b qkv wo ln2_w ln2_b w1 w2
//  12 proj_up
//  13..20 main: (same 8)
//  21 proj_down
//  22..29 dec: (same 8)
//  30 norm_w 31 norm_b
static const int PERM_SIG[32] = {
    0,1,2,3, 4,5,6,7,8,9,10,11, 12, 13,14,15,16,17,18,19,20, 21, 22,23,24,25,26,27,28,29, 30,31
};
// setup_inputs() dict order: byte_ids, embed, wq, wk, proj_up, proj_down,
// norm_w, norm_b, enc(8), main(8), dec(8)
static const int PERM_DICT[32] = {
    0,1,2,3, 8,9,10,11,12,13,14,15, 4, 16,17,18,19,20,21,22,23, 5, 24,25,26,27,28,29,30,31, 6,7
};
// alphabetical name order
static const int PERM_ALPHA[32] = {
    0,9,31,30, 11,10,14,17,13,12,15,16, 29, 19,18,22,25,21,20,23,24, 28, 2,1,5,8,4,3,6,7, 27,26
};

extern "C" void kernel_launch(void* const* d_in, const int* in_sizes, int n_in,
                              void* d_out, int out_size) {
    (void)n_in;
    // Runtime disambiguation of the harness's input ordering via element counts:
    //  alphabetical: slot 1 = dec_ln1_b (384)
    //  dict order:   slot 4 = proj_up   (32768)
    //  signature:    slot 4 = enc_ln1_w (384)
    const int* perm;
    if (in_sizes[1] == 3 * DENC)            perm = PERM_ALPHA;
    else if (in_sizes[4] == DMAIN * DENC)   perm = PERM_DICT;
    else                                    perm = PERM_SIG;

    const float* inp[32];
    for (int i = 0; i < 32; i++) inp[i] = (const float*)d_in[perm[i]];

    const int*   ids       = (const int*)d_in[perm[0]];
    const float* embed     = inp[1];
    const float* wq        = inp[2];
    const float* wk        = inp[3];
    const float* enc_ln1w  = inp[4];
    const float* enc_ln1b  = inp[5];
    const float* enc_qkvw  = inp[6];
    const float* enc_wo    = inp[7];
    const float* enc_ln2w  = inp[8];
    const float* enc_ln2b  = inp[9];
    const float* enc_w1    = inp[10];
    const float* enc_w2    = inp[11];
    const float* proj_up   = inp[12];
    const float* mn_ln1w   = inp[13];
    const float* mn_ln1b   = inp[14];
    const float* mn_qkvw   = inp[15];
    const float* mn_wo     = inp[16];
    const float* mn_ln2w   = inp[17];
    const float* mn_ln2b   = inp[18];
    const float* mn_w1     = inp[19];
    const float* mn_w2     = inp[20];
    const float* proj_down = inp[21];
    const float* dc_ln1w   = inp[22];
    const float* dc_ln1b   = inp[23];
    const float* dc_qkvw   = inp[24];
    const float* dc_wo     = inp[25];
    const float* dc_ln2w   = inp[26];
    const float* dc_ln2b   = inp[27];
    const float* dc_w1     = inp[28];
    const float* dc_w2     = inp[29];
    const float* norm_w    = inp[30];
    const float* norm_b    = inp[31];

    float* x     = (float*)symaddr(g_x);
    float* lnp   = (float*)symaddr(g_lnbuf);
    float* qkvp  = (float*)symaddr(g_qkv);
    float* attp  = (float*)symaddr(g_att);
    float* mlpp  = (float*)symaddr(g_mlp);
    float* zp    = (float*)symaddr(g_z);
    float* compp = (float*)symaddr(g_comp);
    float* qrp   = (float*)symaddr(g_qr);
    float* krp   = (float*)symaddr(g_kr);
    float* zdp   = (float*)symaddr(g_zdown);
    float* zbp   = (float*)symaddr(g_zbar);
    float* pp    = (float*)symaddr(g_p);
    float* bhp   = (float*)symaddr(g_bh);
    float* pcp   = (float*)symaddr(g_pcomp);
    int*   cump  = (int*)symaddr(g_cum);
    int*   cntp  = (int*)symaddr(g_counts);
    float* lossp = (float*)symaddr(g_loss);

    auto run_block = [&](float* xb, int D, int dh,
                         const float* l1w, const float* l1b,
                         const float* qw, const float* wo,
                         const float* l2w, const float* l2b,
                         const float* w1, const float* w2,
                         const int* cnts) {
        int D3 = 3 * D;
        ln_kernel<<<NROWS, D>>>(xb, l1w, l1b, lnp, D, cnts);
        gemm_kernel<0><<<dim3(D3 / 128, 64), 256>>>(lnp, qw, qkvp, D3, D, cnts);
        if (dh == 32)
            attn_kernel<32><<<dim3(BATCH * NHEADS, SEQ / 128), 128>>>(qkvp, attp, D, cnts, 0.17677669529663687f);
        else
            attn_kernel<64><<<dim3(BATCH * NHEADS, SEQ / 128), 128>>>(qkvp, attp, D, cnts, 0.125f);
        gemm_kernel<1><<<dim3(D / 128, 64), 256>>>(attp, wo, xb, D, D, cnts);
        ln_kernel<<<NROWS, D>>>(xb, l2w, l2b, lnp, D, cnts);
        gemm_kernel<2><<<dim3(2 * D / 128, 64), 256>>>(lnp, w1, mlpp, 2 * D, D, cnts);
        gemm_kernel<1><<<dim3(D / 128, 64), 256>>>(mlpp, w2, xb, D, 2 * D, cnts);
    };

    // ---- encoder ----
    embed_kernel<<<NROWS, DENC>>>(ids, embed, x);
    for (int i = 0; i < 3; i++)
        run_block(x, DENC, 32,
                  enc_ln1w + i * DENC, enc_ln1b + i * DENC,
                  enc_qkvw + (size_t)i * 3 * DENC * DENC,
                  enc_wo   + (size_t)i * DENC * DENC,
                  enc_ln2w + i * DENC, enc_ln2b + i * DENC,
                  enc_w1   + (size_t)i * 2 * DENC * DENC,
                  enc_w2   + (size_t)i * 2 * DENC * DENC,
                  nullptr);

    // ---- routing / dynamic chunking ----
    gemm_kernel<0><<<dim3(1, 64), 256>>>(x, wq, qrp, DENC, DENC, nullptr);
    gemm_kernel<0><<<dim3(1, 64), 256>>>(x, wk, krp, DENC, DENC, nullptr);
    route_kernel<<<NROWS / 8, 256>>>(qrp, krp, pp, bhp);
    scan_kernel<<<BATCH, SEQ>>>(bhp, cump, cntp);
    stats_kernel<<<1, 1024>>>(bhp, pp, lossp);
    zero_kernel<<<(NROWS * DENC + 255) / 256, 256>>>(compp, NROWS * DENC);
    zero_kernel<<<(NROWS + 255) / 256, 256>>>(pcp, NROWS);
    scatter_kernel<<<NROWS, DENC>>>(x, pp, bhp, cump, compp, pcp);

    // ---- main stack (padded + masked; padded rows dynamically elided) ----
    gemm_kernel<0><<<dim3(2, 64), 256>>>(compp, proj_up, zp, DMAIN, DENC, cntp);
    for (int i = 0; i < 6; i++)
        run_block(zp, DMAIN, 64,
                  mn_ln1w + i * DMAIN, mn_ln1b + i * DMAIN,
                  mn_qkvw + (size_t)i * 3 * DMAIN * DMAIN,
                  mn_wo   + (size_t)i * DMAIN * DMAIN,
                  mn_ln2w + i * DMAIN, mn_ln2b + i * DMAIN,
                  mn_w1   + (size_t)i * 2 * DMAIN * DMAIN,
                  mn_w2   + (size_t)i * 2 * DMAIN * DMAIN,
                  cntp);
    gemm_kernel<0><<<dim3(1, 64), 256>>>(zp, proj_down, zdp, DENC, DMAIN, cntp);

    // ---- EMA scan + gather + STE add ----
    ema_kernel<<<BATCH, DENC>>>(zdp, pcp, zbp, cntp);
    gather_kernel<<<NROWS, DENC>>>(zbp, cump, pp, bhp, x);

    // ---- decoder ----
    for (int i = 0; i < 3; i++)
        run_block(x, DENC, 32,
                  dc_ln1w + i * DENC, dc_ln1b + i * DENC,
                  dc_qkvw + (size_t)i * 3 * DENC * DENC,
                  dc_wo   + (size_t)i * DENC * DENC,
                  dc_ln2w + i * DENC, dc_ln2b + i * DENC,
                  dc_w1   + (size_t)i * 2 * DENC * DENC,
                  dc_w2   + (size_t)i * 2 * DENC * DENC,
                  nullptr);

    // ---- final norm + tied logits head ----
    ln_kernel<<<NROWS, DENC>>>(x, norm_w, norm_b, lnp, DENC, nullptr);
    gemm_kernel<0><<<dim3(3, 64), 256>>>(lnp, embed, (float*)d_out, 260, DENC, nullptr);

    const int NLOGITS = NROWS * 260;
    if (out_size > NLOGITS)
        tail_kernel<<<1, 1>>>((float*)d_out + NLOGITS, lossp);
}

// round 12
// speedup vs baseline: 1.1011x; 1.1011x over previous
#include <cuda_runtime.h>
#include <cuda_bf16.h>
#include <math.h>

#define BATCH 8
#define SEQ   1024
#define NROWS (BATCH*SEQ)   // 8192
#define DENC  128
#define DMAIN 256
#define NHEADS 4

// ---------------- scratch (device globals: no allocation in kernel_launch) ----------------
__device__ float g_x[NROWS*DENC];
__device__ float g_lnbuf[NROWS*DMAIN];
__device__ float g_qkv[NROWS*3*DMAIN];
__device__ float g_att[NROWS*DMAIN];
__device__ float g_mlp[NROWS*2*DMAIN];
__device__ float g_z[NROWS*DMAIN];
__device__ float g_comp[NROWS*DENC];
__device__ float g_qr[NROWS*DENC];
__device__ float g_kr[NROWS*DENC];
__device__ float g_zdown[NROWS*DENC];
__device__ float g_zbar[NROWS*DENC];
__device__ float g_p[NROWS];
__device__ float g_bh[NROWS];
__device__ float g_pcomp[NROWS];
__device__ int   g_cum[NROWS];
__device__ int   g_counts[BATCH];
__device__ float g_loss[1];

// ---------------- f32x2 packed-FMA helpers (Blackwell FFMA2, PTX-only) ----------------
typedef unsigned long long u64;
__device__ __forceinline__ u64 dup2(float v) {
    u64 r; asm("mov.b64 %0, {%1, %1};" : "=l"(r) : "f"(v)); return r;
}
__device__ __forceinline__ void unpack2(u64 v, float& lo, float& hi) {
    asm("mov.b64 {%0, %1}, %2;" : "=f"(lo), "=f"(hi) : "l"(v));
}
__device__ __forceinline__ u64 fma2(u64 a, u64 b, u64 c) {
    u64 d; asm("fma.rn.f32x2 %0, %1, %2, %3;" : "=l"(d) : "l"(a), "l"(b), "l"(c)); return d;
}
__device__ __forceinline__ u64 mul2(u64 a, u64 b) {
    u64 d; asm("mul.rn.f32x2 %0, %1, %2;" : "=l"(d) : "l"(a), "l"(b)); return d;
}

// ---------------- helpers ----------------
__device__ __forceinline__ float gelu_exact(float v) {
    return 0.5f * v * (1.0f + erff(v * 0.70710678118654752440f));
}

// ---------------- embedding lookup ----------------
__global__ void embed_kernel(const int* __restrict__ ids, const float* __restrict__ emb,
                             float* __restrict__ x) {
    int row = blockIdx.x;
    int t = threadIdx.x;
    x[(size_t)row * DENC + t] = emb[(size_t)ids[row] * DENC + t];
}

// ---------------- LayerNorm (one block per row, blockDim = D) ----------------
__global__ void ln_kernel(const float* __restrict__ x, const float* __restrict__ w,
                          const float* __restrict__ b, float* __restrict__ y, int D,
                          const int* __restrict__ cnts) {
    int row = blockIdx.x;
    if (cnts && (row & (SEQ - 1)) >= cnts[row >> 10]) return;
    int t = threadIdx.x;
    __shared__ float sw[8];
    __shared__ float sbr;
    float v = x[(size_t)row * D + t];
    float s = v;
    #pragma unroll
    for (int o = 16; o; o >>= 1) s += __shfl_xor_sync(0xffffffffu, s, o);
    if ((t & 31) == 0) sw[t >> 5] = s;
    __syncthreads();
    if (t == 0) {
        float tot = 0.f; int nw = D >> 5;
        for (int i = 0; i < nw; i++) tot += sw[i];
        sbr = tot / (float)D;
    }
    __syncthreads();
    float mu = sbr;
    float dlt = v - mu;
    s = dlt * dlt;
    #pragma unroll
    for (int o = 16; o; o >>= 1) s += __shfl_xor_sync(0xffffffffu, s, o);
    __syncthreads();
    if ((t & 31) == 0) sw[t >> 5] = s;
    __syncthreads();
    if (t == 0) {
        float tot = 0.f; int nw = D >> 5;
        for (int i = 0; i < nw; i++) tot += sw[i];
        sbr = rsqrtf(tot / (float)D + 1e-5f);
    }
    __syncthreads();
    y[(size_t)row * D + t] = dlt * sbr * w[t] + b[t];
}

// ---------------- SGEMM (FFMA2): C[M,N] (+)= act(A[M,K] @ W[N,K]^T) ----------------
// BM=BN=128, BK=8, 256 threads, 8x8 per thread; rows paired into f32x2 lanes.
// FUSE: 0 = store, 1 = C += result, 2 = gelu(result)
template<int FUSE>
__global__ __launch_bounds__(256)
void gemm_kernel(const float* __restrict__ A, const float* __restrict__ W,
                 float* __restrict__ C, int N, int K, const int* __restrict__ cnts) {
    int row0 = blockIdx.y * 128, col0 = blockIdx.x * 128;
    if (cnts && (row0 & (SEQ - 1)) >= cnts[row0 >> 10]) return;
    __shared__ float As[8][128];
    __shared__ float Ws[8][128];
    int tid = threadIdx.x;
    int tr = (tid >> 4) << 3;
    int tc = (tid & 15) << 3;
    u64 acc2[4][8];   // [row-pair][col], lane lo = row tr+2p, hi = row tr+2p+1
    #pragma unroll
    for (int p = 0; p < 4; p++)
        #pragma unroll
        for (int j = 0; j < 8; j++) acc2[p][j] = 0ull;
    int la = tid << 2;
    int lar = la >> 3, lac = la & 7;
    const float* Ag = A + (size_t)(row0 + lar) * K + lac;
    int wrow = col0 + lar;
    bool wok = wrow < N;
    const float* Wg = W + (size_t)(wok ? wrow : 0) * K + lac;
    for (int k0 = 0; k0 < K; k0 += 8) {
        float4 av = *(const float4*)(Ag + k0);
        float4 wv = wok ? *(const float4*)(Wg + k0) : make_float4(0.f, 0.f, 0.f, 0.f);
        As[lac + 0][lar] = av.x; As[lac + 1][lar] = av.y;
        As[lac + 2][lar] = av.z; As[lac + 3][lar] = av.w;
        Ws[lac + 0][lar] = wv.x; Ws[lac + 1][lar] = wv.y;
        Ws[lac + 2][lar] = wv.z; Ws[lac + 3][lar] = wv.w;
        __syncthreads();
        #pragma unroll
        for (int k = 0; k < 8; k++) {
            // rows come out of smem already paired (contiguous in As[k][.])
            ulonglong2 aA = *(const ulonglong2*)(&As[k][tr]);
            ulonglong2 aB = *(const ulonglong2*)(&As[k][tr + 4]);
            u64 a2[4] = { aA.x, aA.y, aB.x, aB.y };
            float4 w0 = *(const float4*)(&Ws[k][tc]);
            float4 w1 = *(const float4*)(&Ws[k][tc + 4]);
            u64 wd[8];
            wd[0] = dup2(w0.x); wd[1] = dup2(w0.y); wd[2] = dup2(w0.z); wd[3] = dup2(w0.w);
            wd[4] = dup2(w1.x); wd[5] = dup2(w1.y); wd[6] = dup2(w1.z); wd[7] = dup2(w1.w);
            #pragma unroll
            for (int p = 0; p < 4; p++)
                #pragma unroll
                for (int j = 0; j < 8; j++)
                    acc2[p][j] = fma2(a2[p], wd[j], acc2[p][j]);
        }
        __syncthreads();
    }
    #pragma unroll
    for (int p = 0; p < 4; p++) {
        float* Cr0 = C + (size_t)(row0 + tr + 2 * p) * N;
        float* Cr1 = Cr0 + N;
        #pragma unroll
        for (int j = 0; j < 8; j++) {
            int cc = col0 + tc + j;
            if (cc < N) {
                float lo, hi;
                unpack2(acc2[p][j], lo, hi);
                if (FUSE == 1) { lo += Cr0[cc]; hi += Cr1[cc]; }
                if (FUSE == 2) { lo = gelu_exact(lo); hi = gelu_exact(hi); }
                Cr0[cc] = lo; Cr1[cc] = hi;
            }
        }
    }
}

// ---------------- flash-style causal attention (tile-scores + FFMA2) ----------------
// grid: (BATCH*NHEADS, SEQ/128), block 128 threads, 1 query row per thread.
// NT keys per smem tile; all NT scores computed first (4 independent f32x2 dot
// chains -> ILP 8), then a single max/rescale per tile.
template<int DH, int NT>
__global__ __launch_bounds__(128)
void attn_kernel(const float* __restrict__ qkv, float* __restrict__ out,
                 int D, const int* __restrict__ counts, float scale) {
    const int D3 = 3 * D;
    const int DH2 = DH / 2;
    int b = blockIdx.x >> 2, h = blockIdx.x & 3;
    int tid = threadIdx.x;
    int q = blockIdx.y * 128 + tid;
    __shared__ float Ksh[NT][DH];
    __shared__ float Vsh[NT][DH];
    int cnt = counts ? counts[b] : SEQ;
    float* orow = out + ((size_t)(b * SEQ) + q) * D + h * DH;
    u64* orow2 = (u64*)orow;
    if (counts && (int)(blockIdx.y * 128) >= cnt) {
        #pragma unroll
        for (int d = 0; d < DH2; d++) orow2[d] = 0ull;
        return;
    }
    int qlim = (q < cnt) ? q : -1;               // inclusive max key for this thread
    int limit = min((int)(blockIdx.y * 128 + 127), cnt - 1);  // block-wide max key
    const u64* qrow2 = (const u64*)(qkv + ((size_t)(b * SEQ) + q) * D3 + h * DH);
    u64 q2[DH2], acc2[DH2];
    #pragma unroll
    for (int d = 0; d < DH2; d++) { q2[d] = qrow2[d]; acc2[d] = 0ull; }
    float mval = -1e30f, lsum = 0.f;
    int ntiles = limit / NT + 1;
    for (int kt = 0; kt < ntiles; kt++) {
        int k0 = kt * NT;
        for (int idx = tid; idx < NT * DH; idx += 128) {
            int j = idx / DH, d = idx - j * DH;
            size_t base = ((size_t)(b * SEQ) + (k0 + j)) * D3 + h * DH + d;
            Ksh[j][d] = qkv[base + D];
            Vsh[j][d] = qkv[base + 2 * D];
        }
        __syncthreads();
        int jmax = qlim - k0;                    // inclusive within tile
        if (jmax > NT - 1) jmax = NT - 1;
        if (jmax >= 0) {
            // ---- phase 1: all NT scores, 4 keys in flight ----
            float s[NT];
            #pragma unroll
            for (int j0 = 0; j0 < NT; j0 += 4) {
                u64 s0 = 0ull, s1 = 0ull, s2v = 0ull, s3 = 0ull;
                const u64* K0 = (const u64*)Ksh[j0 + 0];
                const u64* K1 = (const u64*)Ksh[j0 + 1];
                const u64* K2 = (const u64*)Ksh[j0 + 2];
                const u64* K3 = (const u64*)Ksh[j0 + 3];
                #pragma unroll
                for (int d = 0; d < DH2; d++) {
                    u64 qd = q2[d];
                    s0 = fma2(qd, K0[d], s0);
                    s1 = fma2(qd, K1[d], s1);
                    s2v = fma2(qd, K2[d], s2v);
                    s3 = fma2(qd, K3[d], s3);
                }
                float lo, hi;
                unpack2(s0, lo, hi);  s[j0 + 0] = (lo + hi) * scale;
                unpack2(s1, lo, hi);  s[j0 + 1] = (lo + hi) * scale;
                unpack2(s2v, lo, hi); s[j0 + 2] = (lo + hi) * scale;
                unpack2(s3, lo, hi);  s[j0 + 3] = (lo + hi) * scale;
            }
            // ---- phase 2: one rescale per tile ----
            float tmax = -1e30f;
            #pragma unroll
            for (int j = 0; j < NT; j++)
                if (j <= jmax) tmax = fmaxf(tmax, s[j]);
            float newmax = fmaxf(mval, tmax);
            float f = __expf(mval - newmax);
            lsum *= f;
            u64 f2 = dup2(f);
            #pragma unroll
            for (int d = 0; d < DH2; d++) acc2[d] = mul2(acc2[d], f2);
            #pragma unroll
            for (int j = 0; j < NT; j++) {
                float w = (j <= jmax) ? __expf(s[j] - newmax) : 0.f;
                lsum += w;
                u64 w2 = dup2(w);
                const u64* Vj = (const u64*)Vsh[j];
                #pragma unroll
                for (int d = 0; d < DH2; d++) acc2[d] = fma2(w2, Vj[d], acc2[d]);
            }
            mval = newmax;
        }
        __syncthreads();
    }
    if (qlim >= 0) {
        u64 inv2 = dup2(1.f / lsum);
        #pragma unroll
        for (int d = 0; d < DH2; d++) orow2[d] = mul2(acc2[d], inv2);
    } else {
        #pragma unroll
        for (int d = 0; d < DH2; d++) orow2[d] = 0ull;
    }
}

// ---------------- routing: cos similarity of normalized q[l], k[l-1] ----------------
__global__ void route_kernel(const float* __restrict__ q, const float* __restrict__ k,
                             float* __restrict__ p, float* __restrict__ bh) {
    int wid = (blockIdx.x * blockDim.x + threadIdx.x) >> 5;
    int lane = threadIdx.x & 31;
    if (wid >= NROWS) return;
    int l = wid & (SEQ - 1);
    const float* qr = q + (size_t)wid * DENC;
    const float* kr = (l > 0) ? (k + (size_t)(wid - 1) * DENC) : nullptr;
    float nq = 0.f, nk = 0.f, dt = 0.f;
    for (int i = lane; i < DENC; i += 32) {
        float qv = qr[i];
        float kv = kr ? kr[i] : 0.f;
        nq += qv * qv; nk += kv * kv; dt += qv * kv;
    }
    #pragma unroll
    for (int o = 16; o; o >>= 1) {
        nq += __shfl_xor_sync(0xffffffffu, nq, o);
        nk += __shfl_xor_sync(0xffffffffu, nk, o);
        dt += __shfl_xor_sync(0xffffffffu, dt, o);
    }
    if (lane == 0) {
        float denom = fmaxf(sqrtf(nq), 1e-12f) * fmaxf(sqrtf(nk), 1e-12f);
        float cosv = dt / denom;
        float pv = fminf(fmaxf(0.5f * (1.f - cosv), 0.f), 1.f);
        if (l == 0) pv = 1.f;
        p[wid] = pv;
        bh[wid] = (pv >= 0.5f) ? 1.f : 0.f;
    }
}

// ---------------- per-batch inclusive scan of b_hard ----------------
__global__ void scan_kernel(const float* __restrict__ bh, int* __restrict__ cum,
                            int* __restrict__ counts) {
    int b = blockIdx.x, t = threadIdx.x;   // 1024 threads
    __shared__ int s[SEQ];
    s[t] = (int)bh[b * SEQ + t];
    __syncthreads();
    for (int o = 1; o < SEQ; o <<= 1) {
        int add = (t >= o) ? s[t - o] : 0;
        __syncthreads();
        s[t] += add;
        __syncthreads();
    }
    cum[b * SEQ + t] = s[t];
    if (t == SEQ - 1) counts[b] = s[t];
}

// ---------------- ratio loss (single block, deterministic) ----------------
__global__ void stats_kernel(const float* __restrict__ bh, const float* __restrict__ p,
                             float* __restrict__ loss) {
    int t = threadIdx.x;   // 1024
    __shared__ float rb[1024], rp[1024];
    float sb = 0.f, sp = 0.f;
    for (int i = t; i < NROWS; i += 1024) { sb += bh[i]; sp += p[i]; }
    rb[t] = sb; rp[t] = sp;
    __syncthreads();
    for (int o = 512; o; o >>= 1) {
        if (t < o) { rb[t] += rb[t + o]; rp[t] += rp[t + o]; }
        __syncthreads();
    }
    if (t == 0) {
        float F = rb[0] / (float)NROWS, G = rp[0] / (float)NROWS;
        loss[0] = 1.2f * (5.f * F * G + (1.f - F) * (1.f - G));
    }
}

__global__ void zero_kernel(float* __restrict__ ptr, int n) {
    int i = blockIdx.x * blockDim.x + threadIdx.x;
    if (i < n) ptr[i] = 0.f;
}

// ---------------- scatter selected rows to front (downsample) ----------------
__global__ void scatter_kernel(const float* __restrict__ x, const float* __restrict__ p,
                               const float* __restrict__ bh, const int* __restrict__ cum,
                               float* __restrict__ comp, float* __restrict__ pcomp) {
    int row = blockIdx.x;
    if (bh[row] < 0.5f) return;
    int b = row >> 10;
    int dst = cum[row] - 1;
    int t = threadIdx.x;
    comp[((size_t)(b << 10) + dst) * DENC + t] = x[(size_t)row * DENC + t];
    if (t == 0) pcomp[(b << 10) + dst] = p[row];
}

// ---------------- EMA linear recurrence scan ----------------
__global__ void ema_kernel(const float* __restrict__ z, const float* __restrict__ pc,
                           float* __restrict__ zbar, const int* __restrict__ counts) {
    int b = blockIdx.x, d = threadIdx.x;   // 128 threads
    const float* zb = z + (size_t)b * SEQ * DENC;
    float* ob = zbar + (size_t)b * SEQ * DENC;
    const float* pb = pc + b * SEQ;
    int Tn = counts[b];
    float prev = 0.f;
    for (int t = 0; t < Tn; t++) {
        float pv = pb[t];
        float pcl = fminf(fmaxf(pv, 1e-4f), 0.9999f);
        float zv = zb[(size_t)t * DENC + d];
        float cur = (t == 0) ? zv : ((1.f - pcl) * prev + pcl * zv);
        ob[(size_t)t * DENC + d] = cur;
        prev = cur;
    }
}

// ---------------- gather + STE residual add ----------------
__global__ void gather_kernel(const float* __restrict__ zbar, const int* __restrict__ cum,
                              const float* __restrict__ p, const float* __restrict__ bh,
                              float* __restrict__ x) {
    int row = blockIdx.x, t = threadIdx.x;
    int b = row >> 10;
    int ci = cum[row] - 1; if (ci < 0) ci = 0;
    float pv = p[row], bv = bh[row];
    float c = bv * pv + (1.f - bv) * (1.f - pv);
    float cste = c + (1.f - c);   // forward value of STE (match ref rounding)
    x[(size_t)row * DENC + t] += cste * zbar[((size_t)(b << 10) + ci) * DENC + t];
}

__global__ void tail_kernel(float* __restrict__ dst, const float* __restrict__ loss) {
    dst[0] = loss[0];
}

// ---------------- host orchestration ----------------
static void* symaddr(const void* sym) {
    void* p = nullptr;
    cudaGetSymbolAddress(&p, sym);
    return p;
}

static const int PERM_SIG[32] = {
    0,1,2,3, 4,5,6,7,8,9,10,11, 12, 13,14,15,16,17,18,19,20, 21, 22,23,24,25,26,27,28,29, 30,31
};
static const int PERM_DICT[32] = {
    0,1,2,3, 8,9,10,11,12,13,14,15, 4, 16,17,18,19,20,21,22,23, 5, 24,25,26,27,28,29,30,31, 6,7
};
static const int PERM_ALPHA[32] = {
    0,9,31,30, 11,10,14,17,13,12,15,16, 29, 19,18,22,25,21,20,23,24, 28, 2,1,5,8,4,3,6,7, 27,26
};

extern "C" void kernel_launch(void* const* d_in, const int* in_sizes, int n_in,
                              void* d_out, int out_size) {
    (void)n_in;
    const int* perm;
    if (in_sizes[1] == 3 * DENC)            perm = PERM_ALPHA;
    else if (in_sizes[4] == DMAIN * DENC)   perm = PERM_DICT;
    else                                    perm = PERM_SIG;

    const float* inp[32];
    for (int i = 0; i < 32; i++) inp[i] = (const float*)d_in[perm[i]];

    const int*   ids       = (const int*)d_in[perm[0]];
    const float* embed     = inp[1];
    const float* wq        = inp[2];
    const float* wk        = inp[3];
    const float* enc_ln1w  = inp[4];
    const float* enc_ln1b  = inp[5];
    const float* enc_qkvw  = inp[6];
    const float* enc_wo    = inp[7];
    const float* enc_ln2w  = inp[8];
    const float* enc_ln2b  = inp[9];
    const float* enc_w1    = inp[10];
    const float* enc_w2    = inp[11];
    const float* proj_up   = inp[12];
    const float* mn_ln1w   = inp[13];
    const float* mn_ln1b   = inp[14];
    const float* mn_qkvw   = inp[15];
    const float* mn_wo     = inp[16];
    const float* mn_ln2w   = inp[17];
    const float* mn_ln2b   = inp[18];
    const float* mn_w1     = inp[19];
    const float* mn_w2     = inp[20];
    const float* proj_down = inp[21];
    const float* dc_ln1w   = inp[22];
    const float* dc_ln1b   = inp[23];
    const float* dc_qkvw   = inp[24];
    const float* dc_wo     = inp[25];
    const float* dc_ln2w   = inp[26];
    const float* dc_ln2b   = inp[27];
    const float* dc_w1     = inp[28];
    const float* dc_w2     = inp[29];
    const float* norm_w    = inp[30];
    const float* norm_b    = inp[31];

    float* x     = (float*)symaddr(g_x);
    float* lnp   = (float*)symaddr(g_lnbuf);
    float* qkvp  = (float*)symaddr(g_qkv);
    float* attp  = (float*)symaddr(g_att);
    float* mlpp  = (float*)symaddr(g_mlp);
    float* zp    = (float*)symaddr(g_z);
    float* compp = (float*)symaddr(g_comp);
    float* qrp   = (float*)symaddr(g_qr);
    float* krp   = (float*)symaddr(g_kr);
    float* zdp   = (float*)symaddr(g_zdown);
    float* zbp   = (float*)symaddr(g_zbar);
    float* pp    = (float*)symaddr(g_p);
    float* bhp   = (float*)symaddr(g_bh);
    float* pcp   = (float*)symaddr(g_pcomp);
    int*   cump  = (int*)symaddr(g_cum);
    int*   cntp  = (int*)symaddr(g_counts);
    float* lossp = (float*)symaddr(g_loss);

    auto run_block = [&](float* xb, int D, int dh,
                         const float* l1w, const float* l1b,
                         const float* qw, const float* wo,
                         const float* l2w, const float* l2b,
                         const float* w1, const float* w2,
                         const int* cnts) {
        int D3 = 3 * D;
        ln_kernel<<<NROWS, D>>>(xb, l1w, l1b, lnp, D, cnts);
        gemm_kernel<0><<<dim3(D3 / 128, 64), 256>>>(lnp, qw, qkvp, D3, D, cnts);
        if (dh == 32)
            attn_kernel<32, 32><<<dim3(BATCH * NHEADS, SEQ / 128), 128>>>(qkvp, attp, D, cnts, 0.17677669529663687f);
        else
            attn_kernel<64, 16><<<dim3(BATCH * NHEADS, SEQ / 128), 128>>>(qkvp, attp, D, cnts, 0.125f);
        gemm_kernel<1><<<dim3(D / 128, 64), 256>>>(attp, wo, xb, D, D, cnts);
        ln_kernel<<<NROWS, D>>>(xb, l2w, l2b, lnp, D, cnts);
        gemm_kernel<2><<<dim3(2 * D / 128, 64), 256>>>(lnp, w1, mlpp, 2 * D, D, cnts);
        gemm_kernel<1><<<dim3(D / 128, 64), 256>>>(mlpp, w2, xb, D, 2 * D, cnts);
    };

    // ---- encoder ----
    embed_kernel<<<NROWS, DENC>>>(ids, embed, x);
    for (int i = 0; i < 3; i++)
        run_block(x, DENC, 32,
                  enc_ln1w + i * DENC, enc_ln1b + i * DENC,
                  enc_qkvw + (size_t)i * 3 * DENC * DENC,
                  enc_wo   + (size_t)i * DENC * DENC,
                  enc_ln2w + i * DENC, enc_ln2b + i * DENC,
                  enc_w1   + (size_t)i * 2 * DENC * DENC,
                  enc_w2   + (size_t)i * 2 * DENC * DENC,
                  nullptr);

    // ---- routing / dynamic chunking ----
    gemm_kernel<0><<<dim3(1, 64), 256>>>(x, wq, qrp, DENC, DENC, nullptr);
    gemm_kernel<0><<<dim3(1, 64), 256>>>(x, wk, krp, DENC, DENC, nullptr);
    route_kernel<<<NROWS / 8, 256>>>(qrp, krp, pp, bhp);
    scan_kernel<<<BATCH, SEQ>>>(bhp, cump, cntp);
    stats_kernel<<<1, 1024>>>(bhp, pp, lossp);
    zero_kernel<<<(NROWS * DENC + 255) / 256, 256>>>(compp, NROWS * DENC);
    zero_kernel<<<(NROWS + 255) / 256, 256>>>(pcp, NROWS);
    scatter_kernel<<<NROWS, DENC>>>(x, pp, bhp, cump, compp, pcp);

    // ---- main stack (padded + masked; padded rows dynamically elided) ----
    gemm_kernel<0><<<dim3(2, 64), 256>>>(compp, proj_up, zp, DMAIN, DENC, cntp);
    for (int i = 0; i < 6; i++)
        run_block(zp, DMAIN, 64,
                  mn_ln1w + i * DMAIN, mn_ln1b + i * DMAIN,
                  mn_qkvw + (size_t)i * 3 * DMAIN * DMAIN,
                  mn_wo   + (size_t)i * DMAIN * DMAIN,
                  mn_ln2w + i * DMAIN, mn_ln2b + i * DMAIN,
                  mn_w1   + (size_t)i * 2 * DMAIN * DMAIN,
                  mn_w2   + (size_t)i * 2 * DMAIN * DMAIN,
                  cntp);
    gemm_kernel<0><<<dim3(1, 64), 256>>>(zp, proj_down, zdp, DENC, DMAIN, cntp);

    // ---- EMA scan + gather + STE add ----
    ema_kernel<<<BATCH, DENC>>>(zdp, pcp, zbp, cntp);
    gather_kernel<<<NROWS, DENC>>>(zbp, cump, pp, bhp, x);

    // ---- decoder ----
    for (int i = 0; i < 3; i++)
        run_block(x, DENC, 32,
                  dc_ln1w + i * DENC, dc_ln1b + i * DENC,
                  dc_qkvw + (size_t)i * 3 * DENC * DENC,
                  dc_wo   + (size_t)i * DENC * DENC,
                  dc_ln2w + i * DENC, dc_ln2b + i * DENC,
                  dc_w1   + (size_t)i * 2 * DENC * DENC,
                  dc_w2   + (size_t)i * 2 * DENC * DENC,
                  nullptr);

    // ---- final norm + tied logits head ----
    ln_kernel<<<NROWS, DENC>>>(x, norm_w, norm_b, lnp, DENC, nullptr);
    gemm_kernel<0><<<dim3(3, 64), 256>>>(lnp, embed, (float*)d_out, 260, DENC, nullptr);

    const int NLOGITS = NROWS * 260;
    if (out_size > NLOGITS)
        tail_kernel<<<1, 1>>>((float*)d_out + NLOGITS, lossp);
}

// round 13
// speedup vs baseline: 1.1012x; 1.0001x over previous
#include <cuda_runtime.h>
#include <cuda_bf16.h>
#include <math.h>

#define BATCH 8
#define SEQ   1024
#define NROWS (BATCH*SEQ)   // 8192
#define DENC  128
#define DMAIN 256
#define NHEADS 4

// ---------------- scratch (device globals: no allocation in kernel_launch) ----------------
__device__ float g_x[NROWS*DENC];
__device__ float g_lnbuf[NROWS*DMAIN];
__device__ float g_qkv[NROWS*3*DMAIN];
__device__ float g_att[NROWS*DMAIN];
__device__ float g_mlp[NROWS*2*DMAIN];
__device__ float g_z[NROWS*DMAIN];
__device__ float g_comp[NROWS*DENC];
__device__ float g_qr[NROWS*DENC];
__device__ float g_kr[NROWS*DENC];
__device__ float g_zdown[NROWS*DENC];
__device__ float g_zbar[NROWS*DENC];
__device__ float g_p[NROWS];
__device__ float g_bh[NROWS];
__device__ float g_pcomp[NROWS];
__device__ int   g_cum[NROWS];
__device__ int   g_counts[BATCH];
__device__ float g_loss[1];

// ---------------- f32x2 packed-FMA helpers (Blackwell FFMA2, PTX-only) ----------------
typedef unsigned long long u64;
__device__ __forceinline__ u64 dup2(float v) {
    u64 r; asm("mov.b64 %0, {%1, %1};" : "=l"(r) : "f"(v)); return r;
}
__device__ __forceinline__ void unpack2(u64 v, float& lo, float& hi) {
    asm("mov.b64 {%0, %1}, %2;" : "=f"(lo), "=f"(hi) : "l"(v));
}
__device__ __forceinline__ u64 fma2(u64 a, u64 b, u64 c) {
    u64 d; asm("fma.rn.f32x2 %0, %1, %2, %3;" : "=l"(d) : "l"(a), "l"(b), "l"(c)); return d;
}
__device__ __forceinline__ u64 mul2(u64 a, u64 b) {
    u64 d; asm("mul.rn.f32x2 %0, %1, %2;" : "=l"(d) : "l"(a), "l"(b)); return d;
}

// ---------------- helpers ----------------
__device__ __forceinline__ float gelu_exact(float v) {
    return 0.5f * v * (1.0f + erff(v * 0.70710678118654752440f));
}

// ---------------- embedding lookup ----------------
__global__ void embed_kernel(const int* __restrict__ ids, const float* __restrict__ emb,
                             float* __restrict__ x) {
    int row = blockIdx.x;
    int t = threadIdx.x;
    x[(size_t)row * DENC + t] = emb[(size_t)ids[row] * DENC + t];
}

// ---------------- LayerNorm (one block per row, blockDim = D) ----------------
__global__ void ln_kernel(const float* __restrict__ x, const float* __restrict__ w,
                          const float* __restrict__ b, float* __restrict__ y, int D,
                          const int* __restrict__ cnts) {
    int row = blockIdx.x;
    if (cnts && (row & (SEQ - 1)) >= cnts[row >> 10]) return;
    int t = threadIdx.x;
    __shared__ float sw[8];
    __shared__ float sbr;
    float v = x[(size_t)row * D + t];
    float s = v;
    #pragma unroll
    for (int o = 16; o; o >>= 1) s += __shfl_xor_sync(0xffffffffu, s, o);
    if ((t & 31) == 0) sw[t >> 5] = s;
    __syncthreads();
    if (t == 0) {
        float tot = 0.f; int nw = D >> 5;
        for (int i = 0; i < nw; i++) tot += sw[i];
        sbr = tot / (float)D;
    }
    __syncthreads();
    float mu = sbr;
    float dlt = v - mu;
    s = dlt * dlt;
    #pragma unroll
    for (int o = 16; o; o >>= 1) s += __shfl_xor_sync(0xffffffffu, s, o);
    __syncthreads();
    if ((t & 31) == 0) sw[t >> 5] = s;
    __syncthreads();
    if (t == 0) {
        float tot = 0.f; int nw = D >> 5;
        for (int i = 0; i < nw; i++) tot += sw[i];
        sbr = rsqrtf(tot / (float)D + 1e-5f);
    }
    __syncthreads();
    y[(size_t)row * D + t] = dlt * sbr * w[t] + b[t];
}

// ---------------- SGEMM (FFMA2): C[M,N] (+)= act(A[M,K] @ W[N,K]^T) ----------------
// BM=BN=128, BK=8, 256 threads, 8x8 per thread; rows paired into f32x2 lanes.
// FUSE: 0 = store, 1 = C += result, 2 = gelu(result)
template<int FUSE>
__global__ __launch_bounds__(256)
void gemm_kernel(const float* __restrict__ A, const float* __restrict__ W,
                 float* __restrict__ C, int N, int K, const int* __restrict__ cnts) {
    int row0 = blockIdx.y * 128, col0 = blockIdx.x * 128;
    if (cnts && (row0 & (SEQ - 1)) >= cnts[row0 >> 10]) return;
    __shared__ float As[8][128];
    __shared__ float Ws[8][128];
    int tid = threadIdx.x;
    int tr = (tid >> 4) << 3;
    int tc = (tid & 15) << 3;
    u64 acc2[4][8];   // [row-pair][col], lane lo = row tr+2p, hi = row tr+2p+1
    #pragma unroll
    for (int p = 0; p < 4; p++)
        #pragma unroll
        for (int j = 0; j < 8; j++) acc2[p][j] = 0ull;
    int la = tid << 2;
    int lar = la >> 3, lac = la & 7;
    const float* Ag = A + (size_t)(row0 + lar) * K + lac;
    int wrow = col0 + lar;
    bool wok = wrow < N;
    const float* Wg = W + (size_t)(wok ? wrow : 0) * K + lac;
    for (int k0 = 0; k0 < K; k0 += 8) {
        float4 av = *(const float4*)(Ag + k0);
        float4 wv = wok ? *(const float4*)(Wg + k0) : make_float4(0.f, 0.f, 0.f, 0.f);
        As[lac + 0][lar] = av.x; As[lac + 1][lar] = av.y;
        As[lac + 2][lar] = av.z; As[lac + 3][lar] = av.w;
        Ws[lac + 0][lar] = wv.x; Ws[lac + 1][lar] = wv.y;
        Ws[lac + 2][lar] = wv.z; Ws[lac + 3][lar] = wv.w;
        __syncthreads();
        #pragma unroll
        for (int k = 0; k < 8; k++) {
            // rows come out of smem already paired (contiguous in As[k][.])
            ulonglong2 aA = *(const ulonglong2*)(&As[k][tr]);
            ulonglong2 aB = *(const ulonglong2*)(&As[k][tr + 4]);
            u64 a2[4] = { aA.x, aA.y, aB.x, aB.y };
            float4 w0 = *(const float4*)(&Ws[k][tc]);
            float4 w1 = *(const float4*)(&Ws[k][tc + 4]);
            u64 wd[8];
            wd[0] = dup2(w0.x); wd[1] = dup2(w0.y); wd[2] = dup2(w0.z); wd[3] = dup2(w0.w);
            wd[4] = dup2(w1.x); wd[5] = dup2(w1.y); wd[6] = dup2(w1.z); wd[7] = dup2(w1.w);
            #pragma unroll
            for (int p = 0; p < 4; p++)
                #pragma unroll
                for (int j = 0; j < 8; j++)
                    acc2[p][j] = fma2(a2[p], wd[j], acc2[p][j]);
        }
        __syncthreads();
    }
    #pragma unroll
    for (int p = 0; p < 4; p++) {
        float* Cr0 = C + (size_t)(row0 + tr + 2 * p) * N;
        float* Cr1 = Cr0 + N;
        #pragma unroll
        for (int j = 0; j < 8; j++) {
            int cc = col0 + tc + j;
            if (cc < N) {
                float lo, hi;
                unpack2(acc2[p][j], lo, hi);
                if (FUSE == 1) { lo += Cr0[cc]; hi += Cr1[cc]; }
                if (FUSE == 2) { lo = gelu_exact(lo); hi = gelu_exact(hi); }
                Cr0[cc] = lo; Cr1[cc] = hi;
            }
        }
    }
}

// ---------------- flash-style causal attention (tile-scores + FFMA2) ----------------
// grid: (BATCH*NHEADS, SEQ/128), block 128 threads, 1 query row per thread.
// NT keys per smem tile; all NT scores computed first (4 independent f32x2 dot
// chains -> ILP 8), then a single max/rescale per tile.
template<int DH, int NT>
__global__ __launch_bounds__(128)
void attn_kernel(const float* __restrict__ qkv, float* __restrict__ out,
                 int D, const int* __restrict__ counts, float scale) {
    const int D3 = 3 * D;
    const int DH2 = DH / 2;
    int b = blockIdx.x >> 2, h = blockIdx.x & 3;
    int tid = threadIdx.x;
    int q = blockIdx.y * 128 + tid;
    __shared__ float Ksh[NT][DH];
    __shared__ float Vsh[NT][DH];
    int cnt = counts ? counts[b] : SEQ;
    float* orow = out + ((size_t)(b * SEQ) + q) * D + h * DH;
    u64* orow2 = (u64*)orow;
    if (counts && (int)(blockIdx.y * 128) >= cnt) {
        #pragma unroll
        for (int d = 0; d < DH2; d++) orow2[d] = 0ull;
        return;
    }
    int qlim = (q < cnt) ? q : -1;               // inclusive max key for this thread
    int limit = min((int)(blockIdx.y * 128 + 127), cnt - 1);  // block-wide max key
    const u64* qrow2 = (const u64*)(qkv + ((size_t)(b * SEQ) + q) * D3 + h * DH);
    u64 q2[DH2], acc2[DH2];
    #pragma unroll
    for (int d = 0; d < DH2; d++) { q2[d] = qrow2[d]; acc2[d] = 0ull; }
    float mval = -1e30f, lsum = 0.f;
    int ntiles = limit / NT + 1;
    for (int kt = 0; kt < ntiles; kt++) {
        int k0 = kt * NT;
        for (int idx = tid; idx < NT * DH; idx += 128) {
            int j = idx / DH, d = idx - j * DH;
            size_t base = ((size_t)(b * SEQ) + (k0 + j)) * D3 + h * DH + d;
            Ksh[j][d] = qkv[base + D];
            Vsh[j][d] = qkv[base + 2 * D];
        }
        __syncthreads();
        int jmax = qlim - k0;                    // inclusive within tile
        if (jmax > NT - 1) jmax = NT - 1;
        if (jmax >= 0) {
            // ---- phase 1: all NT scores, 4 keys in flight ----
            float s[NT];
            #pragma unroll
            for (int j0 = 0; j0 < NT; j0 += 4) {
                u64 s0 = 0ull, s1 = 0ull, s2v = 0ull, s3 = 0ull;
                const u64* K0 = (const u64*)Ksh[j0 + 0];
                const u64* K1 = (const u64*)Ksh[j0 + 1];
                const u64* K2 = (const u64*)Ksh[j0 + 2];
                const u64* K3 = (const u64*)Ksh[j0 + 3];
                #pragma unroll
                for (int d = 0; d < DH2; d++) {
                    u64 qd = q2[d];
                    s0 = fma2(qd, K0[d], s0);
                    s1 = fma2(qd, K1[d], s1);
                    s2v = fma2(qd, K2[d], s2v);
                    s3 = fma2(qd, K3[d], s3);
                }
                float lo, hi;
                unpack2(s0, lo, hi);  s[j0 + 0] = (lo + hi) * scale;
                unpack2(s1, lo, hi);  s[j0 + 1] = (lo + hi) * scale;
                unpack2(s2v, lo, hi); s[j0 + 2] = (lo + hi) * scale;
                unpack2(s3, lo, hi);  s[j0 + 3] = (lo + hi) * scale;
            }
            // ---- phase 2: one rescale per tile ----
            float tmax = -1e30f;
            #pragma unroll
            for (int j = 0; j < NT; j++)
                if (j <= jmax) tmax = fmaxf(tmax, s[j]);
            float newmax = fmaxf(mval, tmax);
            float f = __expf(mval - newmax);
            lsum *= f;
            u64 f2 = dup2(f);
            #pragma unroll
            for (int d = 0; d < DH2; d++) acc2[d] = mul2(acc2[d], f2);
            #pragma unroll
            for (int j = 0; j < NT; j++) {
                float w = (j <= jmax) ? __expf(s[j] - newmax) : 0.f;
                lsum += w;
                u64 w2 = dup2(w);
                const u64* Vj = (const u64*)Vsh[j];
                #pragma unroll
                for (int d = 0; d < DH2; d++) acc2[d] = fma2(w2, Vj[d], acc2[d]);
            }
            mval = newmax;
        }
        __syncthreads();
    }
    if (qlim >= 0) {
        u64 inv2 = dup2(1.f / lsum);
        #pragma unroll
        for (int d = 0; d < DH2; d++) orow2[d] = mul2(acc2[d], inv2);
    } else {
        #pragma unroll
        for (int d = 0; d < DH2; d++) orow2[d] = 0ull;
    }
}

// ---------------- routing: cos similarity of normalized q[l], k[l-1] ----------------
__global__ void route_kernel(const float* __restrict__ q, const float* __restrict__ k,
                             float* __restrict__ p, float* __restrict__ bh) {
    int wid = (blockIdx.x * blockDim.x + threadIdx.x) >> 5;
    int lane = threadIdx.x & 31;
    if (wid >= NROWS) return;
    int l = wid & (SEQ - 1);
    const float* qr = q + (size_t)wid * DENC;
    const float* kr = (l > 0) ? (k + (size_t)(wid - 1) * DENC) : nullptr;
    float nq = 0.f, nk = 0.f, dt = 0.f;
    for (int i = lane; i < DENC; i += 32) {
        float qv = qr[i];
        float kv = kr ? kr[i] : 0.f;
        nq += qv * qv; nk += kv * kv; dt += qv * kv;
    }
    #pragma unroll
    for (int o = 16; o; o >>= 1) {
        nq += __shfl_xor_sync(0xffffffffu, nq, o);
        nk += __shfl_xor_sync(0xffffffffu, nk, o);
        dt += __shfl_xor_sync(0xffffffffu, dt, o);
    }
    if (lane == 0) {
        float denom = fmaxf(sqrtf(nq), 1e-12f) * fmaxf(sqrtf(nk), 1e-12f);
        float cosv = dt / denom;
        float pv = fminf(fmaxf(0.5f * (1.f - cosv), 0.f), 1.f);
        if (l == 0) pv = 1.f;
        p[wid] = pv;
        bh[wid] = (pv >= 0.5f) ? 1.f : 0.f;
    }
}

// ---------------- per-batch inclusive scan of b_hard ----------------
__global__ void scan_kernel(const float* __restrict__ bh, int* __restrict__ cum,
                            int* __restrict__ counts) {
    int b = blockIdx.x, t = threadIdx.x;   // 1024 threads
    __shared__ int s[SEQ];
    s[t] = (int)bh[b * SEQ + t];
    __syncthreads();
    for (int o = 1; o < SEQ; o <<= 1) {
        int add = (t >= o) ? s[t - o] : 0;
        __syncthreads();
        s[t] += add;
        __syncthreads();
    }
    cum[b * SEQ + t] = s[t];
    if (t == SEQ - 1) counts[b] = s[t];
}

// ---------------- ratio loss (single block, deterministic) ----------------
__global__ void stats_kernel(const float* __restrict__ bh, const float* __restrict__ p,
                             float* __restrict__ loss) {
    int t = threadIdx.x;   // 1024
    __shared__ float rb[1024], rp[1024];
    float sb = 0.f, sp = 0.f;
    for (int i = t; i < NROWS; i += 1024) { sb += bh[i]; sp += p[i]; }
    rb[t] = sb; rp[t] = sp;
    __syncthreads();
    for (int o = 512; o; o >>= 1) {
        if (t < o) { rb[t] += rb[t + o]; rp[t] += rp[t + o]; }
        __syncthreads();
    }
    if (t == 0) {
        float F = rb[0] / (float)NROWS, G = rp[0] / (float)NROWS;
        loss[0] = 1.2f * (5.f * F * G + (1.f - F) * (1.f - G));
    }
}

__global__ void zero_kernel(float* __restrict__ ptr, int n) {
    int i = blockIdx.x * blockDim.x + threadIdx.x;
    if (i < n) ptr[i] = 0.f;
}

// ---------------- scatter selected rows to front (downsample) ----------------
__global__ void scatter_kernel(const float* __restrict__ x, const float* __restrict__ p,
                               const float* __restrict__ bh, const int* __restrict__ cum,
                               float* __restrict__ comp, float* __restrict__ pcomp) {
    int row = blockIdx.x;
    if (bh[row] < 0.5f) return;
    int b = row >> 10;
    int dst = cum[row] - 1;
    int t = threadIdx.x;
    comp[((size_t)(b << 10) + dst) * DENC + t] = x[(size_t)row * DENC + t];
    if (t == 0) pcomp[(b << 10) + dst] = p[row];
}

// ---------------- EMA linear recurrence scan ----------------
__global__ void ema_kernel(const float* __restrict__ z, const float* __restrict__ pc,
                           float* __restrict__ zbar, const int* __restrict__ counts) {
    int b = blockIdx.x, d = threadIdx.x;   // 128 threads
    const float* zb = z + (size_t)b * SEQ * DENC;
    float* ob = zbar + (size_t)b * SEQ * DENC;
    const float* pb = pc + b * SEQ;
    int Tn = counts[b];
    float prev = 0.f;
    for (int t = 0; t < Tn; t++) {
        float pv = pb[t];
        float pcl = fminf(fmaxf(pv, 1e-4f), 0.9999f);
        float zv = zb[(size_t)t * DENC + d];
        float cur = (t == 0) ? zv : ((1.f - pcl) * prev + pcl * zv);
        ob[(size_t)t * DENC + d] = cur;
        prev = cur;
    }
}

// ---------------- gather + STE residual add ----------------
__global__ void gather_kernel(const float* __restrict__ zbar, const int* __restrict__ cum,
                              const float* __restrict__ p, const float* __restrict__ bh,
                              float* __restrict__ x) {
    int row = blockIdx.x, t = threadIdx.x;
    int b = row >> 10;
    int ci = cum[row] - 1; if (ci < 0) ci = 0;
    float pv = p[row], bv = bh[row];
    float c = bv * pv + (1.f - bv) * (1.f - pv);
    float cste = c + (1.f - c);   // forward value of STE (match ref rounding)
    x[(size_t)row * DENC + t] += cste * zbar[((size_t)(b << 10) + ci) * DENC + t];
}

__global__ void tail_kernel(float* __restrict__ dst, const float* __restrict__ loss) {
    dst[0] = loss[0];
}

// ---------------- host orchestration ----------------
static void* symaddr(const void* sym) {
    void* p = nullptr;
    cudaGetSymbolAddress(&p, sym);
    return p;
}

static const int PERM_SIG[32] = {
    0,1,2,3, 4,5,6,7,8,9,10,11, 12, 13,14,15,16,17,18,19,20, 21, 22,23,24,25,26,27,28,29, 30,31
};
static const int PERM_DICT[32] = {
    0,1,2,3, 8,9,10,11,12,13,14,15, 4, 16,17,18,19,20,21,22,23, 5, 24,25,26,27,28,29,30,31, 6,7
};
static const int PERM_ALPHA[32] = {
    0,9,31,30, 11,10,14,17,13,12,15,16, 29, 19,18,22,25,21,20,23,24, 28, 2,1,5,8,4,3,6,7, 27,26
};

extern "C" void kernel_launch(void* const* d_in, const int* in_sizes, int n_in,
                              void* d_out, int out_size) {
    (void)n_in;
    const int* perm;
    if (in_sizes[1] == 3 * DENC)            perm = PERM_ALPHA;
    else if (in_sizes[4] == DMAIN * DENC)   perm = PERM_DICT;
    else                                    perm = PERM_SIG;

    const float* inp[32];
    for (int i = 0; i < 32; i++) inp[i] = (const float*)d_in[perm[i]];

    const int*   ids       = (const int*)d_in[perm[0]];
    const float* embed     = inp[1];
    const float* wq        = inp[2];
    const float* wk        = inp[3];
    const float* enc_ln1w  = inp[4];
    const float* enc_ln1b  = inp[5];
    const float* enc_qkvw  = inp[6];
    const float* enc_wo    = inp[7];
    const float* enc_ln2w  = inp[8];
    const float* enc_ln2b  = inp[9];
    const float* enc_w1    = inp[10];
    const float* enc_w2    = inp[11];
    const float* proj_up   = inp[12];
    const float* mn_ln1w   = inp[13];
    const float* mn_ln1b   = inp[14];
    const float* mn_qkvw   = inp[15];
    const float* mn_wo     = inp[16];
    const float* mn_ln2w   = inp[17];
    const float* mn_ln2b   = inp[18];
    const float* mn_w1     = inp[19];
    const float* mn_w2     = inp[20];
    const float* proj_down = inp[21];
    const float* dc_ln1w   = inp[22];
    const float* dc_ln1b   = inp[23];
    const float* dc_qkvw   = inp[24];
    const float* dc_wo     = inp[25];
    const float* dc_ln2w   = inp[26];
    const float* dc_ln2b   = inp[27];
    const float* dc_w1     = inp[28];
    const float* dc_w2     = inp[29];
    const float* norm_w    = inp[30];
    const float* norm_b    = inp[31];

    float* x     = (float*)symaddr(g_x);
    float* lnp   = (float*)symaddr(g_lnbuf);
    float* qkvp  = (float*)symaddr(g_qkv);
    float* attp  = (float*)symaddr(g_att);
    float* mlpp  = (float*)symaddr(g_mlp);
    float* zp    = (float*)symaddr(g_z);
    float* compp = (float*)symaddr(g_comp);
    float* qrp   = (float*)symaddr(g_qr);
    float* krp   = (float*)symaddr(g_kr);
    float* zdp   = (float*)symaddr(g_zdown);
    float* zbp   = (float*)symaddr(g_zbar);
    float* pp    = (float*)symaddr(g_p);
    float* bhp   = (float*)symaddr(g_bh);
    float* pcp   = (float*)symaddr(g_pcomp);
    int*   cump  = (int*)symaddr(g_cum);
    int*   cntp  = (int*)symaddr(g_counts);
    float* lossp = (float*)symaddr(g_loss);

    auto run_block = [&](float* xb, int D, int dh,
                         const float* l1w, const float* l1b,
                         const float* qw, const float* wo,
                         const float* l2w, const float* l2b,
                         const float* w1, const float* w2,
                         const int* cnts) {
        int D3 = 3 * D;
        ln_kernel<<<NROWS, D>>>(xb, l1w, l1b, lnp, D, cnts);
        gemm_kernel<0><<<dim3(D3 / 128, 64), 256>>>(lnp, qw, qkvp, D3, D, cnts);
        if (dh == 32)
            attn_kernel<32, 32><<<dim3(BATCH * NHEADS, SEQ / 128), 128>>>(qkvp, attp, D, cnts, 0.17677669529663687f);
        else
            attn_kernel<64, 16><<<dim3(BATCH * NHEADS, SEQ / 128), 128>>>(qkvp, attp, D, cnts, 0.125f);
        gemm_kernel<1><<<dim3(D / 128, 64), 256>>>(attp, wo, xb, D, D, cnts);
        ln_kernel<<<NROWS, D>>>(xb, l2w, l2b, lnp, D, cnts);
        gemm_kernel<2><<<dim3(2 * D / 128, 64), 256>>>(lnp, w1, mlpp, 2 * D, D, cnts);
        gemm_kernel<1><<<dim3(D / 128, 64), 256>>>(mlpp, w2, xb, D, 2 * D, cnts);
    };

    // ---- encoder ----
    embed_kernel<<<NROWS, DENC>>>(ids, embed, x);
    for (int i = 0; i < 3; i++)
        run_block(x, DENC, 32,
                  enc_ln1w + i * DENC, enc_ln1b + i * DENC,
                  enc_qkvw + (size_t)i * 3 * DENC * DENC,
                  enc_wo   + (size_t)i * DENC * DENC,
                  enc_ln2w + i * DENC, enc_ln2b + i * DENC,
                  enc_w1   + (size_t)i * 2 * DENC * DENC,
                  enc_w2   + (size_t)i * 2 * DENC * DENC,
                  nullptr);

    // ---- routing / dynamic chunking ----
    gemm_kernel<0><<<dim3(1, 64), 256>>>(x, wq, qrp, DENC, DENC, nullptr);
    gemm_kernel<0><<<dim3(1, 64), 256>>>(x, wk, krp, DENC, DENC, nullptr);
    route_kernel<<<NROWS / 8, 256>>>(qrp, krp, pp, bhp);
    scan_kernel<<<BATCH, SEQ>>>(bhp, cump, cntp);
    stats_kernel<<<1, 1024>>>(bhp, pp, lossp);
    zero_kernel<<<(NROWS * DENC + 255) / 256, 256>>>(compp, NROWS * DENC);
    zero_kernel<<<(NROWS + 255) / 256, 256>>>(pcp, NROWS);
    scatter_kernel<<<NROWS, DENC>>>(x, pp, bhp, cump, compp, pcp);

    // ---- main stack (padded + masked; padded rows dynamically elided) ----
    gemm_kernel<0><<<dim3(2, 64), 256>>>(compp, proj_up, zp, DMAIN, DENC, cntp);
    for (int i = 0; i < 6; i++)
        run_block(zp, DMAIN, 64,
                  mn_ln1w + i * DMAIN, mn_ln1b + i * DMAIN,
                  mn_qkvw + (size_t)i * 3 * DMAIN * DMAIN,
                  mn_wo   + (size_t)i * DMAIN * DMAIN,
                  mn_ln2w + i * DMAIN, mn_ln2b + i * DMAIN,
                  mn_w1   + (size_t)i * 2 * DMAIN * DMAIN,
                  mn_w2   + (size_t)i * 2 * DMAIN * DMAIN,
                  cntp);
    gemm_kernel<0><<<dim3(1, 64), 256>>>(zp, proj_down, zdp, DENC, DMAIN, cntp);

    // ---- EMA scan + gather + STE add ----
    ema_kernel<<<BATCH, DENC>>>(zdp, pcp, zbp, cntp);
    gather_kernel<<<NROWS, DENC>>>(zbp, cump, pp, bhp, x);

    // ---- decoder ----
    for (int i = 0; i < 3; i++)
        run_block(x, DENC, 32,
                  dc_ln1w + i * DENC, dc_ln1b + i * DENC,
                  dc_qkvw + (size_t)i * 3 * DENC * DENC,
                  dc_wo   + (size_t)i * DENC * DENC,
                  dc_ln2w + i * DENC, dc_ln2b + i * DENC,
                  dc_w1   + (size_t)i * 2 * DENC * DENC,
                  dc_w2   + (size_t)i * 2 * DENC * DENC,
                  nullptr);

    // ---- final norm + tied logits head ----
    ln_kernel<<<NROWS, DENC>>>(x, norm_w, norm_b, lnp, DENC, nullptr);
    gemm_kernel<0><<<dim3(3, 64), 256>>>(lnp, embed, (float*)d_out, 260, DENC, nullptr);

    const int NLOGITS = NROWS * 260;
    if (out_size > NLOGITS)
        tail_kernel<<<1, 1>>>((float*)d_out + NLOGITS, lossp);
}

// round 14
// speedup vs baseline: 1.2293x; 1.1163x over previous
#include <cuda_runtime.h>
#include <cuda_bf16.h>
#include <math.h>

#define BATCH 8
#define SEQ   1024
#define NROWS (BATCH*SEQ)   // 8192
#define DENC  128
#define DMAIN 256
#define NHEADS 4
#define ASPLIT 4

// ---------------- scratch (device globals: no allocation in kernel_launch) ----------------
__device__ float g_x[NROWS*DENC];
__device__ float g_lnbuf[NROWS*DMAIN];
__device__ float g_qkv[NROWS*3*DMAIN];
__device__ float g_att[NROWS*DMAIN];
__device__ float g_mlp[NROWS*2*DMAIN];
__device__ float g_z[NROWS*DMAIN];
__device__ float g_comp[NROWS*DENC];
__device__ float g_qr[NROWS*DENC];
__device__ float g_kr[NROWS*DENC];
__device__ float g_zdown[NROWS*DENC];
__device__ float g_zbar[NROWS*DENC];
__device__ float g_p[NROWS];
__device__ float g_bh[NROWS];
__device__ float g_pcomp[NROWS];
__device__ int   g_cum[NROWS];
__device__ int   g_counts[BATCH];
__device__ float g_loss[1];
__device__ float  g_pacc[ASPLIT*NROWS*DMAIN];          // split-K attention partial acc
__device__ float2 g_pml[ASPLIT*NROWS*NHEADS];          // split-K attention partial (m, l)

// ---------------- f32x2 packed-FMA helpers (Blackwell FFMA2, PTX-only) ----------------
typedef unsigned long long u64;
__device__ __forceinline__ u64 dup2(float v) {
    u64 r; asm("mov.b64 %0, {%1, %1};" : "=l"(r) : "f"(v)); return r;
}
__device__ __forceinline__ void unpack2(u64 v, float& lo, float& hi) {
    asm("mov.b64 {%0, %1}, %2;" : "=f"(lo), "=f"(hi) : "l"(v));
}
__device__ __forceinline__ u64 fma2(u64 a, u64 b, u64 c) {
    u64 d; asm("fma.rn.f32x2 %0, %1, %2, %3;" : "=l"(d) : "l"(a), "l"(b), "l"(c)); return d;
}
__device__ __forceinline__ u64 mul2(u64 a, u64 b) {
    u64 d; asm("mul.rn.f32x2 %0, %1, %2;" : "=l"(d) : "l"(a), "l"(b)); return d;
}

// ---------------- helpers ----------------
__device__ __forceinline__ float gelu_exact(float v) {
    return 0.5f * v * (1.0f + erff(v * 0.70710678118654752440f));
}

// ---------------- embedding lookup ----------------
__global__ void embed_kernel(const int* __restrict__ ids, const float* __restrict__ emb,
                             float* __restrict__ x) {
    int row = blockIdx.x;
    int t = threadIdx.x;
    x[(size_t)row * DENC + t] = emb[(size_t)ids[row] * DENC + t];
}

// ---------------- LayerNorm (one block per row, blockDim = D) ----------------
__global__ void ln_kernel(const float* __restrict__ x, const float* __restrict__ w,
                          const float* __restrict__ b, float* __restrict__ y, int D,
                          const int* __restrict__ cnts) {
    int row = blockIdx.x;
    if (cnts && (row & (SEQ - 1)) >= cnts[row >> 10]) return;
    int t = threadIdx.x;
    __shared__ float sw[8];
    __shared__ float sbr;
    float v = x[(size_t)row * D + t];
    float s = v;
    #pragma unroll
    for (int o = 16; o; o >>= 1) s += __shfl_xor_sync(0xffffffffu, s, o);
    if ((t & 31) == 0) sw[t >> 5] = s;
    __syncthreads();
    if (t == 0) {
        float tot = 0.f; int nw = D >> 5;
        for (int i = 0; i < nw; i++) tot += sw[i];
        sbr = tot / (float)D;
    }
    __syncthreads();
    float mu = sbr;
    float dlt = v - mu;
    s = dlt * dlt;
    #pragma unroll
    for (int o = 16; o; o >>= 1) s += __shfl_xor_sync(0xffffffffu, s, o);
    __syncthreads();
    if ((t & 31) == 0) sw[t >> 5] = s;
    __syncthreads();
    if (t == 0) {
        float tot = 0.f; int nw = D >> 5;
        for (int i = 0; i < nw; i++) tot += sw[i];
        sbr = rsqrtf(tot / (float)D + 1e-5f);
    }
    __syncthreads();
    y[(size_t)row * D + t] = dlt * sbr * w[t] + b[t];
}

// ---------------- SGEMM (FFMA2): C[M,N] (+)= act(A[M,K] @ W[N,K]^T) ----------------
// BM=64, BN=128, BK=8, 256 threads, 4x8 per thread (2 f32x2 row-pairs x 8 cols).
// grid = (ceil(N/128), 128). FUSE: 0 = store, 1 = C += result, 2 = gelu(result)
template<int FUSE>
__global__ __launch_bounds__(256)
void gemm_kernel(const float* __restrict__ A, const float* __restrict__ W,
                 float* __restrict__ C, int N, int K, const int* __restrict__ cnts) {
    int row0 = blockIdx.y * 64, col0 = blockIdx.x * 128;
    if (cnts && (row0 & (SEQ - 1)) >= cnts[row0 >> 10]) return;
    __shared__ __align__(16) float As[8][64];
    __shared__ __align__(16) float Ws[8][128];
    int tid = threadIdx.x;
    int tr = (tid >> 4) << 2;     // 4 rows per thread
    int tc = (tid & 15) << 3;     // 8 cols per thread
    u64 acc2[2][8];
    #pragma unroll
    for (int p = 0; p < 2; p++)
        #pragma unroll
        for (int j = 0; j < 8; j++) acc2[p][j] = 0ull;
    // A tile loads: 64x8 = 512 floats, float2 per thread
    int la = tid << 1;
    int lar = la >> 3, lac = la & 7;
    const float* Ag = A + (size_t)(row0 + lar) * K + lac;
    // W tile loads: 128x8 = 1024 floats, float4 per thread
    int lw = tid << 2;
    int lwr = lw >> 3, lwc = lw & 7;
    int wrow = col0 + lwr;
    bool wok = wrow < N;
    const float* Wg = W + (size_t)(wok ? wrow : 0) * K + lwc;
    for (int k0 = 0; k0 < K; k0 += 8) {
        float2 av = *(const float2*)(Ag + k0);
        float4 wv = wok ? *(const float4*)(Wg + k0) : make_float4(0.f, 0.f, 0.f, 0.f);
        As[lac + 0][lar] = av.x; As[lac + 1][lar] = av.y;
        Ws[lwc + 0][lwr] = wv.x; Ws[lwc + 1][lwr] = wv.y;
        Ws[lwc + 2][lwr] = wv.z; Ws[lwc + 3][lwr] = wv.w;
        __syncthreads();
        #pragma unroll
        for (int k = 0; k < 8; k++) {
            ulonglong2 aA = *(const ulonglong2*)(&As[k][tr]);   // 4 rows = 2 pairs
            u64 a2[2] = { aA.x, aA.y };
            float4 w0 = *(const float4*)(&Ws[k][tc]);
            float4 w1 = *(const float4*)(&Ws[k][tc + 4]);
            u64 wd[8];
            wd[0] = dup2(w0.x); wd[1] = dup2(w0.y); wd[2] = dup2(w0.z); wd[3] = dup2(w0.w);
            wd[4] = dup2(w1.x); wd[5] = dup2(w1.y); wd[6] = dup2(w1.z); wd[7] = dup2(w1.w);
            #pragma unroll
            for (int p = 0; p < 2; p++)
                #pragma unroll
                for (int j = 0; j < 8; j++)
                    acc2[p][j] = fma2(a2[p], wd[j], acc2[p][j]);
        }
        __syncthreads();
    }
    #pragma unroll
    for (int p = 0; p < 2; p++) {
        float* Cr0 = C + (size_t)(row0 + tr + 2 * p) * N;
        float* Cr1 = Cr0 + N;
        #pragma unroll
        for (int j = 0; j < 8; j++) {
            int cc = col0 + tc + j;
            if (cc < N) {
                float lo, hi;
                unpack2(acc2[p][j], lo, hi);
                if (FUSE == 1) { lo += Cr0[cc]; hi += Cr1[cc]; }
                if (FUSE == 2) { lo = gelu_exact(lo); hi = gelu_exact(hi); }
                Cr0[cc] = lo; Cr1[cc] = hi;
            }
        }
    }
}

// ---------------- split-K flash attention: partial pass ----------------
// grid: (BATCH*NHEADS, SEQ/128, ASPLIT), block 128 threads, 1 query row/thread.
// Split s handles a contiguous range of key tiles; writes unnormalized partial
// (m, l, acc) for exact online-softmax merge.
template<int DH, int NT>
__global__ __launch_bounds__(128)
void attn_part_kernel(const float* __restrict__ qkv, float* __restrict__ pacc,
                      float2* __restrict__ pml, int D,
                      const int* __restrict__ counts, float scale) {
    const int D3 = 3 * D;
    const int DH2 = DH / 2, DH4 = DH / 4;
    int b = blockIdx.x >> 2, h = blockIdx.x & 3;
    int s = blockIdx.z;
    int tid = threadIdx.x;
    int q = blockIdx.y * 128 + tid;
    __shared__ __align__(16) float Ksh[NT][DH];
    __shared__ __align__(16) float Vsh[NT][DH];
    int cnt = counts ? counts[b] : SEQ;
    if (counts && (int)(blockIdx.y * 128) >= cnt) return;   // merge emits zeros
    int row = b * SEQ + q;
    int qlim = (q < cnt) ? q : -1;
    int limit = min((int)(blockIdx.y * 128 + 127), cnt - 1);
    int T = limit / NT + 1;
    int t0 = (s * T) / ASPLIT, t1 = ((s + 1) * T) / ASPLIT;
    const u64* qrow2 = (const u64*)(qkv + ((size_t)(b * SEQ) + q) * D3 + h * DH);
    u64 q2[DH2], acc2[DH2];
    #pragma unroll
    for (int d = 0; d < DH2; d++) { q2[d] = qrow2[d]; acc2[d] = 0ull; }
    float mval = -1e30f, lsum = 0.f;
    for (int kt = t0; kt < t1; kt++) {
        int k0 = kt * NT;
        for (int idx = tid; idx < NT * DH; idx += 128) {
            int j = idx / DH, d = idx - j * DH;
            size_t base = ((size_t)(b * SEQ) + (k0 + j)) * D3 + h * DH + d;
            Ksh[j][d] = qkv[base + D];
            Vsh[j][d] = qkv[base + 2 * D];
        }
        __syncthreads();
        int jmax = qlim - k0;
        if (jmax > NT - 1) jmax = NT - 1;
        if (jmax >= 0) {
            // phase 1: all NT scores, 4 independent f32x2 chains, LDS.128 K reads
            float sc[NT];
            #pragma unroll
            for (int j0 = 0; j0 < NT; j0 += 4) {
                u64 s0 = 0ull, s1 = 0ull, s2v = 0ull, s3 = 0ull;
                const ulonglong2* K0 = (const ulonglong2*)Ksh[j0 + 0];
                const ulonglong2* K1 = (const ulonglong2*)Ksh[j0 + 1];
                const ulonglong2* K2 = (const ulonglong2*)Ksh[j0 + 2];
                const ulonglong2* K3 = (const ulonglong2*)Ksh[j0 + 3];
                #pragma unroll
                for (int d = 0; d < DH4; d++) {
                    u64 qa = q2[2 * d], qb = q2[2 * d + 1];
                    ulonglong2 k0v = K0[d], k1v = K1[d], k2v = K2[d], k3v = K3[d];
                    s0 = fma2(qa, k0v.x, s0);  s0 = fma2(qb, k0v.y, s0);
                    s1 = fma2(qa, k1v.x, s1);  s1 = fma2(qb, k1v.y, s1);
                    s2v = fma2(qa, k2v.x, s2v); s2v = fma2(qb, k2v.y, s2v);
                    s3 = fma2(qa, k3v.x, s3);  s3 = fma2(qb, k3v.y, s3);
                }
                float lo, hi;
                unpack2(s0, lo, hi);  sc[j0 + 0] = (lo + hi) * scale;
                unpack2(s1, lo, hi);  sc[j0 + 1] = (lo + hi) * scale;
                unpack2(s2v, lo, hi); sc[j0 + 2] = (lo + hi) * scale;
                unpack2(s3, lo, hi);  sc[j0 + 3] = (lo + hi) * scale;
            }
            // phase 2: one rescale per tile
            float tmax = -1e30f;
            #pragma unroll
            for (int j = 0; j < NT; j++)
                if (j <= jmax) tmax = fmaxf(tmax, sc[j]);
            float newmax = fmaxf(mval, tmax);
            float f = __expf(mval - newmax);
            lsum *= f;
            u64 f2 = dup2(f);
            #pragma unroll
            for (int d = 0; d < DH2; d++) acc2[d] = mul2(acc2[d], f2);
            #pragma unroll
            for (int j = 0; j < NT; j++) {
                float w = (j <= jmax) ? __expf(sc[j] - newmax) : 0.f;
                lsum += w;
                u64 w2 = dup2(w);
                const ulonglong2* Vj = (const ulonglong2*)Vsh[j];
                #pragma unroll
                for (int d = 0; d < DH4; d++) {
                    ulonglong2 vv = Vj[d];
                    acc2[2 * d]     = fma2(w2, vv.x, acc2[2 * d]);
                    acc2[2 * d + 1] = fma2(w2, vv.y, acc2[2 * d + 1]);
                }
            }
            mval = newmax;
        }
        __syncthreads();
    }
    // write unnormalized partials (zeros / m=-1e30 for empty splits or invalid q)
    pml[((size_t)s * NROWS + row) * NHEADS + h] = make_float2(mval, lsum);
    u64* pa = (u64*)(pacc + ((size_t)s * NROWS + row) * (size_t)D + h * DH);
    #pragma unroll
    for (int d = 0; d < DH2; d++) pa[d] = acc2[d];
}

// ---------------- split-K attention: merge pass ----------------
// grid NROWS, block D. Exact online-softmax combination of ASPLIT partials.
__global__ void attn_merge_kernel(const float* __restrict__ pacc,
                                  const float2* __restrict__ pml,
                                  float* __restrict__ out, int D, int dhshift,
                                  const int* __restrict__ counts) {
    int row = blockIdx.x, d = threadIdx.x;
    float* o = out + (size_t)row * D + d;
    int cnt = counts ? counts[row >> 10] : SEQ;
    if ((row & (SEQ - 1)) >= cnt) { *o = 0.f; return; }
    int h = d >> dhshift;
    float m[ASPLIT], l[ASPLIT];
    float M = -1e30f;
    #pragma unroll
    for (int s = 0; s < ASPLIT; s++) {
        float2 v = pml[((size_t)s * NROWS + row) * NHEADS + h];
        m[s] = v.x; l[s] = v.y;
        M = fmaxf(M, v.x);
    }
    float L = 0.f, A = 0.f;
    #pragma unroll
    for (int s = 0; s < ASPLIT; s++) {
        float e = __expf(m[s] - M);
        L = fmaf(l[s], e, L);
        A = fmaf(pacc[((size_t)s * NROWS + row) * D + d], e, A);
    }
    *o = A / L;
}

// ---------------- routing: cos similarity of normalized q[l], k[l-1] ----------------
__global__ void route_kernel(const float* __restrict__ q, const float* __restrict__ k,
                             float* __restrict__ p, float* __restrict__ bh) {
    int wid = (blockIdx.x * blockDim.x + threadIdx.x) >> 5;
    int lane = threadIdx.x & 31;
    if (wid >= NROWS) return;
    int l = wid & (SEQ - 1);
    const float* qr = q + (size_t)wid * DENC;
    const float* kr = (l > 0) ? (k + (size_t)(wid - 1) * DENC) : nullptr;
    float nq = 0.f, nk = 0.f, dt = 0.f;
    for (int i = lane; i < DENC; i += 32) {
        float qv = qr[i];
        float kv = kr ? kr[i] : 0.f;
        nq += qv * qv; nk += kv * kv; dt += qv * kv;
    }
    #pragma unroll
    for (int o = 16; o; o >>= 1) {
        nq += __shfl_xor_sync(0xffffffffu, nq, o);
        nk += __shfl_xor_sync(0xffffffffu, nk, o);
        dt += __shfl_xor_sync(0xffffffffu, dt, o);
    }
    if (lane == 0) {
        float denom = fmaxf(sqrtf(nq), 1e-12f) * fmaxf(sqrtf(nk), 1e-12f);
        float cosv = dt / denom;
        float pv = fminf(fmaxf(0.5f * (1.f - cosv), 0.f), 1.f);
        if (l == 0) pv = 1.f;
        p[wid] = pv;
        bh[wid] = (pv >= 0.5f) ? 1.f : 0.f;
    }
}

// ---------------- per-batch inclusive scan of b_hard ----------------
__global__ void scan_kernel(const float* __restrict__ bh, int* __restrict__ cum,
                            int* __restrict__ counts) {
    int b = blockIdx.x, t = threadIdx.x;   // 1024 threads
    __shared__ int s[SEQ];
    s[t] = (int)bh[b * SEQ + t];
    __syncthreads();
    for (int o = 1; o < SEQ; o <<= 1) {
        int add = (t >= o) ? s[t - o] : 0;
        __syncthreads();
        s[t] += add;
        __syncthreads();
    }
    cum[b * SEQ + t] = s[t];
    if (t == SEQ - 1) counts[b] = s[t];
}

// ---------------- ratio loss (single block, deterministic) ----------------
__global__ void stats_kernel(const float* __restrict__ bh, const float* __restrict__ p,
                             float* __restrict__ loss) {
    int t = threadIdx.x;   // 1024
    __shared__ float rb[1024], rp[1024];
    float sb = 0.f, sp = 0.f;
    for (int i = t; i < NROWS; i += 1024) { sb += bh[i]; sp += p[i]; }
    rb[t] = sb; rp[t] = sp;
    __syncthreads();
    for (int o = 512; o; o >>= 1) {
        if (t < o) { rb[t] += rb[t + o]; rp[t] += rp[t + o]; }
        __syncthreads();
    }
    if (t == 0) {
        float F = rb[0] / (float)NROWS, G = rp[0] / (float)NROWS;
        loss[0] = 1.2f * (5.f * F * G + (1.f - F) * (1.f - G));
    }
}

__global__ void zero_kernel(float* __restrict__ ptr, int n) {
    int i = blockIdx.x * blockDim.x + threadIdx.x;
    if (i < n) ptr[i] = 0.f;
}

// ---------------- scatter selected rows to front (downsample) ----------------
__global__ void scatter_kernel(const float* __restrict__ x, const float* __restrict__ p,
                               const float* __restrict__ bh, const int* __restrict__ cum,
                               float* __restrict__ comp, float* __restrict__ pcomp) {
    int row = blockIdx.x;
    if (bh[row] < 0.5f) return;
    int b = row >> 10;
    int dst = cum[row] - 1;
    int t = threadIdx.x;
    comp[((size_t)(b << 10) + dst) * DENC + t] = x[(size_t)row * DENC + t];
    if (t == 0) pcomp[(b << 10) + dst] = p[row];
}

// ---------------- EMA linear recurrence scan ----------------
__global__ void ema_kernel(const float* __restrict__ z, const float* __restrict__ pc,
                           float* __restrict__ zbar, const int* __restrict__ counts) {
    int b = blockIdx.x, d = threadIdx.x;   // 128 threads
    const float* zb = z + (size_t)b * SEQ * DENC;
    float* ob = zbar + (size_t)b * SEQ * DENC;
    const float* pb = pc + b * SEQ;
    int Tn = counts[b];
    float prev = 0.f;
    for (int t = 0; t < Tn; t++) {
        float pv = pb[t];
        float pcl = fminf(fmaxf(pv, 1e-4f), 0.9999f);
        float zv = zb[(size_t)t * DENC + d];
        float cur = (t == 0) ? zv : ((1.f - pcl) * prev + pcl * zv);
        ob[(size_t)t * DENC + d] = cur;
        prev = cur;
    }
}

// ---------------- gather + STE residual add ----------------
__global__ void gather_kernel(const float* __restrict__ zbar, const int* __restrict__ cum,
                              const float* __restrict__ p, const float* __restrict__ bh,
                              float* __restrict__ x) {
    int row = blockIdx.x, t = threadIdx.x;
    int b = row >> 10;
    int ci = cum[row] - 1; if (ci < 0) ci = 0;
    float pv = p[row], bv = bh[row];
    float c = bv * pv + (1.f - bv) * (1.f - pv);
    float cste = c + (1.f - c);   // forward value of STE (match ref rounding)
    x[(size_t)row * DENC + t] += cste * zbar[((size_t)(b << 10) + ci) * DENC + t];
}

__global__ void tail_kernel(float* __restrict__ dst, const float* __restrict__ loss) {
    dst[0] = loss[0];
}

// ---------------- host orchestration ----------------
static void* symaddr(const void* sym) {
    void* p = nullptr;
    cudaGetSymbolAddress(&p, sym);
    return p;
}

static const int PERM_SIG[32] = {
    0,1,2,3, 4,5,6,7,8,9,10,11, 12, 13,14,15,16,17,18,19,20, 21, 22,23,24,25,26,27,28,29, 30,31
};
static const int PERM_DICT[32] = {
    0,1,2,3, 8,9,10,11,12,13,14,15, 4, 16,17,18,19,20,21,22,23, 5, 24,25,26,27,28,29,30,31, 6,7
};
static const int PERM_ALPHA[32] = {
    0,9,31,30, 11,10,14,17,13,12,15,16, 29, 19,18,22,25,21,20,23,24, 28, 2,1,5,8,4,3,6,7, 27,26
};

extern "C" void kernel_launch(void* const* d_in, const int* in_sizes, int n_in,
                              void* d_out, int out_size) {
    (void)n_in;
    const int* perm;
    if (in_sizes[1] == 3 * DENC)            perm = PERM_ALPHA;
    else if (in_sizes[4] == DMAIN * DENC)   perm = PERM_DICT;
    else                                    perm = PERM_SIG;

    const float* inp[32];
    for (int i = 0; i < 32; i++) inp[i] = (const float*)d_in[perm[i]];

    const int*   ids       = (const int*)d_in[perm[0]];
    const float* embed     = inp[1];
    const float* wq        = inp[2];
    const float* wk        = inp[3];
    const float* enc_ln1w  = inp[4];
    const float* enc_ln1b  = inp[5];
    const float* enc_qkvw  = inp[6];
    const float* enc_wo    = inp[7];
    const float* enc_ln2w  = inp[8];
    const float* enc_ln2b  = inp[9];
    const float* enc_w1    = inp[10];
    const float* enc_w2    = inp[11];
    const float* proj_up   = inp[12];
    const float* mn_ln1w   = inp[13];
    const float* mn_ln1b   = inp[14];
    const float* mn_qkvw   = inp[15];
    const float* mn_wo     = inp[16];
    const float* mn_ln2w   = inp[17];
    const float* mn_ln2b   = inp[18];
    const float* mn_w1     = inp[19];
    const float* mn_w2     = inp[20];
    const float* proj_down = inp[21];
    const float* dc_ln1w   = inp[22];
    const float* dc_ln1b   = inp[23];
    const float* dc_qkvw   = inp[24];
    const float* dc_wo     = inp[25];
    const float* dc_ln2w   = inp[26];
    const float* dc_ln2b   = inp[27];
    const float* dc_w1     = inp[28];
    const float* dc_w2     = inp[29];
    const float* norm_w    = inp[30];
    const float* norm_b    = inp[31];

    float*  x     = (float*)symaddr(g_x);
    float*  lnp   = (float*)symaddr(g_lnbuf);
    float*  qkvp  = (float*)symaddr(g_qkv);
    float*  attp  = (float*)symaddr(g_att);
    float*  mlpp  = (float*)symaddr(g_mlp);
    float*  zp    = (float*)symaddr(g_z);
    float*  compp = (float*)symaddr(g_comp);
    float*  qrp   = (float*)symaddr(g_qr);
    float*  krp   = (float*)symaddr(g_kr);
    float*  zdp   = (float*)symaddr(g_zdown);
    float*  zbp   = (float*)symaddr(g_zbar);
    float*  pp    = (float*)symaddr(g_p);
    float*  bhp   = (float*)symaddr(g_bh);
    float*  pcp   = (float*)symaddr(g_pcomp);
    int*    cump  = (int*)symaddr(g_cum);
    int*    cntp  = (int*)symaddr(g_counts);
    float*  lossp = (float*)symaddr(g_loss);
    float*  paccp = (float*)symaddr(g_pacc);
    float2* pmlp  = (float2*)symaddr(g_pml);

    auto gemm_grid = [](int N) { return dim3((N + 127) / 128, 128); };

    auto run_block = [&](float* xb, int D, int dh,
                         const float* l1w, const float* l1b,
                         const float* qw, const float* wo,
                         const float* l2w, const float* l2b,
                         const float* w1, const float* w2,
                         const int* cnts) {
        int D3 = 3 * D;
        ln_kernel<<<NROWS, D>>>(xb, l1w, l1b, lnp, D, cnts);
        gemm_kernel<0><<<gemm_grid(D3), 256>>>(lnp, qw, qkvp, D3, D, cnts);
        if (dh == 32) {
            attn_part_kernel<32, 32><<<dim3(BATCH * NHEADS, SEQ / 128, ASPLIT), 128>>>(
                qkvp, paccp, pmlp, D, cnts, 0.17677669529663687f);
            attn_merge_kernel<<<NROWS, D>>>(paccp, pmlp, attp, D, 5, cnts);
        } else {
            attn_part_kernel<64, 16><<<dim3(BATCH * NHEADS, SEQ / 128, ASPLIT), 128>>>(
                qkvp, paccp, pmlp, D, cnts, 0.125f);
            attn_merge_kernel<<<NROWS, D>>>(paccp, pmlp, attp, D, 6, cnts);
        }
        gemm_kernel<1><<<gemm_grid(D), 256>>>(attp, wo, xb, D, D, cnts);
        ln_kernel<<<NROWS, D>>>(xb, l2w, l2b, lnp, D, cnts);
        gemm_kernel<2><<<gemm_grid(2 * D), 256>>>(lnp, w1, mlpp, 2 * D, D, cnts);
        gemm_kernel<1><<<gemm_grid(D), 256>>>(mlpp, w2, xb, D, 2 * D, cnts);
    };

    // ---- encoder ----
    embed_kernel<<<NROWS, DENC>>>(ids, embed, x);
    for (int i = 0; i < 3; i++)
        run_block(x, DENC, 32,
                  enc_ln1w + i * DENC, enc_ln1b + i * DENC,
                  enc_qkvw + (size_t)i * 3 * DENC * DENC,
                  enc_wo   + (size_t)i * DENC * DENC,
                  enc_ln2w + i * DENC, enc_ln2b + i * DENC,
                  enc_w1   + (size_t)i * 2 * DENC * DENC,
                  enc_w2   + (size_t)i * 2 * DENC * DENC,
                  nullptr);

    // ---- routing / dynamic chunking ----
    gemm_kernel<0><<<gemm_grid(DENC), 256>>>(x, wq, qrp, DENC, DENC, nullptr);
    gemm_kernel<0><<<gemm_grid(DENC), 256>>>(x, wk, krp, DENC, DENC, nullptr);
    route_kernel<<<NROWS / 8, 256>>>(qrp, krp, pp, bhp);
    scan_kernel<<<BATCH, SEQ>>>(bhp, cump, cntp);
    stats_kernel<<<1, 1024>>>(bhp, pp, lossp);
    zero_kernel<<<(NROWS * DENC + 255) / 256, 256>>>(compp, NROWS * DENC);
    zero_kernel<<<(NROWS + 255) / 256, 256>>>(pcp, NROWS);
    scatter_kernel<<<NROWS, DENC>>>(x, pp, bhp, cump, compp, pcp);

    // ---- main stack (padded + masked; padded rows dynamically elided) ----
    gemm_kernel<0><<<gemm_grid(DMAIN), 256>>>(compp, proj_up, zp, DMAIN, DENC, cntp);
    for (int i = 0; i < 6; i++)
        run_block(zp, DMAIN, 64,
                  mn_ln1w + i * DMAIN, mn_ln1b + i * DMAIN,
                  mn_qkvw + (size_t)i * 3 * DMAIN * DMAIN,
                  mn_wo   + (size_t)i * DMAIN * DMAIN,
                  mn_ln2w + i * DMAIN, mn_ln2b + i * DMAIN,
                  mn_w1   + (size_t)i * 2 * DMAIN * DMAIN,
                  mn_w2   + (size_t)i * 2 * DMAIN * DMAIN,
                  cntp);
    gemm_kernel<0><<<gemm_grid(DENC), 256>>>(zp, proj_down, zdp, DENC, DMAIN, cntp);

    // ---- EMA scan + gather + STE add ----
    ema_kernel<<<BATCH, DENC>>>(zdp, pcp, zbp, cntp);
    gather_kernel<<<NROWS, DENC>>>(zbp, cump, pp, bhp, x);

    // ---- decoder ----
    for (int i = 0; i < 3; i++)
        run_block(x, DENC, 32,
                  dc_ln1w + i * DENC, dc_ln1b + i * DENC,
                  dc_qkvw + (size_t)i * 3 * DENC * DENC,
                  dc_wo   + (size_t)i * DENC * DENC,
                  dc_ln2w + i * DENC, dc_ln2b + i * DENC,
                  dc_w1   + (size_t)i * 2 * DENC * DENC,
                  dc_w2   + (size_t)i * 2 * DENC * DENC,
                  nullptr);

    // ---- final norm + tied logits head ----
    ln_kernel<<<NROWS, DENC>>>(x, norm_w, norm_b, lnp, DENC, nullptr);
    gemm_kernel<0><<<gemm_grid(260), 256>>>(lnp, embed, (float*)d_out, 260, DENC, nullptr);

    const int NLOGITS = NROWS * 260;
    if (out_size > NLOGITS)
        tail_kernel<<<1, 1>>>((float*)d_out + NLOGITS, lossp);
}

// round 15
// speedup vs baseline: 1.2407x; 1.0093x over previous
#include <cuda_runtime.h>
#include <cuda_bf16.h>
#include <math.h>

#define BATCH 8
#define SEQ   1024
#define NROWS (BATCH*SEQ)   // 8192
#define DENC  128
#define DMAIN 256
#define NHEADS 4
#define ASPLIT 4

// ---------------- scratch (device globals: no allocation in kernel_launch) ----------------
__device__ float g_x[NROWS*DENC];
__device__ float g_lnbuf[NROWS*DMAIN];
__device__ float g_qkv[NROWS*3*DMAIN];
__device__ float g_mlp[NROWS*2*DMAIN];
__device__ float g_z[NROWS*DMAIN];
__device__ float g_comp[NROWS*DENC];
__device__ float g_qr[NROWS*DENC];
__device__ float g_kr[NROWS*DENC];
__device__ float g_zdown[NROWS*DENC];
__device__ float g_zbar[NROWS*DENC];
__device__ float g_p[NROWS];
__device__ float g_bh[NROWS];
__device__ float g_pcomp[NROWS];
__device__ int   g_cum[NROWS];
__device__ int   g_counts[BATCH];
__device__ float g_loss[1];
__device__ float  g_pacc[ASPLIT*NROWS*DMAIN];          // split-K attention partial acc
__device__ float2 g_pml[ASPLIT*NROWS*NHEADS];          // split-K attention partial (m, l)

// ---------------- f32x2 packed-FMA helpers (Blackwell FFMA2, PTX-only) ----------------
typedef unsigned long long u64;
__device__ __forceinline__ u64 dup2(float v) {
    u64 r; asm("mov.b64 %0, {%1, %1};" : "=l"(r) : "f"(v)); return r;
}
__device__ __forceinline__ void unpack2(u64 v, float& lo, float& hi) {
    asm("mov.b64 {%0, %1}, %2;" : "=f"(lo), "=f"(hi) : "l"(v));
}
__device__ __forceinline__ u64 fma2(u64 a, u64 b, u64 c) {
    u64 d; asm("fma.rn.f32x2 %0, %1, %2, %3;" : "=l"(d) : "l"(a), "l"(b), "l"(c)); return d;
}
__device__ __forceinline__ u64 mul2(u64 a, u64 b) {
    u64 d; asm("mul.rn.f32x2 %0, %1, %2;" : "=l"(d) : "l"(a), "l"(b)); return d;
}

__device__ __forceinline__ float gelu_exact(float v) {
    return 0.5f * v * (1.0f + erff(v * 0.70710678118654752440f));
}

// ---------------- embedding lookup ----------------
__global__ void embed_kernel(const int* __restrict__ ids, const float* __restrict__ emb,
                             float* __restrict__ x) {
    int row = blockIdx.x;
    int t = threadIdx.x;
    x[(size_t)row * DENC + t] = emb[(size_t)ids[row] * DENC + t];
}

// ---------------- LayerNorm: 2 rows per block, blockDim = 2*D ----------------
__global__ void ln_kernel(const float* __restrict__ x, const float* __restrict__ w,
                          const float* __restrict__ b, float* __restrict__ y, int D,
                          const int* __restrict__ cnts) {
    int t = threadIdx.x;
    int sub = (t >= D) ? 1 : 0;
    int tr = t - sub * D;
    int row = (blockIdx.x << 1) + sub;
    bool live = !(cnts && (row & (SEQ - 1)) >= cnts[row >> 10]);
    __shared__ float sw[2][8];
    __shared__ float sred[2];
    float v = live ? x[(size_t)row * D + tr] : 0.f;
    float s = v;
    #pragma unroll
    for (int o = 16; o; o >>= 1) s += __shfl_xor_sync(0xffffffffu, s, o);
    int wps = D >> 5;
    int lw = (t >> 5) - sub * wps;
    if ((t & 31) == 0) sw[sub][lw] = s;
    __syncthreads();
    if (tr == 0) {
        float tot = 0.f;
        for (int i = 0; i < wps; i++) tot += sw[sub][i];
        sred[sub] = tot / (float)D;
    }
    __syncthreads();
    float mu = sred[sub];
    float dlt = v - mu;
    s = dlt * dlt;
    #pragma unroll
    for (int o = 16; o; o >>= 1) s += __shfl_xor_sync(0xffffffffu, s, o);
    __syncthreads();
    if ((t & 31) == 0) sw[sub][lw] = s;
    __syncthreads();
    if (tr == 0) {
        float tot = 0.f;
        for (int i = 0; i < wps; i++) tot += sw[sub][i];
        sred[sub] = rsqrtf(tot / (float)D + 1e-5f);
    }
    __syncthreads();
    if (live) y[(size_t)row * D + tr] = dlt * sred[sub] * w[tr] + b[tr];
}

// ---------------- SGEMM (FFMA2): C[M,N] (+)= act(A[M,K] @ W[N,K]^T) ----------------
// BM=64, BN=128, BK=8, 256 threads, 4x8 per thread (2 f32x2 row-pairs x 8 cols).
// FUSE: 0 = store, 1 = C += result, 2 = gelu(result)
// MERGE: A computed on the fly as exact split-K softmax merge of (pacc, pml).
template<int FUSE, int MERGE>
__global__ __launch_bounds__(256)
void gemm_kernel(const float* __restrict__ A, const float* __restrict__ W,
                 float* __restrict__ C, int N, int K, const int* __restrict__ cnts,
                 const float2* __restrict__ pml, int dhshift) {
    int row0 = blockIdx.y * 64, col0 = blockIdx.x * 128;
    if (cnts && (row0 & (SEQ - 1)) >= cnts[row0 >> 10]) return;
    __shared__ __align__(16) float As[8][64];
    __shared__ __align__(16) float Ws[8][128];
    int tid = threadIdx.x;
    int tr = (tid >> 4) << 2;     // 4 rows per thread
    int tc = (tid & 15) << 3;     // 8 cols per thread
    u64 acc2[2][8];
    #pragma unroll
    for (int p = 0; p < 2; p++)
        #pragma unroll
        for (int j = 0; j < 8; j++) acc2[p][j] = 0ull;
    // A tile loads: 64x8 floats, float2 per thread
    int la = tid << 1;
    int lar = la >> 3, lac = la & 7;
    int grow = row0 + lar;
    const float* Ag = A + (size_t)grow * K + lac;
    // W tile loads: 128x8 floats, float4 per thread
    int lw = tid << 2;
    int lwr = lw >> 3, lwc = lw & 7;
    int wrow = col0 + lwr;
    bool wok = wrow < N;
    const float* Wg = W + (size_t)(wok ? wrow : 0) * K + lwc;
    for (int k0 = 0; k0 < K; k0 += 8) {
        float2 av;
        if (!MERGE) {
            av = *(const float2*)(Ag + k0);
        } else {
            int col = k0 + lac;
            int h = col >> dhshift;
            float mm[ASPLIT], ll[ASPLIT];
            float M = -1e30f;
            #pragma unroll
            for (int s = 0; s < ASPLIT; s++) {
                float2 v = pml[((size_t)s * NROWS + grow) * NHEADS + h];
                mm[s] = v.x; ll[s] = v.y;
                M = fmaxf(M, v.x);
            }
            float L = 0.f, ax = 0.f, ay = 0.f;
            #pragma unroll
            for (int s = 0; s < ASPLIT; s++) {
                float e = __expf(mm[s] - M);
                L = fmaf(ll[s], e, L);
                float2 pv = *(const float2*)(A + ((size_t)s * NROWS + grow) * K + col);
                ax = fmaf(pv.x, e, ax);
                ay = fmaf(pv.y, e, ay);
            }
            float inv = 1.f / fmaxf(L, 1e-30f);   // guard only fires for dead rows
            av = make_float2(ax * inv, ay * inv);
        }
        float4 wv = wok ? *(const float4*)(Wg + k0) : make_float4(0.f, 0.f, 0.f, 0.f);
        As[lac + 0][lar] = av.x; As[lac + 1][lar] = av.y;
        Ws[lwc + 0][lwr] = wv.x; Ws[lwc + 1][lwr] = wv.y;
        Ws[lwc + 2][lwr] = wv.z; Ws[lwc + 3][lwr] = wv.w;
        __syncthreads();
        #pragma unroll
        for (int k = 0; k < 8; k++) {
            ulonglong2 aA = *(const ulonglong2*)(&As[k][tr]);   // 4 rows = 2 pairs
            u64 a2[2] = { aA.x, aA.y };
            float4 w0 = *(const float4*)(&Ws[k][tc]);
            float4 w1 = *(const float4*)(&Ws[k][tc + 4]);
            u64 wd[8];
            wd[0] = dup2(w0.x); wd[1] = dup2(w0.y); wd[2] = dup2(w0.z); wd[3] = dup2(w0.w);
            wd[4] = dup2(w1.x); wd[5] = dup2(w1.y); wd[6] = dup2(w1.z); wd[7] = dup2(w1.w);
            #pragma unroll
            for (int p = 0; p < 2; p++)
                #pragma unroll
                for (int j = 0; j < 8; j++)
                    acc2[p][j] = fma2(a2[p], wd[j], acc2[p][j]);
        }
        __syncthreads();
    }
    #pragma unroll
    for (int p = 0; p < 2; p++) {
        float* Cr0 = C + (size_t)(row0 + tr + 2 * p) * N;
        float* Cr1 = Cr0 + N;
        #pragma unroll
        for (int j = 0; j < 8; j++) {
            int cc = col0 + tc + j;
            if (cc < N) {
                float lo, hi;
                unpack2(acc2[p][j], lo, hi);
                if (FUSE == 1) { lo += Cr0[cc]; hi += Cr1[cc]; }
                if (FUSE == 2) { lo = gelu_exact(lo); hi = gelu_exact(hi); }
                Cr0[cc] = lo; Cr1[cc] = hi;
            }
        }
    }
}

// ---------------- split-K flash attention: partial pass ----------------
// grid: (BATCH*NHEADS, SEQ/128, ASPLIT), block 128 threads, 1 query row/thread.
// Double-buffered smem tiles with register staging (LDG in flight during compute),
// ONE sync per tile. Scores in groups of 8 with exact per-group online rescale.
template<int DH, int NT, int MINB>
__global__ __launch_bounds__(128, MINB)
void attn_part_kernel(const float* __restrict__ qkv, float* __restrict__ pacc,
                      float2* __restrict__ pml, int D,
                      const int* __restrict__ counts, float scale) {
    const int D3 = 3 * D;
    const int DH2 = DH / 2, DH4 = DH / 4;
    const int DQ = DH / 4;                 // float4 per K/V row
    int b = blockIdx.x >> 2, h = blockIdx.x & 3;
    int s = blockIdx.z;
    int tid = threadIdx.x;
    int q = blockIdx.y * 128 + tid;
    __shared__ __align__(16) float Ksh[2][NT][DH];
    __shared__ __align__(16) float Vsh[2][NT][DH];
    int cnt = counts ? counts[b] : SEQ;
    if (counts && (int)(blockIdx.y * 128) >= cnt) return;   // merge guard handles dead rows
    int row = b * SEQ + q;
    int qlim = (q < cnt) ? q : -1;
    int limit = min((int)(blockIdx.y * 128 + 127), cnt - 1);
    int T = limit / NT + 1;
    int t0 = (s * T) / ASPLIT, t1 = ((s + 1) * T) / ASPLIT;
    const u64* qrow2 = (const u64*)(qkv + (size_t)row * D3 + h * DH);
    u64 q2[DH2], acc2[DH2];
    #pragma unroll
    for (int d = 0; d < DH2; d++) { q2[d] = qrow2[d]; acc2[d] = 0ull; }
    float mval = -1e30f, lsum = 0.f;

    // loader mapping: 2 float4 of K and 2 of V per thread per tile
    int i0 = tid, i1 = tid + 128;
    int j0l = i0 / DQ, d0 = (i0 - j0l * DQ) << 2;
    int j1l = i1 / DQ, d1 = (i1 - j1l * DQ) << 2;
    size_t off0 = (size_t)(b * SEQ + j0l) * D3 + h * DH + d0;
    size_t off1 = (size_t)(b * SEQ + j1l) * D3 + h * DH + d1;
    float4 k0r, k1r, v0r, v1r;
    if (t0 < t1) {
        size_t a0 = off0 + (size_t)(t0 * NT) * D3;
        size_t a1 = off1 + (size_t)(t0 * NT) * D3;
        k0r = *(const float4*)(qkv + a0 + D);     v0r = *(const float4*)(qkv + a0 + 2 * D);
        k1r = *(const float4*)(qkv + a1 + D);     v1r = *(const float4*)(qkv + a1 + 2 * D);
    }
    int buf = 0;
    for (int kt = t0; kt < t1; kt++) {
        *(float4*)(&Ksh[buf][j0l][d0]) = k0r;  *(float4*)(&Vsh[buf][j0l][d0]) = v0r;
        *(float4*)(&Ksh[buf][j1l][d1]) = k1r;  *(float4*)(&Vsh[buf][j1l][d1]) = v1r;
        __syncthreads();
        if (kt + 1 < t1) {   // prefetch next tile into regs; latency hides under compute
            size_t a0 = off0 + (size_t)((kt + 1) * NT) * D3;
            size_t a1 = off1 + (size_t)((kt + 1) * NT) * D3;
            k0r = *(const float4*)(qkv + a0 + D);  v0r = *(const float4*)(qkv + a0 + 2 * D);
            k1r = *(const float4*)(qkv + a1 + D);  v1r = *(const float4*)(qkv + a1 + 2 * D);
        }
        int jmax = qlim - kt * NT;
        if (jmax > NT - 1) jmax = NT - 1;
        for (int g = 0; g <= jmax; g += 8) {
            float sc[8];
            #pragma unroll
            for (int half = 0; half < 2; half++) {
                const ulonglong2* K0 = (const ulonglong2*)Ksh[buf][g + half * 4 + 0];
                const ulonglong2* K1 = (const ulonglong2*)Ksh[buf][g + half * 4 + 1];
                const ulonglong2* K2 = (const ulonglong2*)Ksh[buf][g + half * 4 + 2];
                const ulonglong2* K3 = (const ulonglong2*)Ksh[buf][g + half * 4 + 3];
                u64 s0 = 0ull, s1 = 0ull, s2v = 0ull, s3 = 0ull;
                #pragma unroll
                for (int d = 0; d < DH4; d++) {
                    u64 qa = q2[2 * d], qb = q2[2 * d + 1];
                    ulonglong2 ka = K0[d], kb = K1[d], kc = K2[d], kd = K3[d];
                    s0 = fma2(qa, ka.x, s0);   s0 = fma2(qb, ka.y, s0);
                    s1 = fma2(qa, kb.x, s1);   s1 = fma2(qb, kb.y, s1);
                    s2v = fma2(qa, kc.x, s2v); s2v = fma2(qb, kc.y, s2v);
                    s3 = fma2(qa, kd.x, s3);   s3 = fma2(qb, kd.y, s3);
                }
                float lo, hi;
                unpack2(s0, lo, hi);  sc[half * 4 + 0] = (lo + hi) * scale;
                unpack2(s1, lo, hi);  sc[half * 4 + 1] = (lo + hi) * scale;
                unpack2(s2v, lo, hi); sc[half * 4 + 2] = (lo + hi) * scale;
                unpack2(s3, lo, hi);  sc[half * 4 + 3] = (lo + hi) * scale;
            }
            float gmax = -1e30f;
            #pragma unroll
            for (int j = 0; j < 8; j++)
                if (g + j <= jmax) gmax = fmaxf(gmax, sc[j]);
            float nm = fmaxf(mval, gmax);
            float f = __expf(mval - nm);
            lsum *= f;
            u64 f2 = dup2(f);
            #pragma unroll
            for (int d = 0; d < DH2; d++) acc2[d] = mul2(acc2[d], f2);
            #pragma unroll
            for (int j = 0; j < 8; j++) {
                float w = (g + j <= jmax) ? __expf(sc[j] - nm) : 0.f;
                lsum += w;
                u64 w2 = dup2(w);
                const ulonglong2* Vj = (const ulonglong2*)Vsh[buf][g + j];
                #pragma unroll
                for (int d = 0; d < DH4; d++) {
                    ulonglong2 vv = Vj[d];
                    acc2[2 * d]     = fma2(w2, vv.x, acc2[2 * d]);
                    acc2[2 * d + 1] = fma2(w2, vv.y, acc2[2 * d + 1]);
                }
            }
            mval = nm;
        }
        buf ^= 1;
    }
    pml[((size_t)s * NROWS + row) * NHEADS + h] = make_float2(mval, lsum);
    u64* pa = (u64*)(pacc + ((size_t)s * NROWS + row) * (size_t)D + h * DH);
    #pragma unroll
    for (int d = 0; d < DH2; d++) pa[d] = acc2[d];
}

// ---------------- routing: cos similarity of normalized q[l], k[l-1] ----------------
__global__ void route_kernel(const float* __restrict__ q, const float* __restrict__ k,
                             float* __restrict__ p, float* __restrict__ bh) {
    int wid = (blockIdx.x * blockDim.x + threadIdx.x) >> 5;
    int lane = threadIdx.x & 31;
    if (wid >= NROWS) return;
    int l = wid & (SEQ - 1);
    const float* qr = q + (size_t)wid * DENC;
    const float* kr = (l > 0) ? (k + (size_t)(wid - 1) * DENC) : nullptr;
    float nq = 0.f, nk = 0.f, dt = 0.f;
    for (int i = lane; i < DENC; i += 32) {
        float qv = qr[i];
        float kv = kr ? kr[i] : 0.f;
        nq += qv * qv; nk += kv * kv; dt += qv * kv;
    }
    #pragma unroll
    for (int o = 16; o; o >>= 1) {
        nq += __shfl_xor_sync(0xffffffffu, nq, o);
        nk += __shfl_xor_sync(0xffffffffu, nk, o);
        dt += __shfl_xor_sync(0xffffffffu, dt, o);
    }
    if (lane == 0) {
        float denom = fmaxf(sqrtf(nq), 1e-12f) * fmaxf(sqrtf(nk), 1e-12f);
        float cosv = dt / denom;
        float pv = fminf(fmaxf(0.5f * (1.f - cosv), 0.f), 1.f);
        if (l == 0) pv = 1.f;
        p[wid] = pv;
        bh[wid] = (pv >= 0.5f) ? 1.f : 0.f;
    }
}

// ---------------- per-batch inclusive scan of b_hard ----------------
__global__ void scan_kernel(const float* __restrict__ bh, int* __restrict__ cum,
                            int* __restrict__ counts) {
    int b = blockIdx.x, t = threadIdx.x;   // 1024 threads
    __shared__ int s[SEQ];
    s[t] = (int)bh[b * SEQ + t];
    __syncthreads();
    for (int o = 1; o < SEQ; o <<= 1) {
        int add = (t >= o) ? s[t - o] : 0;
        __syncthreads();
        s[t] += add;
        __syncthreads();
    }
    cum[b * SEQ + t] = s[t];
    if (t == SEQ - 1) counts[b] = s[t];
}

// ---------------- ratio loss ----------------
__global__ void stats_kernel(const float* __restrict__ bh, const float* __restrict__ p,
                             float* __restrict__ loss) {
    int t = threadIdx.x;   // 1024
    __shared__ float rb[1024], rp[1024];
    float sb = 0.f, sp = 0.f;
    for (int i = t; i < NROWS; i += 1024) { sb += bh[i]; sp += p[i]; }
    rb[t] = sb; rp[t] = sp;
    __syncthreads();
    for (int o = 512; o; o >>= 1) {
        if (t < o) { rb[t] += rb[t + o]; rp[t] += rp[t + o]; }
        __syncthreads();
    }
    if (t == 0) {
        float F = rb[0] / (float)NROWS, G = rp[0] / (float)NROWS;
        loss[0] = 1.2f * (5.f * F * G + (1.f - F) * (1.f - G));
    }
}

__global__ void zero_kernel(float* __restrict__ ptr, int n) {
    int i = blockIdx.x * blockDim.x + threadIdx.x;
    if (i < n) ptr[i] = 0.f;
}

// ---------------- scatter selected rows to front (downsample) ----------------
__global__ void scatter_kernel(const float* __restrict__ x, const float* __restrict__ p,
                               const float* __restrict__ bh, const int* __restrict__ cum,
                               float* __restrict__ comp, float* __restrict__ pcomp) {
    int row = blockIdx.x;
    if (bh[row] < 0.5f) return;
    int b = row >> 10;
    int dst = cum[row] - 1;
    int t = threadIdx.x;
    comp[((size_t)(b << 10) + dst) * DENC + t] = x[(size_t)row * DENC + t];
    if (t == 0) pcomp[(b << 10) + dst] = p[row];
}

// ---------------- EMA linear recurrence scan ----------------
__global__ void ema_kernel(const float* __restrict__ z, const float* __restrict__ pc,
                           float* __restrict__ zbar, const int* __restrict__ counts) {
    int b = blockIdx.x, d = threadIdx.x;   // 128 threads
    const float* zb = z + (size_t)b * SEQ * DENC;
    float* ob = zbar + (size_t)b * SEQ * DENC;
    const float* pb = pc + b * SEQ;
    int Tn = counts[b];
    float prev = 0.f;
    for (int t = 0; t < Tn; t++) {
        float pv = pb[t];
        float pcl = fminf(fmaxf(pv, 1e-4f), 0.9999f);
        float zv = zb[(size_t)t * DENC + d];
        float cur = (t == 0) ? zv : ((1.f - pcl) * prev + pcl * zv);
        ob[(size_t)t * DENC + d] = cur;
        prev = cur;
    }
}

// ---------------- gather + STE residual add ----------------
__global__ void gather_kernel(const float* __restrict__ zbar, const int* __restrict__ cum,
                              const float* __restrict__ p, const float* __restrict__ bh,
                              float* __restrict__ x) {
    int row = blockIdx.x, t = threadIdx.x;
    int b = row >> 10;
    int ci = cum[row] - 1; if (ci < 0) ci = 0;
    float pv = p[row], bv = bh[row];
    float c = bv * pv + (1.f - bv) * (1.f - pv);
    float cste = c + (1.f - c);   // forward value of STE (match ref rounding)
    x[(size_t)row * DENC + t] += cste * zbar[((size_t)(b << 10) + ci) * DENC + t];
}

__global__ void tail_kernel(float* __restrict__ dst, const float* __restrict__ loss) {
    dst[0] = loss[0];
}

// ---------------- host orchestration ----------------
static void* symaddr(const void* sym) {
    void* p = nullptr;
    cudaGetSymbolAddress(&p, sym);
    return p;
}

static const int PERM_SIG[32] = {
    0,1,2,3, 4,5,6,7,8,9,10,11, 12, 13,14,15,16,17,18,19,20, 21, 22,23,24,25,26,27,28,29, 30,31
};
static const int PERM_DICT[32] = {
    0,1,2,3, 8,9,10,11,12,13,14,15, 4, 16,17,18,19,20,21,22,23, 5, 24,25,26,27,28,29,30,31, 6,7
};
static const int PERM_ALPHA[32] = {
    0,9,31,30, 11,10,14,17,13,12,15,16, 29, 19,18,22,25,21,20,23,24, 28, 2,1,5,8,4,3,6,7, 27,26
};

extern "C" void kernel_launch(void* const* d_in, const int* in_sizes, int n_in,
                              void* d_out, int out_size) {
    (void)n_in;
    const int* perm;
    if (in_sizes[1] == 3 * DENC)            perm = PERM_ALPHA;
    else if (in_sizes[4] == DMAIN * DENC)   perm = PERM_DICT;
    else                                    perm = PERM_SIG;

    const float* inp[32];
    for (int i = 0; i < 32; i++) inp[i] = (const float*)d_in[perm[i]];

    const int*   ids       = (const int*)d_in[perm[0]];
    const float* embed     = inp[1];
    const float* wq        = inp[2];
    const float* wk        = inp[3];
    const float* enc_ln1w  = inp[4];
    const float* enc_ln1b  = inp[5];
    const float* enc_qkvw  = inp[6];
    const float* enc_wo    = inp[7];
    const float* enc_ln2w  = inp[8];
    const float* enc_ln2b  = inp[9];
    const float* enc_w1    = inp[10];
    const float* enc_w2    = inp[11];
    const float* proj_up   = inp[12];
    const float* mn_ln1w   = inp[13];
    const float* mn_ln1b   = inp[14];
    const float* mn_qkvw   = inp[15];
    const float* mn_wo     = inp[16];
    const float* mn_ln2w   = inp[17];
    const float* mn_ln2b   = inp[18];
    const float* mn_w1     = inp[19];
    const float* mn_w2     = inp[20];
    const float* proj_down = inp[21];
    const float* dc_ln1w   = inp[22];
    const float* dc_ln1b   = inp[23];
    const float* dc_qkvw   = inp[24];
    const float* dc_wo     = inp[25];
    const float* dc_ln2w   = inp[26];
    const float* dc_ln2b   = inp[27];
    const float* dc_w1     = inp[28];
    const float* dc_w2     = inp[29];
    const float* norm_w    = inp[30];
    const float* norm_b    = inp[31];

    float*  x     = (float*)symaddr(g_x);
    float*  lnp   = (float*)symaddr(g_lnbuf);
    float*  qkvp  = (float*)symaddr(g_qkv);
    float*  mlpp  = (float*)symaddr(g_mlp);
    float*  zp    = (float*)symaddr(g_z);
    float*  compp = (float*)symaddr(g_comp);
    float*  qrp   = (float*)symaddr(g_qr);
    float*  krp   = (float*)symaddr(g_kr);
    float*  zdp   = (float*)symaddr(g_zdown);
    float*  zbp   = (float*)symaddr(g_zbar);
    float*  pp    = (float*)symaddr(g_p);
    float*  bhp   = (float*)symaddr(g_bh);
    float*  pcp   = (float*)symaddr(g_pcomp);
    int*    cump  = (int*)symaddr(g_cum);
    int*    cntp  = (int*)symaddr(g_counts);
    float*  lossp = (float*)symaddr(g_loss);
    float*  paccp = (float*)symaddr(g_pacc);
    float2* pmlp  = (float2*)symaddr(g_pml);

    auto gemm_grid = [](int N) { return dim3((N + 127) / 128, 128); };

    auto run_block = [&](float* xb, int D, int dh,
                         const float* l1w, const float* l1b,
                         const float* qw, const float* wo,
                         const float* l2w, const float* l2b,
                         const float* w1, const float* w2,
                         const int* cnts) {
        int D3 = 3 * D;
        ln_kernel<<<NROWS / 2, 2 * D>>>(xb, l1w, l1b, lnp, D, cnts);
        gemm_kernel<0, 0><<<gemm_grid(D3), 256>>>(lnp, qw, qkvp, D3, D, cnts, nullptr, 0);
        if (dh == 32) {
            attn_part_kernel<32, 32, 4><<<dim3(BATCH * NHEADS, SEQ / 128, ASPLIT), 128>>>(
                qkvp, paccp, pmlp, D, cnts, 0.17677669529663687f);
            gemm_kernel<1, 1><<<gemm_grid(D), 256>>>(paccp, wo, xb, D, D, cnts, pmlp, 5);
        } else {
            attn_part_kernel<64, 16, 3><<<dim3(BATCH * NHEADS, SEQ / 128, ASPLIT), 128>>>(
                qkvp, paccp, pmlp, D, cnts, 0.125f);
            gemm_kernel<1, 1><<<gemm_grid(D), 256>>>(paccp, wo, xb, D, D, cnts, pmlp, 6);
        }
        ln_kernel<<<NROWS / 2, 2 * D>>>(xb, l2w, l2b, lnp, D, cnts);
        gemm_kernel<2, 0><<<gemm_grid(2 * D), 256>>>(lnp, w1, mlpp, 2 * D, D, cnts, nullptr, 0);
        gemm_kernel<1, 0><<<gemm_grid(D), 256>>>(mlpp, w2, xb, D, 2 * D, cnts, nullptr, 0);
    };

    // ---- encoder ----
    embed_kernel<<<NROWS, DENC>>>(ids, embed, x);
    for (int i = 0; i < 3; i++)
        run_block(x, DENC, 32,
                  enc_ln1w + i * DENC, enc_ln1b + i * DENC,
                  enc_qkvw + (size_t)i * 3 * DENC * DENC,
                  enc_wo   + (size_t)i * DENC * DENC,
                  enc_ln2w + i * DENC, enc_ln2b + i * DENC,
                  enc_w1   + (size_t)i * 2 * DENC * DENC,
                  enc_w2   + (size_t)i * 2 * DENC * DENC,
                  nullptr);

    // ---- routing / dynamic chunking ----
    gemm_kernel<0, 0><<<gemm_grid(DENC), 256>>>(x, wq, qrp, DENC, DENC, nullptr, nullptr, 0);
    gemm_kernel<0, 0><<<gemm_grid(DENC), 256>>>(x, wk, krp, DENC, DENC, nullptr, nullptr, 0);
    route_kernel<<<NROWS / 8, 256>>>(qrp, krp, pp, bhp);
    scan_kernel<<<BATCH, SEQ>>>(bhp, cump, cntp);
    stats_kernel<<<1, 1024>>>(bhp, pp, lossp);
    zero_kernel<<<(NROWS * DENC + 255) / 256, 256>>>(compp, NROWS * DENC);
    zero_kernel<<<(NROWS + 255) / 256, 256>>>(pcp, NROWS);
    scatter_kernel<<<NROWS, DENC>>>(x, pp, bhp, cump, compp, pcp);

    // ---- main stack (padded + masked; padded rows dynamically elided) ----
    gemm_kernel<0, 0><<<gemm_grid(DMAIN), 256>>>(compp, proj_up, zp, DMAIN, DENC, cntp, nullptr, 0);
    for (int i = 0; i < 6; i++)
        run_block(zp, DMAIN, 64,
                  mn_ln1w + i * DMAIN, mn_ln1b + i * DMAIN,
                  mn_qkvw + (size_t)i * 3 * DMAIN * DMAIN,
                  mn_wo   + (size_t)i * DMAIN * DMAIN,
                  mn_ln2w + i * DMAIN, mn_ln2b + i * DMAIN,
                  mn_w1   + (size_t)i * 2 * DMAIN * DMAIN,
                  mn_w2   + (size_t)i * 2 * DMAIN * DMAIN,
                  cntp);
    gemm_kernel<0, 0><<<gemm_grid(DENC), 256>>>(zp, proj_down, zdp, DENC, DMAIN, cntp, nullptr, 0);

    // ---- EMA scan + gather + STE add ----
    ema_kernel<<<BATCH, DENC>>>(zdp, pcp, zbp, cntp);
    gather_kernel<<<NROWS, DENC>>>(zbp, cump, pp, bhp, x);

    // ---- decoder ----
    for (int i = 0; i < 3; i++)
        run_block(x, DENC, 32,
                  dc_ln1w + i * DENC, dc_ln1b + i * DENC,
                  dc_qkvw + (size_t)i * 3 * DENC * DENC,
                  dc_wo   + (size_t)i * DENC * DENC,
                  dc_ln2w + i * DENC, dc_ln2b + i * DENC,
                  dc_w1   + (size_t)i * 2 * DENC * DENC,
                  dc_w2   + (size_t)i * 2 * DENC * DENC,
                  nullptr);

    // ---- final norm + tied logits head ----
    ln_kernel<<<NROWS / 2, 2 * DENC>>>(x, norm_w, norm_b, lnp, DENC, nullptr);
    gemm_kernel<0, 0><<<gemm_grid(260), 256>>>(lnp, embed, (float*)d_out, 260, DENC, nullptr, nullptr, 0);

    const int NLOGITS = NROWS * 260;
    if (out_size > NLOGITS)
        tail_kernel<<<1, 1>>>((float*)d_out + NLOGITS, lossp);
}

// round 16
// speedup vs baseline: 1.2854x; 1.0360x over previous
#include <cuda_runtime.h>
#include <cuda_bf16.h>
#include <math.h>

#define BATCH 8
#define SEQ   1024
#define NROWS (BATCH*SEQ)   // 8192
#define DENC  128
#define DMAIN 256
#define NHEADS 4
#define ASPLIT 4

// ---------------- scratch (device globals: no allocation in kernel_launch) ----------------
__device__ float g_x[NROWS*DENC];
__device__ float g_lnbuf[NROWS*DMAIN];
__device__ float g_qkv[NROWS*3*DMAIN];
__device__ float g_mlp[NROWS*2*DMAIN];
__device__ float g_z[NROWS*DMAIN];
__device__ float g_comp[NROWS*DENC];
__device__ float g_qr[NROWS*DENC];
__device__ float g_kr[NROWS*DENC];
__device__ float g_zdown[NROWS*DENC];
__device__ float g_zbar[NROWS*DENC];
__device__ float g_p[NROWS];
__device__ float g_bh[NROWS];
__device__ float g_pcomp[NROWS];
__device__ int   g_cum[NROWS];
__device__ int   g_counts[BATCH];
__device__ float g_loss[1];
__device__ float  g_pacc[ASPLIT*NROWS*DMAIN];          // split-K attention partial acc
__device__ float2 g_pml[ASPLIT*NROWS*NHEADS];          // split-K attention partial (m, l)

// ---------------- f32x2 packed-FMA helpers (Blackwell FFMA2, PTX-only) ----------------
typedef unsigned long long u64;
__device__ __forceinline__ u64 dup2(float v) {
    u64 r; asm("mov.b64 %0, {%1, %1};" : "=l"(r) : "f"(v)); return r;
}
__device__ __forceinline__ void unpack2(u64 v, float& lo, float& hi) {
    asm("mov.b64 {%0, %1}, %2;" : "=f"(lo), "=f"(hi) : "l"(v));
}
__device__ __forceinline__ u64 fma2(u64 a, u64 b, u64 c) {
    u64 d; asm("fma.rn.f32x2 %0, %1, %2, %3;" : "=l"(d) : "l"(a), "l"(b), "l"(c)); return d;
}
__device__ __forceinline__ u64 mul2(u64 a, u64 b) {
    u64 d; asm("mul.rn.f32x2 %0, %1, %2;" : "=l"(d) : "l"(a), "l"(b)); return d;
}

__device__ __forceinline__ float gelu_exact(float v) {
    return 0.5f * v * (1.0f + erff(v * 0.70710678118654752440f));
}

// ---------------- embedding lookup ----------------
__global__ void embed_kernel(const int* __restrict__ ids, const float* __restrict__ emb,
                             float* __restrict__ x) {
    int row = blockIdx.x;
    int t = threadIdx.x;
    x[(size_t)row * DENC + t] = emb[(size_t)ids[row] * DENC + t];
}

// ---------------- LayerNorm: 2 rows per block, blockDim = 2*D ----------------
__global__ void ln_kernel(const float* __restrict__ x, const float* __restrict__ w,
                          const float* __restrict__ b, float* __restrict__ y, int D,
                          const int* __restrict__ cnts) {
    int t = threadIdx.x;
    int sub = (t >= D) ? 1 : 0;
    int tr = t - sub * D;
    int row = (blockIdx.x << 1) + sub;
    bool live = !(cnts && (row & (SEQ - 1)) >= cnts[row >> 10]);
    __shared__ float sw[2][8];
    __shared__ float sred[2];
    float v = live ? x[(size_t)row * D + tr] : 0.f;
    float s = v;
    #pragma unroll
    for (int o = 16; o; o >>= 1) s += __shfl_xor_sync(0xffffffffu, s, o);
    int wps = D >> 5;
    int lw = (t >> 5) - sub * wps;
    if ((t & 31) == 0) sw[sub][lw] = s;
    __syncthreads();
    if (tr == 0) {
        float tot = 0.f;
        for (int i = 0; i < wps; i++) tot += sw[sub][i];
        sred[sub] = tot / (float)D;
    }
    __syncthreads();
    float mu = sred[sub];
    float dlt = v - mu;
    s = dlt * dlt;
    #pragma unroll
    for (int o = 16; o; o >>= 1) s += __shfl_xor_sync(0xffffffffu, s, o);
    __syncthreads();
    if ((t & 31) == 0) sw[sub][lw] = s;
    __syncthreads();
    if (tr == 0) {
        float tot = 0.f;
        for (int i = 0; i < wps; i++) tot += sw[sub][i];
        sred[sub] = rsqrtf(tot / (float)D + 1e-5f);
    }
    __syncthreads();
    if (live) y[(size_t)row * D + tr] = dlt * sred[sub] * w[tr] + b[tr];
}

// ---------------- SGEMM (FFMA2, double-buffered): C[M,N] (+)= act(A @ W^T) ----------------
// BM=64, BN=128, BK=8, 256 threads, 4x8 per thread (2 f32x2 row-pairs x 8 cols).
// Register-staged double buffering: next tile's global loads issue right after
// the single per-stage sync, hiding DRAM/L2 latency under the FMA phase.
// FUSE: 0 = store, 1 = C += result, 2 = gelu(result)
// MERGE: A computed on the fly as exact split-K softmax merge of (pacc, pml).
template<int FUSE, int MERGE>
__global__ __launch_bounds__(256)
void gemm_kernel(const float* __restrict__ A, const float* __restrict__ W,
                 float* __restrict__ C, int N, int K, const int* __restrict__ cnts,
                 const float2* __restrict__ pml, int dhshift) {
    int row0 = blockIdx.y * 64, col0 = blockIdx.x * 128;
    if (cnts && (row0 & (SEQ - 1)) >= cnts[row0 >> 10]) return;
    __shared__ __align__(16) float As[2][8][64];
    __shared__ __align__(16) float Ws[2][8][128];
    int tid = threadIdx.x;
    int tr = (tid >> 4) << 2;     // 4 rows per thread
    int tc = (tid & 15) << 3;     // 8 cols per thread
    u64 acc2[2][8];
    #pragma unroll
    for (int p = 0; p < 2; p++)
        #pragma unroll
        for (int j = 0; j < 8; j++) acc2[p][j] = 0ull;
    // A tile loads: 64x8 floats, float2 per thread
    int la = tid << 1;
    int lar = la >> 3, lac = la & 7;
    int grow = row0 + lar;
    const float* Ag = A + (size_t)grow * K + lac;
    // W tile loads: 128x8 floats, float4 per thread
    int lw = tid << 2;
    int lwr = lw >> 3, lwc = lw & 7;
    int wrow = col0 + lwr;
    bool wok = wrow < N;
    const float* Wg = W + (size_t)(wok ? wrow : 0) * K + lwc;

    auto loadA = [&](int k0) -> float2 {
        if (!MERGE) {
            return *(const float2*)(Ag + k0);
        } else {
            int col = k0 + lac;
            int h = col >> dhshift;
            float mm[ASPLIT], ll[ASPLIT];
            float M = -1e30f;
            #pragma unroll
            for (int s = 0; s < ASPLIT; s++) {
                float2 v = pml[((size_t)s * NROWS + grow) * NHEADS + h];
                mm[s] = v.x; ll[s] = v.y;
                M = fmaxf(M, v.x);
            }
            float L = 0.f, ax = 0.f, ay = 0.f;
            #pragma unroll
            for (int s = 0; s < ASPLIT; s++) {
                float e = __expf(mm[s] - M);
                L = fmaf(ll[s], e, L);
                float2 pv = *(const float2*)(A + ((size_t)s * NROWS + grow) * K + col);
                ax = fmaf(pv.x, e, ax);
                ay = fmaf(pv.y, e, ay);
            }
            float inv = 1.f / fmaxf(L, 1e-30f);   // guard only fires for dead rows
            return make_float2(ax * inv, ay * inv);
        }
    };
    auto loadW = [&](int k0) -> float4 {
        return wok ? *(const float4*)(Wg + k0) : make_float4(0.f, 0.f, 0.f, 0.f);
    };

    float2 av = loadA(0);
    float4 wv = loadW(0);
    int buf = 0;
    for (int k0 = 0; k0 < K; k0 += 8) {
        As[buf][lac + 0][lar] = av.x; As[buf][lac + 1][lar] = av.y;
        Ws[buf][lwc + 0][lwr] = wv.x; Ws[buf][lwc + 1][lwr] = wv.y;
        Ws[buf][lwc + 2][lwr] = wv.z; Ws[buf][lwc + 3][lwr] = wv.w;
        __syncthreads();
        if (k0 + 8 < K) {             // prefetch next stage; latency hides under FMAs
            av = loadA(k0 + 8);
            wv = loadW(k0 + 8);
        }
        #pragma unroll
        for (int k = 0; k < 8; k++) {
            ulonglong2 aA = *(const ulonglong2*)(&As[buf][k][tr]);   // 4 rows = 2 pairs
            u64 a2[2] = { aA.x, aA.y };
            float4 w0 = *(const float4*)(&Ws[buf][k][tc]);
            float4 w1 = *(const float4*)(&Ws[buf][k][tc + 4]);
            u64 wd[8];
            wd[0] = dup2(w0.x); wd[1] = dup2(w0.y); wd[2] = dup2(w0.z); wd[3] = dup2(w0.w);
            wd[4] = dup2(w1.x); wd[5] = dup2(w1.y); wd[6] = dup2(w1.z); wd[7] = dup2(w1.w);
            #pragma unroll
            for (int p = 0; p < 2; p++)
                #pragma unroll
                for (int j = 0; j < 8; j++)
                    acc2[p][j] = fma2(a2[p], wd[j], acc2[p][j]);
        }
        buf ^= 1;
        // safe without a second sync: stores at stage i+1 touch buffer buf^1,
        // whose last readers finished before passing stage i's barrier.
    }
    #pragma unroll
    for (int p = 0; p < 2; p++) {
        float* Cr0 = C + (size_t)(row0 + tr + 2 * p) * N;
        float* Cr1 = Cr0 + N;
        #pragma unroll
        for (int j = 0; j < 8; j++) {
            int cc = col0 + tc + j;
            if (cc < N) {
                float lo, hi;
                unpack2(acc2[p][j], lo, hi);
                if (FUSE == 1) { lo += Cr0[cc]; hi += Cr1[cc]; }
                if (FUSE == 2) { lo = gelu_exact(lo); hi = gelu_exact(hi); }
                Cr0[cc] = lo; Cr1[cc] = hi;
            }
        }
    }
}

// ---------------- split-K flash attention: partial pass ----------------
// grid: (BATCH*NHEADS, SEQ/128, ASPLIT), block 128 threads, 1 query row/thread.
// Double-buffered smem tiles with register staging, ONE sync per tile.
// Scores in groups of 8 with exact per-group online rescale.
template<int DH, int NT, int MINB>
__global__ __launch_bounds__(128, MINB)
void attn_part_kernel(const float* __restrict__ qkv, float* __restrict__ pacc,
                      float2* __restrict__ pml, int D,
                      const int* __restrict__ counts, float scale) {
    const int D3 = 3 * D;
    const int DH2 = DH / 2, DH4 = DH / 4;
    const int DQ = DH / 4;                 // float4 per K/V row
    int b = blockIdx.x >> 2, h = blockIdx.x & 3;
    int s = blockIdx.z;
    int tid = threadIdx.x;
    int q = blockIdx.y * 128 + tid;
    __shared__ __align__(16) float Ksh[2][NT][DH];
    __shared__ __align__(16) float Vsh[2][NT][DH];
    int cnt = counts ? counts[b] : SEQ;
    if (counts && (int)(blockIdx.y * 128) >= cnt) return;   // merge guard handles dead rows
    int row = b * SEQ + q;
    int qlim = (q < cnt) ? q : -1;
    int limit = min((int)(blockIdx.y * 128 + 127), cnt - 1);
    int T = limit / NT + 1;
    int t0 = (s * T) / ASPLIT, t1 = ((s + 1) * T) / ASPLIT;
    const u64* qrow2 = (const u64*)(qkv + (size_t)row * D3 + h * DH);
    u64 q2[DH2], acc2[DH2];
    #pragma unroll
    for (int d = 0; d < DH2; d++) { q2[d] = qrow2[d]; acc2[d] = 0ull; }
    float mval = -1e30f, lsum = 0.f;

    // loader mapping: 2 float4 of K and 2 of V per thread per tile
    int i0 = tid, i1 = tid + 128;
    int j0l = i0 / DQ, d0 = (i0 - j0l * DQ) << 2;
    int j1l = i1 / DQ, d1 = (i1 - j1l * DQ) << 2;
    size_t off0 = (size_t)(b * SEQ + j0l) * D3 + h * DH + d0;
    size_t off1 = (size_t)(b * SEQ + j1l) * D3 + h * DH + d1;
    float4 k0r, k1r, v0r, v1r;
    if (t0 < t1) {
        size_t a0 = off0 + (size_t)(t0 * NT) * D3;
        size_t a1 = off1 + (size_t)(t0 * NT) * D3;
        k0r = *(const float4*)(qkv + a0 + D);     v0r = *(const float4*)(qkv + a0 + 2 * D);
        k1r = *(const float4*)(qkv + a1 + D);     v1r = *(const float4*)(qkv + a1 + 2 * D);
    }
    int buf = 0;
    for (int kt = t0; kt < t1; kt++) {
        *(float4*)(&Ksh[buf][j0l][d0]) = k0r;  *(float4*)(&Vsh[buf][j0l][d0]) = v0r;
        *(float4*)(&Ksh[buf][j1l][d1]) = k1r;  *(float4*)(&Vsh[buf][j1l][d1]) = v1r;
        __syncthreads();
        if (kt + 1 < t1) {   // prefetch next tile into regs; latency hides under compute
            size_t a0 = off0 + (size_t)((kt + 1) * NT) * D3;
            size_t a1 = off1 + (size_t)((kt + 1) * NT) * D3;
            k0r = *(const float4*)(qkv + a0 + D);  v0r = *(const float4*)(qkv + a0 + 2 * D);
            k1r = *(const float4*)(qkv + a1 + D);  v1r = *(const float4*)(qkv + a1 + 2 * D);
        }
        int jmax = qlim - kt * NT;
        if (jmax > NT - 1) jmax = NT - 1;
        for (int g = 0; g <= jmax; g += 8) {
            float sc[8];
            #pragma unroll
            for (int half = 0; half < 2; half++) {
                const ulonglong2* K0 = (const ulonglong2*)Ksh[buf][g + half * 4 + 0];
                const ulonglong2* K1 = (const ulonglong2*)Ksh[buf][g + half * 4 + 1];
                const ulonglong2* K2 = (const ulonglong2*)Ksh[buf][g + half * 4 + 2];
                const ulonglong2* K3 = (const ulonglong2*)Ksh[buf][g + half * 4 + 3];
                u64 s0 = 0ull, s1 = 0ull, s2v = 0ull, s3 = 0ull;
                #pragma unroll
                for (int d = 0; d < DH4; d++) {
                    u64 qa = q2[2 * d], qb = q2[2 * d + 1];
                    ulonglong2 ka = K0[d], kb = K1[d], kc = K2[d], kd = K3[d];
                    s0 = fma2(qa, ka.x, s0);   s0 = fma2(qb, ka.y, s0);
                    s1 = fma2(qa, kb.x, s1);   s1 = fma2(qb, kb.y, s1);
                    s2v = fma2(qa, kc.x, s2v); s2v = fma2(qb, kc.y, s2v);
                    s3 = fma2(qa, kd.x, s3);   s3 = fma2(qb, kd.y, s3);
                }
                float lo, hi;
                unpack2(s0, lo, hi);  sc[half * 4 + 0] = (lo + hi) * scale;
                unpack2(s1, lo, hi);  sc[half * 4 + 1] = (lo + hi) * scale;
                unpack2(s2v, lo, hi); sc[half * 4 + 2] = (lo + hi) * scale;
                unpack2(s3, lo, hi);  sc[half * 4 + 3] = (lo + hi) * scale;
            }
            float gmax = -1e30f;
            #pragma unroll
            for (int j = 0; j < 8; j++)
                if (g + j <= jmax) gmax = fmaxf(gmax, sc[j]);
            float nm = fmaxf(mval, gmax);
            float f = __expf(mval - nm);
            lsum *= f;
            u64 f2 = dup2(f);
            #pragma unroll
            for (int d = 0; d < DH2; d++) acc2[d] = mul2(acc2[d], f2);
            #pragma unroll
            for (int j = 0; j < 8; j++) {
                float w = (g + j <= jmax) ? __expf(sc[j] - nm) : 0.f;
                lsum += w;
                u64 w2 = dup2(w);
                const ulonglong2* Vj = (const ulonglong2*)Vsh[buf][g + j];
                #pragma unroll
                for (int d = 0; d < DH4; d++) {
                    ulonglong2 vv = Vj[d];
                    acc2[2 * d]     = fma2(w2, vv.x, acc2[2 * d]);
                    acc2[2 * d + 1] = fma2(w2, vv.y, acc2[2 * d + 1]);
                }
            }
            mval = nm;
        }
        buf ^= 1;
    }
    pml[((size_t)s * NROWS + row) * NHEADS + h] = make_float2(mval, lsum);
    u64* pa = (u64*)(pacc + ((size_t)s * NROWS + row) * (size_t)D + h * DH);
    #pragma unroll
    for (int d = 0; d < DH2; d++) pa[d] = acc2[d];
}

// ---------------- routing: cos similarity of normalized q[l], k[l-1] ----------------
__global__ void route_kernel(const float* __restrict__ q, const float* __restrict__ k,
                             float* __restrict__ p, float* __restrict__ bh) {
    int wid = (blockIdx.x * blockDim.x + threadIdx.x) >> 5;
    int lane = threadIdx.x & 31;
    if (wid >= NROWS) return;
    int l = wid & (SEQ - 1);
    const float* qr = q + (size_t)wid * DENC;
    const float* kr = (l > 0) ? (k + (size_t)(wid - 1) * DENC) : nullptr;
    float nq = 0.f, nk = 0.f, dt = 0.f;
    for (int i = lane; i < DENC; i += 32) {
        float qv = qr[i];
        float kv = kr ? kr[i] : 0.f;
        nq += qv * qv; nk += kv * kv; dt += qv * kv;
    }
    #pragma unroll
    for (int o = 16; o; o >>= 1) {
        nq += __shfl_xor_sync(0xffffffffu, nq, o);
        nk += __shfl_xor_sync(0xffffffffu, nk, o);
        dt += __shfl_xor_sync(0xffffffffu, dt, o);
    }
    if (lane == 0) {
        float denom = fmaxf(sqrtf(nq), 1e-12f) * fmaxf(sqrtf(nk), 1e-12f);
        float cosv = dt / denom;
        float pv = fminf(fmaxf(0.5f * (1.f - cosv), 0.f), 1.f);
        if (l == 0) pv = 1.f;
        p[wid] = pv;
        bh[wid] = (pv >= 0.5f) ? 1.f : 0.f;
    }
}

// ---------------- per-batch inclusive scan of b_hard ----------------
__global__ void scan_kernel(const float* __restrict__ bh, int* __restrict__ cum,
                            int* __restrict__ counts) {
    int b = blockIdx.x, t = threadIdx.x;   // 1024 threads
    __shared__ int s[SEQ];
    s[t] = (int)bh[b * SEQ + t];
    __syncthreads();
    for (int o = 1; o < SEQ; o <<= 1) {
        int add = (t >= o) ? s[t - o] : 0;
        __syncthreads();
        s[t] += add;
        __syncthreads();
    }
    cum[b * SEQ + t] = s[t];
    if (t == SEQ - 1) counts[b] = s[t];
}

// ---------------- ratio loss ----------------
__global__ void stats_kernel(const float* __restrict__ bh, const float* __restrict__ p,
                             float* __restrict__ loss) {
    int t = threadIdx.x;   // 1024
    __shared__ float rb[1024], rp[1024];
    float sb = 0.f, sp = 0.f;
    for (int i = t; i < NROWS; i += 1024) { sb += bh[i]; sp += p[i]; }
    rb[t] = sb; rp[t] = sp;
    __syncthreads();
    for (int o = 512; o; o >>= 1) {
        if (t < o) { rb[t] += rb[t + o]; rp[t] += rp[t + o]; }
        __syncthreads();
    }
    if (t == 0) {
        float F = rb[0] / (float)NROWS, G = rp[0] / (float)NROWS;
        loss[0] = 1.2f * (5.f * F * G + (1.f - F) * (1.f - G));
    }
}

__global__ void zero_kernel(float* __restrict__ ptr, int n) {
    int i = blockIdx.x * blockDim.x + threadIdx.x;
    if (i < n) ptr[i] = 0.f;
}

// ---------------- scatter selected rows to front (downsample) ----------------
__global__ void scatter_kernel(const float* __restrict__ x, const float* __restrict__ p,
                               const float* __restrict__ bh, const int* __restrict__ cum,
                               float* __restrict__ comp, float* __restrict__ pcomp) {
    int row = blockIdx.x;
    if (bh[row] < 0.5f) return;
    int b = row >> 10;
    int dst = cum[row] - 1;
    int t = threadIdx.x;
    comp[((size_t)(b << 10) + dst) * DENC + t] = x[(size_t)row * DENC + t];
    if (t == 0) pcomp[(b << 10) + dst] = p[row];
}

// ---------------- EMA linear recurrence scan ----------------
__global__ void ema_kernel(const float* __restrict__ z, const float* __restrict__ pc,
                           float* __restrict__ zbar, const int* __restrict__ counts) {
    int b = blockIdx.x, d = threadIdx.x;   // 128 threads
    const float* zb = z + (size_t)b * SEQ * DENC;
    float* ob = zbar + (size_t)b * SEQ * DENC;
    const float* pb = pc + b * SEQ;
    int Tn = counts[b];
    float prev = 0.f;
    for (int t = 0; t < Tn; t++) {
        float pv = pb[t];
        float pcl = fminf(fmaxf(pv, 1e-4f), 0.9999f);
        float zv = zb[(size_t)t * DENC + d];
        float cur = (t == 0) ? zv : ((1.f - pcl) * prev + pcl * zv);
        ob[(size_t)t * DENC + d] = cur;
        prev = cur;
    }
}

// ---------------- gather + STE residual add ----------------
__global__ void gather_kernel(const float* __restrict__ zbar, const int* __restrict__ cum,
                              const float* __restrict__ p, const float* __restrict__ bh,
                              float* __restrict__ x) {
    int row = blockIdx.x, t = threadIdx.x;
    int b = row >> 10;
    int ci = cum[row] - 1; if (ci < 0) ci = 0;
    float pv = p[row], bv = bh[row];
    float c = bv * pv + (1.f - bv) * (1.f - pv);
    float cste = c + (1.f - c);   // forward value of STE (match ref rounding)
    x[(size_t)row * DENC + t] += cste * zbar[((size_t)(b << 10) + ci) * DENC + t];
}

__global__ void tail_kernel(float* __restrict__ dst, const float* __restrict__ loss) {
    dst[0] = loss[0];
}

// ---------------- host orchestration ----------------
static void* symaddr(const void* sym) {
    void* p = nullptr;
    cudaGetSymbolAddress(&p, sym);
    return p;
}

static const int PERM_SIG[32] = {
    0,1,2,3, 4,5,6,7,8,9,10,11, 12, 13,14,15,16,17,18,19,20, 21, 22,23,24,25,26,27,28,29, 30,31
};
static const int PERM_DICT[32] = {
    0,1,2,3, 8,9,10,11,12,13,14,15, 4, 16,17,18,19,20,21,22,23, 5, 24,25,26,27,28,29,30,31, 6,7
};
static const int PERM_ALPHA[32] = {
    0,9,31,30, 11,10,14,17,13,12,15,16, 29, 19,18,22,25,21,20,23,24, 28, 2,1,5,8,4,3,6,7, 27,26
};

extern "C" void kernel_launch(void* const* d_in, const int* in_sizes, int n_in,
                              void* d_out, int out_size) {
    (void)n_in;
    const int* perm;
    if (in_sizes[1] == 3 * DENC)            perm = PERM_ALPHA;
    else if (in_sizes[4] == DMAIN * DENC)   perm = PERM_DICT;
    else                                    perm = PERM_SIG;

    const float* inp[32];
    for (int i = 0; i < 32; i++) inp[i] = (const float*)d_in[perm[i]];

    const int*   ids       = (const int*)d_in[perm[0]];
    const float* embed     = inp[1];
    const float* wq        = inp[2];
    const float* wk        = inp[3];
    const float* enc_ln1w  = inp[4];
    const float* enc_ln1b  = inp[5];
    const float* enc_qkvw  = inp[6];
    const float* enc_wo    = inp[7];
    const float* enc_ln2w  = inp[8];
    const float* enc_ln2b  = inp[9];
    const float* enc_w1    = inp[10];
    const float* enc_w2    = inp[11];
    const float* proj_up   = inp[12];
    const float* mn_ln1w   = inp[13];
    const float* mn_ln1b   = inp[14];
    const float* mn_qkvw   = inp[15];
    const float* mn_wo     = inp[16];
    const float* mn_ln2w   = inp[17];
    const float* mn_ln2b   = inp[18];
    const float* mn_w1     = inp[19];
    const float* mn_w2     = inp[20];
    const float* proj_down = inp[21];
    const float* dc_ln1w   = inp[22];
    const float* dc_ln1b   = inp[23];
    const float* dc_qkvw   = inp[24];
    const float* dc_wo     = inp[25];
    const float* dc_ln2w   = inp[26];
    const float* dc_ln2b   = inp[27];
    const float* dc_w1     = inp[28];
    const float* dc_w2     = inp[29];
    const float* norm_w    = inp[30];
    const float* norm_b    = inp[31];

    float*  x     = (float*)symaddr(g_x);
    float*  lnp   = (float*)symaddr(g_lnbuf);
    float*  qkvp  = (float*)symaddr(g_qkv);
    float*  mlpp  = (float*)symaddr(g_mlp);
    float*  zp    = (float*)symaddr(g_z);
    float*  compp = (float*)symaddr(g_comp);
    float*  qrp   = (float*)symaddr(g_qr);
    float*  krp   = (float*)symaddr(g_kr);
    float*  zdp   = (float*)symaddr(g_zdown);
    float*  zbp   = (float*)symaddr(g_zbar);
    float*  pp    = (float*)symaddr(g_p);
    float*  bhp   = (float*)symaddr(g_bh);
    float*  pcp   = (float*)symaddr(g_pcomp);
    int*    cump  = (int*)symaddr(g_cum);
    int*    cntp  = (int*)symaddr(g_counts);
    float*  lossp = (float*)symaddr(g_loss);
    float*  paccp = (float*)symaddr(g_pacc);
    float2* pmlp  = (float2*)symaddr(g_pml);

    auto gemm_grid = [](int N) { return dim3((N + 127) / 128, 128); };

    auto run_block = [&](float* xb, int D, int dh,
                         const float* l1w, const float* l1b,
                         const float* qw, const float* wo,
                         const float* l2w, const float* l2b,
                         const float* w1, const float* w2,
                         const int* cnts) {
        int D3 = 3 * D;
        ln_kernel<<<NROWS / 2, 2 * D>>>(xb, l1w, l1b, lnp, D, cnts);
        gemm_kernel<0, 0><<<gemm_grid(D3), 256>>>(lnp, qw, qkvp, D3, D, cnts, nullptr, 0);
        if (dh == 32) {
            attn_part_kernel<32, 32, 4><<<dim3(BATCH * NHEADS, SEQ / 128, ASPLIT), 128>>>(
                qkvp, paccp, pmlp, D, cnts, 0.17677669529663687f);
            gemm_kernel<1, 1><<<gemm_grid(D), 256>>>(paccp, wo, xb, D, D, cnts, pmlp, 5);
        } else {
            attn_part_kernel<64, 16, 3><<<dim3(BATCH * NHEADS, SEQ / 128, ASPLIT), 128>>>(
                qkvp, paccp, pmlp, D, cnts, 0.125f);
            gemm_kernel<1, 1><<<gemm_grid(D), 256>>>(paccp, wo, xb, D, D, cnts, pmlp, 6);
        }
        ln_kernel<<<NROWS / 2, 2 * D>>>(xb, l2w, l2b, lnp, D, cnts);
        gemm_kernel<2, 0><<<gemm_grid(2 * D), 256>>>(lnp, w1, mlpp, 2 * D, D, cnts, nullptr, 0);
        gemm_kernel<1, 0><<<gemm_grid(D), 256>>>(mlpp, w2, xb, D, 2 * D, cnts, nullptr, 0);
    };

    // ---- encoder ----
    embed_kernel<<<NROWS, DENC>>>(ids, embed, x);
    for (int i = 0; i < 3; i++)
        run_block(x, DENC, 32,
                  enc_ln1w + i * DENC, enc_ln1b + i * DENC,
                  enc_qkvw + (size_t)i * 3 * DENC * DENC,
                  enc_wo   + (size_t)i * DENC * DENC,
                  enc_ln2w + i * DENC, enc_ln2b + i * DENC,
                  enc_w1   + (size_t)i * 2 * DENC * DENC,
                  enc_w2   + (size_t)i * 2 * DENC * DENC,
                  nullptr);

    // ---- routing / dynamic chunking ----
    gemm_kernel<0, 0><<<gemm_grid(DENC), 256>>>(x, wq, qrp, DENC, DENC, nullptr, nullptr, 0);
    gemm_kernel<0, 0><<<gemm_grid(DENC), 256>>>(x, wk, krp, DENC, DENC, nullptr, nullptr, 0);
    route_kernel<<<NROWS / 8, 256>>>(qrp, krp, pp, bhp);
    scan_kernel<<<BATCH, SEQ>>>(bhp, cump, cntp);
    stats_kernel<<<1, 1024>>>(bhp, pp, lossp);
    zero_kernel<<<(NROWS * DENC + 255) / 256, 256>>>(compp, NROWS * DENC);
    zero_kernel<<<(NROWS + 255) / 256, 256>>>(pcp, NROWS);
    scatter_kernel<<<NROWS, DENC>>>(x, pp, bhp, cump, compp, pcp);

    // ---- main stack (padded + masked; padded rows dynamically elided) ----
    gemm_kernel<0, 0><<<gemm_grid(DMAIN), 256>>>(compp, proj_up, zp, DMAIN, DENC, cntp, nullptr, 0);
    for (int i = 0; i < 6; i++)
        run_block(zp, DMAIN, 64,
                  mn_ln1w + i * DMAIN, mn_ln1b + i * DMAIN,
                  mn_qkvw + (size_t)i * 3 * DMAIN * DMAIN,
                  mn_wo   + (size_t)i * DMAIN * DMAIN,
                  mn_ln2w + i * DMAIN, mn_ln2b + i * DMAIN,
                  mn_w1   + (size_t)i * 2 * DMAIN * DMAIN,
                  mn_w2   + (size_t)i * 2 * DMAIN * DMAIN,
                  cntp);
    gemm_kernel<0, 0><<<gemm_grid(DENC), 256>>>(zp, proj_down, zdp, DENC, DMAIN, cntp, nullptr, 0);

    // ---- EMA scan + gather + STE add ----
    ema_kernel<<<BATCH, DENC>>>(zdp, pcp, zbp, cntp);
    gather_kernel<<<NROWS, DENC>>>(zbp, cump, pp, bhp, x);

    // ---- decoder ----
    for (int i = 0; i < 3; i++)
        run_block(x, DENC, 32,
                  dc_ln1w + i * DENC, dc_ln1b + i * DENC,
                  dc_qkvw + (size_t)i * 3 * DENC * DENC,
                  dc_wo   + (size_t)i * DENC * DENC,
                  dc_ln2w + i * DENC, dc_ln2b + i * DENC,
                  dc_w1   + (size_t)i * 2 * DENC * DENC,
                  dc_w2   + (size_t)i * 2 * DENC * DENC,
                  nullptr);

    // ---- final norm + tied logits head ----
    ln_kernel<<<NROWS / 2, 2 * DENC>>>(x, norm_w, norm_b, lnp, DENC, nullptr);
    gemm_kernel<0, 0><<<gemm_grid(260), 256>>>(lnp, embed, (float*)d_out, 260, DENC, nullptr, nullptr, 0);

    const int NLOGITS = NROWS * 260;
    if (out_size > NLOGITS)
        tail_kernel<<<1, 1>>>((float*)d_out + NLOGITS, lossp);
}

// round 17
// speedup vs baseline: 1.2908x; 1.0042x over previous
#include <cuda_runtime.h>
#include <cuda_bf16.h>
#include <math.h>

#define BATCH 8
#define SEQ   1024
#define NROWS (BATCH*SEQ)   // 8192
#define DENC  128
#define DMAIN 256
#define NHEADS 4
#define ASPLIT 4

// ---------------- scratch (device globals: no allocation in kernel_launch) ----------------
__device__ float g_x[NROWS*DENC];
__device__ float g_lnbuf[NROWS*DMAIN];
__device__ float g_qkv[NROWS*3*DMAIN];
__device__ float g_mlp[NROWS*2*DMAIN];
__device__ float g_z[NROWS*DMAIN];
__device__ float g_comp[NROWS*DENC];
__device__ float g_qr[NROWS*DENC];
__device__ float g_kr[NROWS*DENC];
__device__ float g_zdown[NROWS*DENC];
__device__ float g_zbar[NROWS*DENC];
__device__ float g_p[NROWS];
__device__ float g_bh[NROWS];
__device__ float g_pcomp[NROWS];
__device__ int   g_cum[NROWS];
__device__ int   g_counts[BATCH];
__device__ float g_loss[1];
__device__ float  g_pacc[ASPLIT*NROWS*DMAIN];          // split-K attention partial acc
__device__ float2 g_pml[ASPLIT*NROWS*NHEADS];          // split-K attention partial (m, l)

// ---------------- f32x2 packed-FMA helpers (Blackwell FFMA2, PTX-only) ----------------
typedef unsigned long long u64;
__device__ __forceinline__ u64 dup2(float v) {
    u64 r; asm("mov.b64 %0, {%1, %1};" : "=l"(r) : "f"(v)); return r;
}
__device__ __forceinline__ void unpack2(u64 v, float& lo, float& hi) {
    asm("mov.b64 {%0, %1}, %2;" : "=f"(lo), "=f"(hi) : "l"(v));
}
__device__ __forceinline__ u64 fma2(u64 a, u64 b, u64 c) {
    u64 d; asm("fma.rn.f32x2 %0, %1, %2, %3;" : "=l"(d) : "l"(a), "l"(b), "l"(c)); return d;
}
__device__ __forceinline__ u64 mul2(u64 a, u64 b) {
    u64 d; asm("mul.rn.f32x2 %0, %1, %2;" : "=l"(d) : "l"(a), "l"(b)); return d;
}

__device__ __forceinline__ float gelu_exact(float v) {
    return 0.5f * v * (1.0f + erff(v * 0.70710678118654752440f));
}

// ---------------- embedding lookup ----------------
__global__ void embed_kernel(const int* __restrict__ ids, const float* __restrict__ emb,
                             float* __restrict__ x) {
    int row = blockIdx.x;
    int t = threadIdx.x;
    x[(size_t)row * DENC + t] = emb[(size_t)ids[row] * DENC + t];
}

// ---------------- LayerNorm: 2 rows per block, blockDim = 2*D ----------------
__global__ void ln_kernel(const float* __restrict__ x, const float* __restrict__ w,
                          const float* __restrict__ b, float* __restrict__ y, int D,
                          const int* __restrict__ cnts) {
    int t = threadIdx.x;
    int sub = (t >= D) ? 1 : 0;
    int tr = t - sub * D;
    int row = (blockIdx.x << 1) + sub;
    bool live = !(cnts && (row & (SEQ - 1)) >= cnts[row >> 10]);
    __shared__ float sw[2][8];
    __shared__ float sred[2];
    float v = live ? x[(size_t)row * D + tr] : 0.f;
    float s = v;
    #pragma unroll
    for (int o = 16; o; o >>= 1) s += __shfl_xor_sync(0xffffffffu, s, o);
    int wps = D >> 5;
    int lw = (t >> 5) - sub * wps;
    if ((t & 31) == 0) sw[sub][lw] = s;
    __syncthreads();
    if (tr == 0) {
        float tot = 0.f;
        for (int i = 0; i < wps; i++) tot += sw[sub][i];
        sred[sub] = tot / (float)D;
    }
    __syncthreads();
    float mu = sred[sub];
    float dlt = v - mu;
    s = dlt * dlt;
    #pragma unroll
    for (int o = 16; o; o >>= 1) s += __shfl_xor_sync(0xffffffffu, s, o);
    __syncthreads();
    if ((t & 31) == 0) sw[sub][lw] = s;
    __syncthreads();
    if (tr == 0) {
        float tot = 0.f;
        for (int i = 0; i < wps; i++) tot += sw[sub][i];
        sred[sub] = rsqrtf(tot / (float)D + 1e-5f);
    }
    __syncthreads();
    if (live) y[(size_t)row * D + tr] = dlt * sred[sub] * w[tr] + b[tr];
}

// ---------------- SGEMM (FFMA2, double-buffered): C[M,N] (+)= act(A @ W^T) ----------------
// BM=64, BN=128, BK=8, 256 threads, 4x8 per thread (2 f32x2 row-pairs x 8 cols).
// Register-staged double buffering: next tile's global loads issue right after
// the single per-stage sync, hiding DRAM/L2 latency under the FMA phase.
// FUSE: 0 = store, 1 = C += result, 2 = gelu(result)
// MERGE: A computed on the fly as exact split-K softmax merge of (pacc, pml).
template<int FUSE, int MERGE>
__global__ __launch_bounds__(256)
void gemm_kernel(const float* __restrict__ A, const float* __restrict__ W,
                 float* __restrict__ C, int N, int K, const int* __restrict__ cnts,
                 const float2* __restrict__ pml, int dhshift) {
    int row0 = blockIdx.y * 64, col0 = blockIdx.x * 128;
    if (cnts && (row0 & (SEQ - 1)) >= cnts[row0 >> 10]) return;
    __shared__ __align__(16) float As[2][8][64];
    __shared__ __align__(16) float Ws[2][8][128];
    int tid = threadIdx.x;
    int tr = (tid >> 4) << 2;     // 4 rows per thread
    int tc = (tid & 15) << 3;     // 8 cols per thread
    u64 acc2[2][8];
    #pragma unroll
    for (int p = 0; p < 2; p++)
        #pragma unroll
        for (int j = 0; j < 8; j++) acc2[p][j] = 0ull;
    // A tile loads: 64x8 floats, float2 per thread
    int la = tid << 1;
    int lar = la >> 3, lac = la & 7;
    int grow = row0 + lar;
    const float* Ag = A + (size_t)grow * K + lac;
    // W tile loads: 128x8 floats, float4 per thread
    int lw = tid << 2;
    int lwr = lw >> 3, lwc = lw & 7;
    int wrow = col0 + lwr;
    bool wok = wrow < N;
    const float* Wg = W + (size_t)(wok ? wrow : 0) * K + lwc;

    auto loadA = [&](int k0) -> float2 {
        if (!MERGE) {
            return *(const float2*)(Ag + k0);
        } else {
            int col = k0 + lac;
            int h = col >> dhshift;
            float mm[ASPLIT], ll[ASPLIT];
            float M = -1e30f;
            #pragma unroll
            for (int s = 0; s < ASPLIT; s++) {
                float2 v = pml[((size_t)s * NROWS + grow) * NHEADS + h];
                mm[s] = v.x; ll[s] = v.y;
                M = fmaxf(M, v.x);
            }
            float L = 0.f, ax = 0.f, ay = 0.f;
            #pragma unroll
            for (int s = 0; s < ASPLIT; s++) {
                float e = __expf(mm[s] - M);
                L = fmaf(ll[s], e, L);
                float2 pv = *(const float2*)(A + ((size_t)s * NROWS + grow) * K + col);
                ax = fmaf(pv.x, e, ax);
                ay = fmaf(pv.y, e, ay);
            }
            float inv = 1.f / fmaxf(L, 1e-30f);   // guard only fires for dead rows
            return make_float2(ax * inv, ay * inv);
        }
    };
    auto loadW = [&](int k0) -> float4 {
        return wok ? *(const float4*)(Wg + k0) : make_float4(0.f, 0.f, 0.f, 0.f);
    };

    float2 av = loadA(0);
    float4 wv = loadW(0);
    int buf = 0;
    for (int k0 = 0; k0 < K; k0 += 8) {
        As[buf][lac + 0][lar] = av.x; As[buf][lac + 1][lar] = av.y;
        Ws[buf][lwc + 0][lwr] = wv.x; Ws[buf][lwc + 1][lwr] = wv.y;
        Ws[buf][lwc + 2][lwr] = wv.z; Ws[buf][lwc + 3][lwr] = wv.w;
        __syncthreads();
        if (k0 + 8 < K) {             // prefetch next stage; latency hides under FMAs
            av = loadA(k0 + 8);
            wv = loadW(k0 + 8);
        }
        #pragma unroll
        for (int k = 0; k < 8; k++) {
            ulonglong2 aA = *(const ulonglong2*)(&As[buf][k][tr]);   // 4 rows = 2 pairs
            u64 a2[2] = { aA.x, aA.y };
            float4 w0 = *(const float4*)(&Ws[buf][k][tc]);
            float4 w1 = *(const float4*)(&Ws[buf][k][tc + 4]);
            u64 wd[8];
            wd[0] = dup2(w0.x); wd[1] = dup2(w0.y); wd[2] = dup2(w0.z); wd[3] = dup2(w0.w);
            wd[4] = dup2(w1.x); wd[5] = dup2(w1.y); wd[6] = dup2(w1.z); wd[7] = dup2(w1.w);
            #pragma unroll
            for (int p = 0; p < 2; p++)
                #pragma unroll
                for (int j = 0; j < 8; j++)
                    acc2[p][j] = fma2(a2[p], wd[j], acc2[p][j]);
        }
        buf ^= 1;
        // safe without a second sync: stores at stage i+1 touch buffer buf^1,
        // whose last readers finished before passing stage i's barrier.
    }
    #pragma unroll
    for (int p = 0; p < 2; p++) {
        float* Cr0 = C + (size_t)(row0 + tr + 2 * p) * N;
        float* Cr1 = Cr0 + N;
        #pragma unroll
        for (int j = 0; j < 8; j++) {
            int cc = col0 + tc + j;
            if (cc < N) {
                float lo, hi;
                unpack2(acc2[p][j], lo, hi);
                if (FUSE == 1) { lo += Cr0[cc]; hi += Cr1[cc]; }
                if (FUSE == 2) { lo = gelu_exact(lo); hi = gelu_exact(hi); }
                Cr0[cc] = lo; Cr1[cc] = hi;
            }
        }
    }
}

// ---------------- split-K flash attention: partial pass ----------------
// grid: (BATCH*NHEADS, SEQ/128, ASPLIT), block 128 threads, 1 query row/thread.
// Double-buffered smem tiles with register staging, ONE sync per tile.
// Scores in groups of 8 with exact per-group online rescale.
template<int DH, int NT, int MINB>
__global__ __launch_bounds__(128, MINB)
void attn_part_kernel(const float* __restrict__ qkv, float* __restrict__ pacc,
                      float2* __restrict__ pml, int D,
                      const int* __restrict__ counts, float scale) {
    const int D3 = 3 * D;
    const int DH2 = DH / 2, DH4 = DH / 4;
    const int DQ = DH / 4;                 // float4 per K/V row
    int b = blockIdx.x >> 2, h = blockIdx.x & 3;
    int s = blockIdx.z;
    int tid = threadIdx.x;
    int q = blockIdx.y * 128 + tid;
    __shared__ __align__(16) float Ksh[2][NT][DH];
    __shared__ __align__(16) float Vsh[2][NT][DH];
    int cnt = counts ? counts[b] : SEQ;
    if (counts && (int)(blockIdx.y * 128) >= cnt) return;   // merge guard handles dead rows
    int row = b * SEQ + q;
    int qlim = (q < cnt) ? q : -1;
    int limit = min((int)(blockIdx.y * 128 + 127), cnt - 1);
    int T = limit / NT + 1;
    int t0 = (s * T) / ASPLIT, t1 = ((s + 1) * T) / ASPLIT;
    const u64* qrow2 = (const u64*)(qkv + (size_t)row * D3 + h * DH);
    u64 q2[DH2], acc2[DH2];
    #pragma unroll
    for (int d = 0; d < DH2; d++) { q2[d] = qrow2[d]; acc2[d] = 0ull; }
    float mval = -1e30f, lsum = 0.f;

    // loader mapping: 2 float4 of K and 2 of V per thread per tile
    int i0 = tid, i1 = tid + 128;
    int j0l = i0 / DQ, d0 = (i0 - j0l * DQ) << 2;
    int j1l = i1 / DQ, d1 = (i1 - j1l * DQ) << 2;
    size_t off0 = (size_t)(b * SEQ + j0l) * D3 + h * DH + d0;
    size_t off1 = (size_t)(b * SEQ + j1l) * D3 + h * DH + d1;
    float4 k0r, k1r, v0r, v1r;
    if (t0 < t1) {
        size_t a0 = off0 + (size_t)(t0 * NT) * D3;
        size_t a1 = off1 + (size_t)(t0 * NT) * D3;
        k0r = *(const float4*)(qkv + a0 + D);     v0r = *(const float4*)(qkv + a0 + 2 * D);
        k1r = *(const float4*)(qkv + a1 + D);     v1r = *(const float4*)(qkv + a1 + 2 * D);
    }
    int buf = 0;
    for (int kt = t0; kt < t1; kt++) {
        *(float4*)(&Ksh[buf][j0l][d0]) = k0r;  *(float4*)(&Vsh[buf][j0l][d0]) = v0r;
        *(float4*)(&Ksh[buf][j1l][d1]) = k1r;  *(float4*)(&Vsh[buf][j1l][d1]) = v1r;
        __syncthreads();
        if (kt + 1 < t1) {   // prefetch next tile into regs; latency hides under compute
            size_t a0 = off0 + (size_t)((kt + 1) * NT) * D3;
            size_t a1 = off1 + (size_t)((kt + 1) * NT) * D3;
            k0r = *(const float4*)(qkv + a0 + D);  v0r = *(const float4*)(qkv + a0 + 2 * D);
            k1r = *(const float4*)(qkv + a1 + D);  v1r = *(const float4*)(qkv + a1 + 2 * D);
        }
        int jmax = qlim - kt * NT;
        if (jmax > NT - 1) jmax = NT - 1;
        for (int g = 0; g <= jmax; g += 8) {
            float sc[8];
            #pragma unroll
            for (int half = 0; half < 2; half++) {
                const ulonglong2* K0 = (const ulonglong2*)Ksh[buf][g + half * 4 + 0];
                const ulonglong2* K1 = (const ulonglong2*)Ksh[buf][g + half * 4 + 1];
                const ulonglong2* K2 = (const ulonglong2*)Ksh[buf][g + half * 4 + 2];
                const ulonglong2* K3 = (const ulonglong2*)Ksh[buf][g + half * 4 + 3];
                u64 s0 = 0ull, s1 = 0ull, s2v = 0ull, s3 = 0ull;
                #pragma unroll
                for (int d = 0; d < DH4; d++) {
                    u64 qa = q2[2 * d], qb = q2[2 * d + 1];
                    ulonglong2 ka = K0[d], kb = K1[d], kc = K2[d], kd = K3[d];
                    s0 = fma2(qa, ka.x, s0);   s0 = fma2(qb, ka.y, s0);
                    s1 = fma2(qa, kb.x, s1);   s1 = fma2(qb, kb.y, s1);
                    s2v = fma2(qa, kc.x, s2v); s2v = fma2(qb, kc.y, s2v);
                    s3 = fma2(qa, kd.x, s3);   s3 = fma2(qb, kd.y, s3);
                }
                float lo, hi;
                unpack2(s0, lo, hi);  sc[half * 4 + 0] = (lo + hi) * scale;
                unpack2(s1, lo, hi);  sc[half * 4 + 1] = (lo + hi) * scale;
                unpack2(s2v, lo, hi); sc[half * 4 + 2] = (lo + hi) * scale;
                unpack2(s3, lo, hi);  sc[half * 4 + 3] = (lo + hi) * scale;
            }
            float gmax = -1e30f;
            #pragma unroll
            for (int j = 0; j < 8; j++)
                if (g + j <= jmax) gmax = fmaxf(gmax, sc[j]);
            float nm = fmaxf(mval, gmax);
            float f = __expf(mval - nm);
            lsum *= f;
            u64 f2 = dup2(f);
            #pragma unroll
            for (int d = 0; d < DH2; d++) acc2[d] = mul2(acc2[d], f2);
            #pragma unroll
            for (int j = 0; j < 8; j++) {
                float w = (g + j <= jmax) ? __expf(sc[j] - nm) : 0.f;
                lsum += w;
                u64 w2 = dup2(w);
                const ulonglong2* Vj = (const ulonglong2*)Vsh[buf][g + j];
                #pragma unroll
                for (int d = 0; d < DH4; d++) {
                    ulonglong2 vv = Vj[d];
                    acc2[2 * d]     = fma2(w2, vv.x, acc2[2 * d]);
                    acc2[2 * d + 1] = fma2(w2, vv.y, acc2[2 * d + 1]);
                }
            }
            mval = nm;
        }
        buf ^= 1;
    }
    pml[((size_t)s * NROWS + row) * NHEADS + h] = make_float2(mval, lsum);
    u64* pa = (u64*)(pacc + ((size_t)s * NROWS + row) * (size_t)D + h * DH);
    #pragma unroll
    for (int d = 0; d < DH2; d++) pa[d] = acc2[d];
}

// ---------------- routing: cos similarity of normalized q[l], k[l-1] ----------------
__global__ void route_kernel(const float* __restrict__ q, const float* __restrict__ k,
                             float* __restrict__ p, float* __restrict__ bh) {
    int wid = (blockIdx.x * blockDim.x + threadIdx.x) >> 5;
    int lane = threadIdx.x & 31;
    if (wid >= NROWS) return;
    int l = wid & (SEQ - 1);
    const float* qr = q + (size_t)wid * DENC;
    const float* kr = (l > 0) ? (k + (size_t)(wid - 1) * DENC) : nullptr;
    float nq = 0.f, nk = 0.f, dt = 0.f;
    for (int i = lane; i < DENC; i += 32) {
        float qv = qr[i];
        float kv = kr ? kr[i] : 0.f;
        nq += qv * qv; nk += kv * kv; dt += qv * kv;
    }
    #pragma unroll
    for (int o = 16; o; o >>= 1) {
        nq += __shfl_xor_sync(0xffffffffu, nq, o);
        nk += __shfl_xor_sync(0xffffffffu, nk, o);
        dt += __shfl_xor_sync(0xffffffffu, dt, o);
    }
    if (lane == 0) {
        float denom = fmaxf(sqrtf(nq), 1e-12f) * fmaxf(sqrtf(nk), 1e-12f);
        float cosv = dt / denom;
        float pv = fminf(fmaxf(0.5f * (1.f - cosv), 0.f), 1.f);
        if (l == 0) pv = 1.f;
        p[wid] = pv;
        bh[wid] = (pv >= 0.5f) ? 1.f : 0.f;
    }
}

// ---------------- per-batch inclusive scan of b_hard ----------------
__global__ void scan_kernel(const float* __restrict__ bh, int* __restrict__ cum,
                            int* __restrict__ counts) {
    int b = blockIdx.x, t = threadIdx.x;   // 1024 threads
    __shared__ int s[SEQ];
    s[t] = (int)bh[b * SEQ + t];
    __syncthreads();
    for (int o = 1; o < SEQ; o <<= 1) {
        int add = (t >= o) ? s[t - o] : 0;
        __syncthreads();
        s[t] += add;
        __syncthreads();
    }
    cum[b * SEQ + t] = s[t];
    if (t == SEQ - 1) counts[b] = s[t];
}

// ---------------- ratio loss ----------------
__global__ void stats_kernel(const float* __restrict__ bh, const float* __restrict__ p,
                             float* __restrict__ loss) {
    int t = threadIdx.x;   // 1024
    __shared__ float rb[1024], rp[1024];
    float sb = 0.f, sp = 0.f;
    for (int i = t; i < NROWS; i += 1024) { sb += bh[i]; sp += p[i]; }
    rb[t] = sb; rp[t] = sp;
    __syncthreads();
    for (int o = 512; o; o >>= 1) {
        if (t < o) { rb[t] += rb[t + o]; rp[t] += rp[t + o]; }
        __syncthreads();
    }
    if (t == 0) {
        float F = rb[0] / (float)NROWS, G = rp[0] / (float)NROWS;
        loss[0] = 1.2f * (5.f * F * G + (1.f - F) * (1.f - G));
    }
}

__global__ void zero_kernel(float* __restrict__ ptr, int n) {
    int i = blockIdx.x * blockDim.x + threadIdx.x;
    if (i < n) ptr[i] = 0.f;
}

// ---------------- scatter selected rows to front (downsample) ----------------
__global__ void scatter_kernel(const float* __restrict__ x, const float* __restrict__ p,
                               const float* __restrict__ bh, const int* __restrict__ cum,
                               float* __restrict__ comp, float* __restrict__ pcomp) {
    int row = blockIdx.x;
    if (bh[row] < 0.5f) return;
    int b = row >> 10;
    int dst = cum[row] - 1;
    int t = threadIdx.x;
    comp[((size_t)(b << 10) + dst) * DENC + t] = x[(size_t)row * DENC + t];
    if (t == 0) pcomp[(b << 10) + dst] = p[row];
}

// ---------------- EMA linear recurrence scan ----------------
__global__ void ema_kernel(const float* __restrict__ z, const float* __restrict__ pc,
                           float* __restrict__ zbar, const int* __restrict__ counts) {
    int b = blockIdx.x, d = threadIdx.x;   // 128 threads
    const float* zb = z + (size_t)b * SEQ * DENC;
    float* ob = zbar + (size_t)b * SEQ * DENC;
    const float* pb = pc + b * SEQ;
    int Tn = counts[b];
    float prev = 0.f;
    for (int t = 0; t < Tn; t++) {
        float pv = pb[t];
        float pcl = fminf(fmaxf(pv, 1e-4f), 0.9999f);
        float zv = zb[(size_t)t * DENC + d];
        float cur = (t == 0) ? zv : ((1.f - pcl) * prev + pcl * zv);
        ob[(size_t)t * DENC + d] = cur;
        prev = cur;
    }
}

// ---------------- gather + STE residual add ----------------
__global__ void gather_kernel(const float* __restrict__ zbar, const int* __restrict__ cum,
                              const float* __restrict__ p, const float* __restrict__ bh,
                              float* __restrict__ x) {
    int row = blockIdx.x, t = threadIdx.x;
    int b = row >> 10;
    int ci = cum[row] - 1; if (ci < 0) ci = 0;
    float pv = p[row], bv = bh[row];
    float c = bv * pv + (1.f - bv) * (1.f - pv);
    float cste = c + (1.f - c);   // forward value of STE (match ref rounding)
    x[(size_t)row * DENC + t] += cste * zbar[((size_t)(b << 10) + ci) * DENC + t];
}

__global__ void tail_kernel(float* __restrict__ dst, const float* __restrict__ loss) {
    dst[0] = loss[0];
}

// ---------------- host orchestration ----------------
static void* symaddr(const void* sym) {
    void* p = nullptr;
    cudaGetSymbolAddress(&p, sym);
    return p;
}

static const int PERM_SIG[32] = {
    0,1,2,3, 4,5,6,7,8,9,10,11, 12, 13,14,15,16,17,18,19,20, 21, 22,23,24,25,26,27,28,29, 30,31
};
static const int PERM_DICT[32] = {
    0,1,2,3, 8,9,10,11,12,13,14,15, 4, 16,17,18,19,20,21,22,23, 5, 24,25,26,27,28,29,30,31, 6,7
};
static const int PERM_ALPHA[32] = {
    0,9,31,30, 11,10,14,17,13,12,15,16, 29, 19,18,22,25,21,20,23,24, 28, 2,1,5,8,4,3,6,7, 27,26
};

extern "C" void kernel_launch(void* const* d_in, const int* in_sizes, int n_in,
                              void* d_out, int out_size) {
    (void)n_in;
    const int* perm;
    if (in_sizes[1] == 3 * DENC)            perm = PERM_ALPHA;
    else if (in_sizes[4] == DMAIN * DENC)   perm = PERM_DICT;
    else                                    perm = PERM_SIG;

    const float* inp[32];
    for (int i = 0; i < 32; i++) inp[i] = (const float*)d_in[perm[i]];

    const int*   ids       = (const int*)d_in[perm[0]];
    const float* embed     = inp[1];
    const float* wq        = inp[2];
    const float* wk        = inp[3];
    const float* enc_ln1w  = inp[4];
    const float* enc_ln1b  = inp[5];
    const float* enc_qkvw  = inp[6];
    const float* enc_wo    = inp[7];
    const float* enc_ln2w  = inp[8];
    const float* enc_ln2b  = inp[9];
    const float* enc_w1    = inp[10];
    const float* enc_w2    = inp[11];
    const float* proj_up   = inp[12];
    const float* mn_ln1w   = inp[13];
    const float* mn_ln1b   = inp[14];
    const float* mn_qkvw   = inp[15];
    const float* mn_wo     = inp[16];
    const float* mn_ln2w   = inp[17];
    const float* mn_ln2b   = inp[18];
    const float* mn_w1     = inp[19];
    const float* mn_w2     = inp[20];
    const float* proj_down = inp[21];
    const float* dc_ln1w   = inp[22];
    const float* dc_ln1b   = inp[23];
    const float* dc_qkvw   = inp[24];
    const float* dc_wo     = inp[25];
    const float* dc_ln2w   = inp[26];
    const float* dc_ln2b   = inp[27];
    const float* dc_w1     = inp[28];
    const float* dc_w2     = inp[29];
    const float* norm_w    = inp[30];
    const float* norm_b    = inp[31];

    float*  x     = (float*)symaddr(g_x);
    float*  lnp   = (float*)symaddr(g_lnbuf);
    float*  qkvp  = (float*)symaddr(g_qkv);
    float*  mlpp  = (float*)symaddr(g_mlp);
    float*  zp    = (float*)symaddr(g_z);
    float*  compp = (float*)symaddr(g_comp);
    float*  qrp   = (float*)symaddr(g_qr);
    float*  krp   = (float*)symaddr(g_kr);
    float*  zdp   = (float*)symaddr(g_zdown);
    float*  zbp   = (float*)symaddr(g_zbar);
    float*  pp    = (float*)symaddr(g_p);
    float*  bhp   = (float*)symaddr(g_bh);
    float*  pcp   = (float*)symaddr(g_pcomp);
    int*    cump  = (int*)symaddr(g_cum);
    int*    cntp  = (int*)symaddr(g_counts);
    float*  lossp = (float*)symaddr(g_loss);
    float*  paccp = (float*)symaddr(g_pacc);
    float2* pmlp  = (float2*)symaddr(g_pml);

    auto gemm_grid = [](int N) { return dim3((N + 127) / 128, 128); };

    auto run_block = [&](float* xb, int D, int dh,
                         const float* l1w, const float* l1b,
                         const float* qw, const float* wo,
                         const float* l2w, const float* l2b,
                         const float* w1, const float* w2,
                         const int* cnts) {
        int D3 = 3 * D;
        ln_kernel<<<NROWS / 2, 2 * D>>>(xb, l1w, l1b, lnp, D, cnts);
        gemm_kernel<0, 0><<<gemm_grid(D3), 256>>>(lnp, qw, qkvp, D3, D, cnts, nullptr, 0);
        if (dh == 32) {
            attn_part_kernel<32, 32, 4><<<dim3(BATCH * NHEADS, SEQ / 128, ASPLIT), 128>>>(
                qkvp, paccp, pmlp, D, cnts, 0.17677669529663687f);
            gemm_kernel<1, 1><<<gemm_grid(D), 256>>>(paccp, wo, xb, D, D, cnts, pmlp, 5);
        } else {
            attn_part_kernel<64, 16, 3><<<dim3(BATCH * NHEADS, SEQ / 128, ASPLIT), 128>>>(
                qkvp, paccp, pmlp, D, cnts, 0.125f);
            gemm_kernel<1, 1><<<gemm_grid(D), 256>>>(paccp, wo, xb, D, D, cnts, pmlp, 6);
        }
        ln_kernel<<<NROWS / 2, 2 * D>>>(xb, l2w, l2b, lnp, D, cnts);
        gemm_kernel<2, 0><<<gemm_grid(2 * D), 256>>>(lnp, w1, mlpp, 2 * D, D, cnts, nullptr, 0);
        gemm_kernel<1, 0><<<gemm_grid(D), 256>>>(mlpp, w2, xb, D, 2 * D, cnts, nullptr, 0);
    };

    // ---- encoder ----
    embed_kernel<<<NROWS, DENC>>>(ids, embed, x);
    for (int i = 0; i < 3; i++)
        run_block(x, DENC, 32,
                  enc_ln1w + i * DENC, enc_ln1b + i * DENC,
                  enc_qkvw + (size_t)i * 3 * DENC * DENC,
                  enc_wo   + (size_t)i * DENC * DENC,
                  enc_ln2w + i * DENC, enc_ln2b + i * DENC,
                  enc_w1   + (size_t)i * 2 * DENC * DENC,
                  enc_w2   + (size_t)i * 2 * DENC * DENC,
                  nullptr);

    // ---- routing / dynamic chunking ----
    gemm_kernel<0, 0><<<gemm_grid(DENC), 256>>>(x, wq, qrp, DENC, DENC, nullptr, nullptr, 0);
    gemm_kernel<0, 0><<<gemm_grid(DENC), 256>>>(x, wk, krp, DENC, DENC, nullptr, nullptr, 0);
    route_kernel<<<NROWS / 8, 256>>>(qrp, krp, pp, bhp);
    scan_kernel<<<BATCH, SEQ>>>(bhp, cump, cntp);
    stats_kernel<<<1, 1024>>>(bhp, pp, lossp);
    zero_kernel<<<(NROWS * DENC + 255) / 256, 256>>>(compp, NROWS * DENC);
    zero_kernel<<<(NROWS + 255) / 256, 256>>>(pcp, NROWS);
    scatter_kernel<<<NROWS, DENC>>>(x, pp, bhp, cump, compp, pcp);

    // ---- main stack (padded + masked; padded rows dynamically elided) ----
    gemm_kernel<0, 0><<<gemm_grid(DMAIN), 256>>>(compp, proj_up, zp, DMAIN, DENC, cntp, nullptr, 0);
    for (int i = 0; i < 6; i++)
        run_block(zp, DMAIN, 64,
                  mn_ln1w + i * DMAIN, mn_ln1b + i * DMAIN,
                  mn_qkvw + (size_t)i * 3 * DMAIN * DMAIN,
                  mn_wo   + (size_t)i * DMAIN * DMAIN,
                  mn_ln2w + i * DMAIN, mn_ln2b + i * DMAIN,
                  mn_w1   + (size_t)i * 2 * DMAIN * DMAIN,
                  mn_w2   + (size_t)i * 2 * DMAIN * DMAIN,
                  cntp);
    gemm_kernel<0, 0><<<gemm_grid(DENC), 256>>>(zp, proj_down, zdp, DENC, DMAIN, cntp, nullptr, 0);

    // ---- EMA scan + gather + STE add ----
    ema_kernel<<<BATCH, DENC>>>(zdp, pcp, zbp, cntp);
    gather_kernel<<<NROWS, DENC>>>(zbp, cump, pp, bhp, x);

    // ---- decoder ----
    for (int i = 0; i < 3; i++)
        run_block(x, DENC, 32,
                  dc_ln1w + i * DENC, dc_ln1b + i * DENC,
                  dc_qkvw + (size_t)i * 3 * DENC * DENC,
                  dc_wo   + (size_t)i * DENC * DENC,
                  dc_ln2w + i * DENC, dc_ln2b + i * DENC,
                  dc_w1   + (size_t)i * 2 * DENC * DENC,
                  dc_w2   + (size_t)i * 2 * DENC * DENC,
                  nullptr);

    // ---- final norm + tied logits head ----
    ln_kernel<<<NROWS / 2, 2 * DENC>>>(x, norm_w, norm_b, lnp, DENC, nullptr);
    gemm_kernel<0, 0><<<gemm_grid(260), 256>>>(lnp, embed, (float*)d_out, 260, DENC, nullptr, nullptr, 0);

    const int NLOGITS = NROWS * 260;
    if (out_size > NLOGITS)
        tail_kernel<<<1, 1>>>((float*)d_out + NLOGITS, lossp);
}